// round 6
// baseline (speedup 1.0000x reference)
#include <cuda_runtime.h>
#include <cuda_bf16.h>
#include <stdint.h>
#include <math.h>

// Problem constants
#define BB   4
#define TTT  4096
#define CC   1024
#define HH   16
#define KD   64          // head dim
#define TCH  128         // chunk length
#define NCH  32          // chunks
#define MM   (BB*TTT)    // 16384 rows

// ---------------- scratch (device globals; no allocation allowed) ----------
__device__ __nv_bfloat16 g_xr_h[MM*CC], g_xr_l[MM*CC];
__device__ __nv_bfloat16 g_xk_h[MM*CC], g_xk_l[MM*CC];
__device__ __nv_bfloat16 g_xv_h[MM*CC], g_xv_l[MM*CC];
__device__ __nv_bfloat16 g_xg_h[MM*CC], g_xg_l[MM*CC];
__device__ __nv_bfloat16 g_z_h [MM*CC], g_z_l [MM*CC];
__device__ __nv_bfloat16 g_wr_h[CC*CC], g_wr_l[CC*CC];
__device__ __nv_bfloat16 g_wk_h[CC*CC], g_wk_l[CC*CC];
__device__ __nv_bfloat16 g_wv_h[CC*CC], g_wv_l[CC*CC];
__device__ __nv_bfloat16 g_wg_h[CC*CC], g_wg_l[CC*CC];
__device__ __nv_bfloat16 g_wo_h[CC*CC], g_wo_l[CC*CC];
__device__ float g_r [MM*CC];
__device__ float g_k [MM*CC];
__device__ float g_v [MM*CC];
__device__ float g_g [MM*CC];
__device__ float g_xo[MM*CC];
__device__ float g_states[BB*HH*NCH*KD*KD];

// ---------------- helpers ---------------------------------------------------
__device__ __forceinline__ void split_store(__nv_bfloat16* ah, __nv_bfloat16* al,
                                            size_t i, float v) {
    __nv_bfloat16 h = __float2bfloat16(v);
    ah[i] = h;
    al[i] = __float2bfloat16(v - __bfloat162float(h));
}

__device__ __forceinline__ void mma_bf16(float* c, const uint32_t* a,
                                         uint32_t b0, uint32_t b1) {
    asm volatile(
        "mma.sync.aligned.m16n8k16.row.col.f32.bf16.bf16.f32 "
        "{%0,%1,%2,%3}, {%4,%5,%6,%7}, {%8,%9}, {%0,%1,%2,%3};"
        : "+f"(c[0]), "+f"(c[1]), "+f"(c[2]), "+f"(c[3])
        : "r"(a[0]), "r"(a[1]), "r"(a[2]), "r"(a[3]), "r"(b0), "r"(b1));
}

__device__ __forceinline__ uint32_t smem_u32(const void* p) {
    uint32_t a;
    asm("{ .reg .u64 t; cvta.to.shared.u64 t, %1; cvt.u32.u64 %0, t; }"
        : "=r"(a) : "l"(p));
    return a;
}
__device__ __forceinline__ void cp16(uint32_t saddr, const void* g) {
    asm volatile("cp.async.cg.shared.global [%0], [%1], 16;" :: "r"(saddr), "l"(g));
}
__device__ __forceinline__ void cp_commit() {
    asm volatile("cp.async.commit_group;");
}
__device__ __forceinline__ void cp_wait0() {
    asm volatile("cp.async.wait_group 0;");
}
__device__ __forceinline__ void ldsm4(uint32_t* r, uint32_t addr) {
    asm volatile("ldmatrix.sync.aligned.m8n8.x4.shared.b16 {%0,%1,%2,%3}, [%4];"
                 : "=r"(r[0]), "=r"(r[1]), "=r"(r[2]), "=r"(r[3]) : "r"(addr));
}

// ---------------- 0) weight split fp32 -> bf16 hi/lo (all 5 fused) ---------
__global__ void wsplit5_kernel(const float* __restrict__ W0, const float* __restrict__ W1,
                               const float* __restrict__ W2, const float* __restrict__ W3,
                               const float* __restrict__ W4,
                               __nv_bfloat16* __restrict__ H0, __nv_bfloat16* __restrict__ L0,
                               __nv_bfloat16* __restrict__ H1, __nv_bfloat16* __restrict__ L1,
                               __nv_bfloat16* __restrict__ H2, __nv_bfloat16* __restrict__ L2,
                               __nv_bfloat16* __restrict__ H3, __nv_bfloat16* __restrict__ L3,
                               __nv_bfloat16* __restrict__ H4, __nv_bfloat16* __restrict__ L4) {
    int i = blockIdx.x * blockDim.x + threadIdx.x;
    const float* W; __nv_bfloat16 *Hh, *Ll;
    switch (blockIdx.y) {
        case 0: W = W0; Hh = H0; Ll = L0; break;
        case 1: W = W1; Hh = H1; Ll = L1; break;
        case 2: W = W2; Hh = H2; Ll = L2; break;
        case 3: W = W3; Hh = H3; Ll = L3; break;
        default: W = W4; Hh = H4; Ll = L4; break;
    }
    split_store(Hh, Ll, i, W[i]);
}

// ---------------- 1) time-shift mixing -> bf16 hi/lo ----------------------
__global__ void mix_kernel(const float* __restrict__ x,
                           const float* __restrict__ tmk,
                           const float* __restrict__ tmv,
                           const float* __restrict__ tmr,
                           const float* __restrict__ tmg) {
    int idx = blockIdx.x * blockDim.x + threadIdx.x;   // MM*CC total
    int c = idx & (CC - 1);
    int t = (idx >> 10) & (TTT - 1);
    float xc = x[idx];
    float xp = t ? x[idx - CC] : 0.f;
    float mr = tmr[c]; split_store(g_xr_h, g_xr_l, idx, xc * mr + xp * (1.f - mr));
    float mk = tmk[c]; split_store(g_xk_h, g_xk_l, idx, xc * mk + xp * (1.f - mk));
    float mv = tmv[c]; split_store(g_xv_h, g_xv_l, idx, xc * mv + xp * (1.f - mv));
    float mg = tmg[c]; split_store(g_xg_h, g_xg_l, idx, xc * mg + xp * (1.f - mg));
}

// ---------------- 2) mma.sync GEMM: C = A @ W^T (bf16 hi/lo, 3 passes) -----
// CTA tile 128x128, 8 warps (warp tile 32x64), K-chunk 32, cp.async double buf,
// ldmatrix fragment loads. 2 CTAs/SM.
#define KCH   32
#define APAD  40                         // padded row stride (elems) -> 80B
#define TS    (128*APAD)                 // one tile in smem (elems)
#define GSM_TOTAL (2*4*TS*2)             // 2 bufs x 4 tiles = 81920 B
#define NKC   (CC/KCH)                   // 32 chunks

__global__ void __launch_bounds__(256, 2)
gemm_mma(const __nv_bfloat16* __restrict__ Ah, const __nv_bfloat16* __restrict__ Al,
         const __nv_bfloat16* __restrict__ Bh, const __nv_bfloat16* __restrict__ Bl,
         float* __restrict__ C) {
    extern __shared__ __nv_bfloat16 dsm[];
    uint32_t sbase = smem_u32(dsm);
    int tid = threadIdx.x;
    int w   = tid >> 5;
    int lane = tid & 31;
    int g = lane >> 2;           // group id 0..7
    int t = lane & 3;            // thread-in-group
    int n0 = blockIdx.x * 128;
    int m0 = blockIdx.y * 128;
    int m0w = (w >> 1) * 32;     // warp M offset in tile
    int n0w = (w & 1) * 64;      // warp N offset in tile

    const __nv_bfloat16* sAh = Ah + (size_t)m0 * CC;
    const __nv_bfloat16* sAl = Al + (size_t)m0 * CC;
    const __nv_bfloat16* sBh = Bh + (size_t)n0 * CC;
    const __nv_bfloat16* sBl = Bl + (size_t)n0 * CC;

    // cp.async coords: u = tid + j*256; row=u>>2 (0..127), seg=(u&3)*8 elems
    int row0 = tid >> 2,         seg0 = (tid & 3) * 8;
    int row1 = row0 + 64;
    size_t go0 = (size_t)row0 * CC + seg0;
    size_t go1 = (size_t)row1 * CC + seg0;
    uint32_t so0 = (row0 * APAD + seg0) * 2;   // byte offsets
    uint32_t so1 = (row1 * APAD + seg0) * 2;

    // ldmatrix per-lane address components
    int arow = lane & 15;                       // A: row within 16-row group
    int akof = ((lane >> 4) << 3);              // A: k offset 0/8
    int brow = ((lane >> 4) << 3) + (lane & 7); // B: row within 16-row (ni pair)
    int bkof = ((lane >> 3) & 1) << 3;          // B: k offset 0/8

    float acc[2][8][4];
#pragma unroll
    for (int mi = 0; mi < 2; mi++)
#pragma unroll
        for (int ni = 0; ni < 8; ni++)
#pragma unroll
            for (int q = 0; q < 4; q++) acc[mi][ni][q] = 0.f;

    // prologue: chunk 0 -> buf 0
    {
        uint32_t b = sbase;
        cp16(b + 0*TS*2 + so0, sAh + go0); cp16(b + 0*TS*2 + so1, sAh + go1);
        cp16(b + 1*TS*2 + so0, sAl + go0); cp16(b + 1*TS*2 + so1, sAl + go1);
        cp16(b + 2*TS*2 + so0, sBh + go0); cp16(b + 2*TS*2 + so1, sBh + go1);
        cp16(b + 3*TS*2 + so0, sBl + go0); cp16(b + 3*TS*2 + so1, sBl + go1);
        cp_commit();
    }

    for (int c = 0; c < NKC; ++c) {
        cp_wait0();
        __syncthreads();
        if (c + 1 < NKC) {
            int k0 = (c + 1) * KCH;
            uint32_t b = sbase + (uint32_t)(((c + 1) & 1) * 4 * TS * 2);
            cp16(b + 0*TS*2 + so0, sAh + go0 + k0); cp16(b + 0*TS*2 + so1, sAh + go1 + k0);
            cp16(b + 1*TS*2 + so0, sAl + go0 + k0); cp16(b + 1*TS*2 + so1, sAl + go1 + k0);
            cp16(b + 2*TS*2 + so0, sBh + go0 + k0); cp16(b + 2*TS*2 + so1, sBh + go1 + k0);
            cp16(b + 3*TS*2 + so0, sBl + go0 + k0); cp16(b + 3*TS*2 + so1, sBl + go1 + k0);
            cp_commit();
        }
        uint32_t sb = sbase + (uint32_t)((c & 1) * 4 * TS * 2);
        uint32_t tAh = sb;
        uint32_t tAl = sb + TS * 2;
        uint32_t tBh = sb + 2 * TS * 2;
        uint32_t tBl = sb + 3 * TS * 2;
#pragma unroll
        for (int ks = 0; ks < 2; ++ks) {
            int kk = ks * 16;
            uint32_t ah[2][4], al[2][4];
#pragma unroll
            for (int mi = 0; mi < 2; mi++) {
                uint32_t ro = (uint32_t)((m0w + mi * 16 + arow) * APAD + kk + akof) * 2;
                ldsm4(ah[mi], tAh + ro);
                ldsm4(al[mi], tAl + ro);
            }
#pragma unroll
            for (int np = 0; np < 4; np++) {
                uint32_t bo = (uint32_t)((n0w + np * 16 + brow) * APAD + kk + bkof) * 2;
                uint32_t bh4[4], bl4[4];
                ldsm4(bh4, tBh + bo);
                ldsm4(bl4, tBl + bo);
#pragma unroll
                for (int sub = 0; sub < 2; sub++) {
                    int ni = np * 2 + sub;
                    uint32_t b0h = bh4[sub * 2], b1h = bh4[sub * 2 + 1];
                    uint32_t b0l = bl4[sub * 2], b1l = bl4[sub * 2 + 1];
#pragma unroll
                    for (int mi = 0; mi < 2; mi++) {
                        mma_bf16(acc[mi][ni], ah[mi], b0h, b1h);
                        mma_bf16(acc[mi][ni], ah[mi], b0l, b1l);
                        mma_bf16(acc[mi][ni], al[mi], b0h, b1h);
                    }
                }
            }
        }
        __syncthreads();
    }

    // epilogue: write fp32
#pragma unroll
    for (int mi = 0; mi < 2; mi++) {
        int r0 = m0 + m0w + mi * 16 + g;
#pragma unroll
        for (int ni = 0; ni < 8; ni++) {
            int col = n0 + n0w + ni * 8 + 2 * t;
            *(float2*)&C[(size_t)r0 * CC + col] =
                make_float2(acc[mi][ni][0], acc[mi][ni][1]);
            *(float2*)&C[(size_t)(r0 + 8) * CC + col] =
                make_float2(acc[mi][ni][2], acc[mi][ni][3]);
        }
    }
}

// ---------------- 3) chunk-boundary states (sequential recurrence) ---------
__global__ void __launch_bounds__(256)
state_kernel(const float* __restrict__ tdecay) {
    __shared__ float kw[TCH * KD];
    __shared__ float vsh[TCH * 16];
    __shared__ float dp[TCH + 1];
    int bh = blockIdx.x;
    int vs = blockIdx.y;
    int b = bh >> 4, h = bh & 15;
    int tid = threadIdx.x;
    float decay = expf(-expf(tdecay[h]));
    if (tid <= TCH) dp[tid] = powf(decay, (float)tid);
    __syncthreads();
    float ws = dp[TCH];
    int tr = tid >> 2;
    int tc = (tid & 3) * 4;
    float s0 = 0.f, s1 = 0.f, s2 = 0.f, s3 = 0.f;
    const float* kb = g_k + ((size_t)b * TTT) * CC + h * KD;
    const float* vb = g_v + ((size_t)b * TTT) * CC + h * KD + vs * 16;
    float* stb = g_states + ((size_t)bh * NCH) * KD * KD;
    for (int n = 0; n < NCH; n++) {
        float* sd = stb + (size_t)n * KD * KD + tr * KD + vs * 16 + tc;
        sd[0] = s0; sd[1] = s1; sd[2] = s2; sd[3] = s3;
        __syncthreads();
        for (int e = tid; e < TCH * KD; e += 256) {
            int j = e >> 6, kk2 = e & 63;
            kw[e] = kb[(size_t)(n * TCH + j) * CC + kk2] * dp[127 - j];
        }
        for (int e = tid; e < TCH * 16; e += 256) {
            int j = e >> 4, cc2 = e & 15;
            vsh[e] = vb[(size_t)(n * TCH + j) * CC + cc2];
        }
        __syncthreads();
        float a0 = 0.f, a1 = 0.f, a2 = 0.f, a3 = 0.f;
#pragma unroll 4
        for (int j = 0; j < TCH; j++) {
            float kv = kw[j * KD + tr];
            float4 v4 = *(const float4*)&vsh[j * 16 + tc];
            a0 = fmaf(kv, v4.x, a0); a1 = fmaf(kv, v4.y, a1);
            a2 = fmaf(kv, v4.z, a2); a3 = fmaf(kv, v4.w, a3);
        }
        s0 = ws * s0 + a0; s1 = ws * s1 + a1;
        s2 = ws * s2 + a2; s3 = ws * s3 + a3;
    }
}

// ---------------- 4) per-chunk attention output (parallel) -----------------
#define OUT_SMEM_FLOATS (TCH*65 + TCH*65 + TCH*KD + KD*KD + TCH*129)
__global__ void __launch_bounds__(256)
out_kernel(const float* __restrict__ tdecay, const float* __restrict__ tfa) {
    extern __shared__ float sm[];
    float* rs  = sm;
    float* ksm = rs  + TCH * 65;
    float* vsm = ksm + TCH * 65;
    float* ssm = vsm + TCH * KD;
    float* att = ssm + KD * KD;
    __shared__ float dp[TCH];
    int bhn = blockIdx.x;
    int n  = bhn & (NCH - 1);
    int bh = bhn >> 5;
    int h = bh & 15, b = bh >> 4;
    int tid = threadIdx.x;
    float decay = expf(-expf(tdecay[h]));
    if (tid < TCH) dp[tid] = powf(decay, (float)tid);
    float u = tfa[h];
    size_t base = ((size_t)(b * TTT + n * TCH)) * CC + h * KD;
    for (int e = tid; e < TCH * KD; e += 256) {
        int i = e >> 6, k2 = e & 63;
        size_t gi = base + (size_t)i * CC + k2;
        rs [i * 65 + k2] = g_r[gi];
        ksm[i * 65 + k2] = g_k[gi];
        vsm[e]           = g_v[gi];
    }
    const float* stp = g_states + ((size_t)bh * NCH + n) * KD * KD;
    for (int e = tid; e < KD * KD; e += 256) ssm[e] = stp[e];
    __syncthreads();
    {
        int i0 = (tid >> 4) * 8, j0 = (tid & 15) * 8;
        float acc[8][8];
#pragma unroll
        for (int i = 0; i < 8; i++)
#pragma unroll
            for (int j = 0; j < 8; j++) acc[i][j] = 0.f;
        for (int k2 = 0; k2 < KD; k2++) {
            float ra[8], rb[8];
#pragma unroll
            for (int ii = 0; ii < 8; ii++) ra[ii] = rs[(i0 + ii) * 65 + k2];
#pragma unroll
            for (int jj = 0; jj < 8; jj++) rb[jj] = ksm[(j0 + jj) * 65 + k2];
#pragma unroll
            for (int ii = 0; ii < 8; ii++)
#pragma unroll
                for (int jj = 0; jj < 8; jj++)
                    acc[ii][jj] = fmaf(ra[ii], rb[jj], acc[ii][jj]);
        }
#pragma unroll
        for (int ii = 0; ii < 8; ii++)
#pragma unroll
            for (int jj = 0; jj < 8; jj++) {
                int i = i0 + ii, j = j0 + jj, d = i - j;
                float w = (d > 0) ? dp[d - 1] : ((d == 0) ? u : 0.f);
                att[i * 129 + j] = acc[ii][jj] * w;
            }
    }
    __syncthreads();
    {
        int i0 = (tid >> 3) * 4, v0 = (tid & 7) * 8;
        float aA[4][8], aB[4][8];
#pragma unroll
        for (int i = 0; i < 4; i++)
#pragma unroll
            for (int j = 0; j < 8; j++) { aA[i][j] = 0.f; aB[i][j] = 0.f; }
        for (int j = 0; j < TCH; j++) {
            float a4[4];
#pragma unroll
            for (int ii = 0; ii < 4; ii++) a4[ii] = att[(i0 + ii) * 129 + j];
            float4 va = *(const float4*)&vsm[j * KD + v0];
            float4 vb2 = *(const float4*)&vsm[j * KD + v0 + 4];
            float vv[8] = {va.x, va.y, va.z, va.w, vb2.x, vb2.y, vb2.z, vb2.w};
#pragma unroll
            for (int ii = 0; ii < 4; ii++)
#pragma unroll
                for (int jj = 0; jj < 8; jj++)
                    aA[ii][jj] = fmaf(a4[ii], vv[jj], aA[ii][jj]);
        }
        for (int k2 = 0; k2 < KD; k2++) {
            float r4[4];
#pragma unroll
            for (int ii = 0; ii < 4; ii++) r4[ii] = rs[(i0 + ii) * 65 + k2];
            float4 sa = *(const float4*)&ssm[k2 * KD + v0];
            float4 sb = *(const float4*)&ssm[k2 * KD + v0 + 4];
            float sv[8] = {sa.x, sa.y, sa.z, sa.w, sb.x, sb.y, sb.z, sb.w};
#pragma unroll
            for (int ii = 0; ii < 4; ii++)
#pragma unroll
                for (int jj = 0; jj < 8; jj++)
                    aB[ii][jj] = fmaf(r4[ii], sv[jj], aB[ii][jj]);
        }
#pragma unroll
        for (int ii = 0; ii < 4; ii++) {
            float wbv = dp[i0 + ii];
#pragma unroll
            for (int jj = 0; jj < 8; jj++)
                g_xo[base + (size_t)(i0 + ii) * CC + v0 + jj] =
                    aA[ii][jj] + wbv * aB[ii][jj];
        }
    }
}

// ---------------- 5) GroupNorm(/8) + silu gate -> bf16 hi/lo ---------------
__global__ void gn_gate_kernel(const float* __restrict__ lnw,
                               const float* __restrict__ lnb) {
    int gidx = blockIdx.x * blockDim.x + threadIdx.x;
    int warp = gidx >> 5, lane = gidx & 31;
    size_t basep = (size_t)warp * 64;
    float a  = g_xo[basep + lane]      * 0.125f;
    float c2 = g_xo[basep + 32 + lane] * 0.125f;
    float s = a + c2, sq = a * a + c2 * c2;
#pragma unroll
    for (int o = 16; o; o >>= 1) {
        s  += __shfl_xor_sync(0xffffffffu, s,  o);
        sq += __shfl_xor_sync(0xffffffffu, sq, o);
    }
    float mu  = s * (1.f / 64.f);
    float var = sq * (1.f / 64.f) - mu * mu;
    float inv = rsqrtf(var + 1e-5f);
    int h = warp & 15;
    int cb = h * 64;
    float g0r = g_g[basep + lane];
    float g1r = g_g[basep + 32 + lane];
    float y0 = ((a  - mu) * inv) * lnw[cb + lane]      + lnb[cb + lane];
    float y1 = ((c2 - mu) * inv) * lnw[cb + 32 + lane] + lnb[cb + 32 + lane];
    split_store(g_z_h, g_z_l, basep + lane,      y0 * (g0r / (1.f + expf(-g0r))));
    split_store(g_z_h, g_z_l, basep + 32 + lane, y1 * (g1r / (1.f + expf(-g1r))));
}

// ---------------- launch ---------------------------------------------------
extern "C" void kernel_launch(void* const* d_in, const int* in_sizes, int n_in,
                              void* d_out, int out_size) {
    const float* xq     = (const float*)d_in[0];
    const float* tmk    = (const float*)d_in[1];
    const float* tmv    = (const float*)d_in[2];
    const float* tmr    = (const float*)d_in[3];
    const float* tmg    = (const float*)d_in[4];
    const float* tdecay = (const float*)d_in[5];
    const float* tfa    = (const float*)d_in[6];
    const float* Wr     = (const float*)d_in[7];
    const float* Wk     = (const float*)d_in[8];
    const float* Wv     = (const float*)d_in[9];
    const float* Wg     = (const float*)d_in[10];
    const float* Wo     = (const float*)d_in[11];
    const float* lnw    = (const float*)d_in[12];
    const float* lnb    = (const float*)d_in[13];
    float* out = (float*)d_out;

    __nv_bfloat16 *pxr_h, *pxr_l, *pxk_h, *pxk_l, *pxv_h, *pxv_l, *pxg_h, *pxg_l;
    __nv_bfloat16 *pz_h, *pz_l;
    __nv_bfloat16 *pwr_h, *pwr_l, *pwk_h, *pwk_l, *pwv_h, *pwv_l, *pwg_h, *pwg_l,
                  *pwo_h, *pwo_l;
    float *pr, *pk, *pv, *pg;
    cudaGetSymbolAddress((void**)&pxr_h, g_xr_h); cudaGetSymbolAddress((void**)&pxr_l, g_xr_l);
    cudaGetSymbolAddress((void**)&pxk_h, g_xk_h); cudaGetSymbolAddress((void**)&pxk_l, g_xk_l);
    cudaGetSymbolAddress((void**)&pxv_h, g_xv_h); cudaGetSymbolAddress((void**)&pxv_l, g_xv_l);
    cudaGetSymbolAddress((void**)&pxg_h, g_xg_h); cudaGetSymbolAddress((void**)&pxg_l, g_xg_l);
    cudaGetSymbolAddress((void**)&pz_h,  g_z_h);  cudaGetSymbolAddress((void**)&pz_l,  g_z_l);
    cudaGetSymbolAddress((void**)&pwr_h, g_wr_h); cudaGetSymbolAddress((void**)&pwr_l, g_wr_l);
    cudaGetSymbolAddress((void**)&pwk_h, g_wk_h); cudaGetSymbolAddress((void**)&pwk_l, g_wk_l);
    cudaGetSymbolAddress((void**)&pwv_h, g_wv_h); cudaGetSymbolAddress((void**)&pwv_l, g_wv_l);
    cudaGetSymbolAddress((void**)&pwg_h, g_wg_h); cudaGetSymbolAddress((void**)&pwg_l, g_wg_l);
    cudaGetSymbolAddress((void**)&pwo_h, g_wo_h); cudaGetSymbolAddress((void**)&pwo_l, g_wo_l);
    cudaGetSymbolAddress((void**)&pr, g_r); cudaGetSymbolAddress((void**)&pk, g_k);
    cudaGetSymbolAddress((void**)&pv, g_v); cudaGetSymbolAddress((void**)&pg, g_g);

    wsplit5_kernel<<<dim3(CC * CC / 256, 5), 256>>>(
        Wr, Wk, Wv, Wg, Wo,
        pwr_h, pwr_l, pwk_h, pwk_l, pwv_h, pwv_l, pwg_h, pwg_l, pwo_h, pwo_l);

    mix_kernel<<<MM * CC / 256, 256>>>(xq, tmk, tmv, tmr, tmg);

    cudaFuncSetAttribute(gemm_mma, cudaFuncAttributeMaxDynamicSharedMemorySize,
                         GSM_TOTAL);
    dim3 gg(CC / 128, MM / 128);
    gemm_mma<<<gg, 256, GSM_TOTAL>>>(pxr_h, pxr_l, pwr_h, pwr_l, pr);
    gemm_mma<<<gg, 256, GSM_TOTAL>>>(pxk_h, pxk_l, pwk_h, pwk_l, pk);
    gemm_mma<<<gg, 256, GSM_TOTAL>>>(pxv_h, pxv_l, pwv_h, pwv_l, pv);
    gemm_mma<<<gg, 256, GSM_TOTAL>>>(pxg_h, pxg_l, pwg_h, pwg_l, pg);

    state_kernel<<<dim3(BB * HH, 4), 256>>>(tdecay);

    size_t out_smem = OUT_SMEM_FLOATS * sizeof(float);
    cudaFuncSetAttribute(out_kernel, cudaFuncAttributeMaxDynamicSharedMemorySize,
                         (int)out_smem);
    out_kernel<<<BB * HH * NCH, 256, out_smem>>>(tdecay, tfa);

    gn_gate_kernel<<<(MM * HH * 32) / 256, 256>>>(lnw, lnb);

    gemm_mma<<<gg, 256, GSM_TOTAL>>>(pz_h, pz_l, pwo_h, pwo_l, out);
}

// round 7
// speedup vs baseline: 1.6634x; 1.6634x over previous
#include <cuda_runtime.h>
#include <cuda_bf16.h>
#include <stdint.h>
#include <math.h>

// Problem constants
#define BB   4
#define TTT  4096
#define CC   1024
#define HH   16
#define KD   64          // head dim
#define TCH  128         // chunk length
#define NCH  32          // chunks
#define MM   (BB*TTT)    // 16384 rows

// ---------------- scratch (device globals; no allocation allowed) ----------
__device__ __nv_bfloat16 g_xr_h[MM*CC], g_xr_l[MM*CC];
__device__ __nv_bfloat16 g_xk_h[MM*CC], g_xk_l[MM*CC];
__device__ __nv_bfloat16 g_xv_h[MM*CC], g_xv_l[MM*CC];
__device__ __nv_bfloat16 g_xg_h[MM*CC], g_xg_l[MM*CC];
__device__ __nv_bfloat16 g_z_h [MM*CC], g_z_l [MM*CC];
__device__ __nv_bfloat16 g_wr_h[CC*CC], g_wr_l[CC*CC];
__device__ __nv_bfloat16 g_wk_h[CC*CC], g_wk_l[CC*CC];
__device__ __nv_bfloat16 g_wv_h[CC*CC], g_wv_l[CC*CC];
__device__ __nv_bfloat16 g_wg_h[CC*CC], g_wg_l[CC*CC];
__device__ __nv_bfloat16 g_wo_h[CC*CC], g_wo_l[CC*CC];
__device__ float g_r [MM*CC];
__device__ float g_k [MM*CC];
__device__ float g_v [MM*CC];
__device__ float g_g [MM*CC];
__device__ float g_xo[MM*CC];
__device__ float g_states[BB*HH*NCH*KD*KD];

// ---------------- helpers ---------------------------------------------------
__device__ __forceinline__ void split_store(__nv_bfloat16* ah, __nv_bfloat16* al,
                                            size_t i, float v) {
    __nv_bfloat16 h = __float2bfloat16(v);
    ah[i] = h;
    al[i] = __float2bfloat16(v - __bfloat162float(h));
}

__device__ __forceinline__ void mma_bf16(float* c, const uint32_t* a,
                                         uint32_t b0, uint32_t b1) {
    asm volatile(
        "mma.sync.aligned.m16n8k16.row.col.f32.bf16.bf16.f32 "
        "{%0,%1,%2,%3}, {%4,%5,%6,%7}, {%8,%9}, {%0,%1,%2,%3};"
        : "+f"(c[0]), "+f"(c[1]), "+f"(c[2]), "+f"(c[3])
        : "r"(a[0]), "r"(a[1]), "r"(a[2]), "r"(a[3]), "r"(b0), "r"(b1));
}

__device__ __forceinline__ uint32_t smem_u32(const void* p) {
    uint32_t a;
    asm("{ .reg .u64 t; cvta.to.shared.u64 t, %1; cvt.u32.u64 %0, t; }"
        : "=r"(a) : "l"(p));
    return a;
}
__device__ __forceinline__ void cp16(uint32_t saddr, const void* g) {
    asm volatile("cp.async.cg.shared.global [%0], [%1], 16;" :: "r"(saddr), "l"(g));
}
__device__ __forceinline__ void cp_commit() {
    asm volatile("cp.async.commit_group;");
}
__device__ __forceinline__ void cp_wait1() {
    asm volatile("cp.async.wait_group 1;");
}
__device__ __forceinline__ void ldsm4(uint32_t* r, uint32_t addr) {
    asm volatile("ldmatrix.sync.aligned.m8n8.x4.shared.b16 {%0,%1,%2,%3}, [%4];"
                 : "=r"(r[0]), "=r"(r[1]), "=r"(r[2]), "=r"(r[3]) : "r"(addr));
}

// swizzled byte offset within a 128-row x 64B tile: row r, 16B-unit u (0..3)
__device__ __forceinline__ uint32_t swz(int r, int u) {
    return (uint32_t)(r * 64 + ((u ^ ((r >> 1) & 3)) << 4));
}

// ---------------- 0) weight split fp32 -> bf16 hi/lo (all 5 fused) ---------
__global__ void wsplit5_kernel(const float* __restrict__ W0, const float* __restrict__ W1,
                               const float* __restrict__ W2, const float* __restrict__ W3,
                               const float* __restrict__ W4,
                               __nv_bfloat16* __restrict__ H0, __nv_bfloat16* __restrict__ L0,
                               __nv_bfloat16* __restrict__ H1, __nv_bfloat16* __restrict__ L1,
                               __nv_bfloat16* __restrict__ H2, __nv_bfloat16* __restrict__ L2,
                               __nv_bfloat16* __restrict__ H3, __nv_bfloat16* __restrict__ L3,
                               __nv_bfloat16* __restrict__ H4, __nv_bfloat16* __restrict__ L4) {
    int i = blockIdx.x * blockDim.x + threadIdx.x;
    const float* W; __nv_bfloat16 *Hh, *Ll;
    switch (blockIdx.y) {
        case 0: W = W0; Hh = H0; Ll = L0; break;
        case 1: W = W1; Hh = H1; Ll = L1; break;
        case 2: W = W2; Hh = H2; Ll = L2; break;
        case 3: W = W3; Hh = H3; Ll = L3; break;
        default: W = W4; Hh = H4; Ll = L4; break;
    }
    split_store(Hh, Ll, i, W[i]);
}

// ---------------- 1) time-shift mixing -> bf16 hi/lo ----------------------
__global__ void mix_kernel(const float* __restrict__ x,
                           const float* __restrict__ tmk,
                           const float* __restrict__ tmv,
                           const float* __restrict__ tmr,
                           const float* __restrict__ tmg) {
    int idx = blockIdx.x * blockDim.x + threadIdx.x;   // MM*CC total
    int c = idx & (CC - 1);
    int t = (idx >> 10) & (TTT - 1);
    float xc = x[idx];
    float xp = t ? x[idx - CC] : 0.f;
    float mr = tmr[c]; split_store(g_xr_h, g_xr_l, idx, xc * mr + xp * (1.f - mr));
    float mk = tmk[c]; split_store(g_xk_h, g_xk_l, idx, xc * mk + xp * (1.f - mk));
    float mv = tmv[c]; split_store(g_xv_h, g_xv_l, idx, xc * mv + xp * (1.f - mv));
    float mg = tmg[c]; split_store(g_xg_h, g_xg_l, idx, xc * mg + xp * (1.f - mg));
}

// ---------------- 2) mma.sync GEMM: C = A @ W^T (bf16 hi/lo, 3 passes) -----
// CTA tile 128x128, 8 warps (warp tile 32x64), K-chunk 32.
// Swizzled 64B-row smem tiles (8KB each), 3-stage cp.async pipeline,
// ONE __syncthreads per chunk. 96KB smem/CTA -> 2 CTAs/SM.
#define KCH     32
#define TILE_B  8192                     // 128 rows x 64B
#define BUF_B   (4*TILE_B)               // Ah, Al, Bh, Bl
#define GSM_TOTAL (3*BUF_B)              // 98304 B
#define NKC     (CC/KCH)                 // 32 chunks

__global__ void __launch_bounds__(256, 2)
gemm_mma(const __nv_bfloat16* __restrict__ A0h, const __nv_bfloat16* __restrict__ A0l,
         const __nv_bfloat16* __restrict__ B0h, const __nv_bfloat16* __restrict__ B0l,
         float* __restrict__ C0,
         const __nv_bfloat16* __restrict__ A1h, const __nv_bfloat16* __restrict__ A1l,
         const __nv_bfloat16* __restrict__ B1h, const __nv_bfloat16* __restrict__ B1l,
         float* __restrict__ C1,
         const __nv_bfloat16* __restrict__ A2h, const __nv_bfloat16* __restrict__ A2l,
         const __nv_bfloat16* __restrict__ B2h, const __nv_bfloat16* __restrict__ B2l,
         float* __restrict__ C2,
         const __nv_bfloat16* __restrict__ A3h, const __nv_bfloat16* __restrict__ A3l,
         const __nv_bfloat16* __restrict__ B3h, const __nv_bfloat16* __restrict__ B3l,
         float* __restrict__ C3) {
    extern __shared__ char dsm[];
    uint32_t sbase = smem_u32(dsm);
    int tid = threadIdx.x;
    int w   = tid >> 5;
    int lane = tid & 31;
    int g = lane >> 2;           // group id 0..7
    int t = lane & 3;            // thread-in-group
    int n0 = blockIdx.x * 128;
    int m0 = blockIdx.y * 128;
    int m0w = (w >> 1) * 32;     // warp M offset in tile
    int n0w = (w & 1) * 64;      // warp N offset in tile

    const __nv_bfloat16 *Ah, *Al, *Bh, *Bl; float* C;
    switch (blockIdx.z) {
        case 0: Ah = A0h; Al = A0l; Bh = B0h; Bl = B0l; C = C0; break;
        case 1: Ah = A1h; Al = A1l; Bh = B1h; Bl = B1l; C = C1; break;
        case 2: Ah = A2h; Al = A2l; Bh = B2h; Bl = B2l; C = C2; break;
        default: Ah = A3h; Al = A3l; Bh = B3h; Bl = B3l; C = C3; break;
    }
    const __nv_bfloat16* sAh = Ah + (size_t)m0 * CC;
    const __nv_bfloat16* sAl = Al + (size_t)m0 * CC;
    const __nv_bfloat16* sBh = Bh + (size_t)n0 * CC;
    const __nv_bfloat16* sBl = Bl + (size_t)n0 * CC;

    // cp.async coords: thread handles rows r0, r0+64 at 16B-unit u
    int r0 = tid >> 2, u = tid & 3;
    size_t go0 = (size_t)r0 * CC + u * 8;
    size_t go1 = go0 + (size_t)64 * CC;
    uint32_t so0 = swz(r0, u);           // (r0+64) swizzle == same unit perm
    uint32_t so1 = so0 + 64 * 64;

    // ldmatrix per-lane components
    int arow = lane & 15;
    int akof = (lane >> 4) << 3;
    int brow = ((lane >> 4) << 3) + (lane & 7);
    int bkof = ((lane >> 3) & 1) << 3;
    int rowA0 = m0w + arow, rowA1 = m0w + 16 + arow;

    float acc[2][8][4];
#pragma unroll
    for (int mi = 0; mi < 2; mi++)
#pragma unroll
        for (int ni = 0; ni < 8; ni++)
#pragma unroll
            for (int q = 0; q < 4; q++) acc[mi][ni][q] = 0.f;

    // issue chunk -> buf (chunk % 3)
    auto issue = [&](int chunk) {
        int k0 = chunk * KCH;
        uint32_t b = sbase + (uint32_t)((chunk % 3) * BUF_B);
        cp16(b + 0*TILE_B + so0, sAh + go0 + k0); cp16(b + 0*TILE_B + so1, sAh + go1 + k0);
        cp16(b + 1*TILE_B + so0, sAl + go0 + k0); cp16(b + 1*TILE_B + so1, sAl + go1 + k0);
        cp16(b + 2*TILE_B + so0, sBh + go0 + k0); cp16(b + 2*TILE_B + so1, sBh + go1 + k0);
        cp16(b + 3*TILE_B + so0, sBl + go0 + k0); cp16(b + 3*TILE_B + so1, sBl + go1 + k0);
        cp_commit();
    };

    issue(0);
    issue(1);

    for (int c = 0; c < NKC; ++c) {
        cp_wait1();               // chunk c's group complete (c+1 may fly)
        __syncthreads();          // visibility + buffer-reuse protection
        if (c + 2 < NKC) issue(c + 2);

        uint32_t sb = sbase + (uint32_t)((c % 3) * BUF_B);
        uint32_t tAh = sb;
        uint32_t tAl = sb + TILE_B;
        uint32_t tBh = sb + 2 * TILE_B;
        uint32_t tBl = sb + 3 * TILE_B;
#pragma unroll
        for (int ks = 0; ks < 2; ++ks) {
            int kk = ks * 16;
            int uA = (kk + akof) >> 3;
            uint32_t ah[2][4], al[2][4];
            {
                uint32_t o0 = swz(rowA0, uA), o1 = swz(rowA1, uA);
                ldsm4(ah[0], tAh + o0);
                ldsm4(ah[1], tAh + o1);
                ldsm4(al[0], tAl + o0);
                ldsm4(al[1], tAl + o1);
            }
            int uB = (kk + bkof) >> 3;
#pragma unroll
            for (int np = 0; np < 4; np++) {
                uint32_t bo = swz(n0w + np * 16 + brow, uB);
                uint32_t bh4[4], bl4[4];
                ldsm4(bh4, tBh + bo);
                ldsm4(bl4, tBl + bo);
#pragma unroll
                for (int sub = 0; sub < 2; sub++) {
                    int ni = np * 2 + sub;
                    uint32_t b0h = bh4[sub * 2], b1h = bh4[sub * 2 + 1];
                    uint32_t b0l = bl4[sub * 2], b1l = bl4[sub * 2 + 1];
#pragma unroll
                    for (int mi = 0; mi < 2; mi++) {
                        mma_bf16(acc[mi][ni], ah[mi], b0h, b1h);
                        mma_bf16(acc[mi][ni], ah[mi], b0l, b1l);
                        mma_bf16(acc[mi][ni], al[mi], b0h, b1h);
                    }
                }
            }
        }
    }

    // epilogue: write fp32
#pragma unroll
    for (int mi = 0; mi < 2; mi++) {
        int r = m0 + m0w + mi * 16 + g;
#pragma unroll
        for (int ni = 0; ni < 8; ni++) {
            int col = n0 + n0w + ni * 8 + 2 * t;
            *(float2*)&C[(size_t)r * CC + col] =
                make_float2(acc[mi][ni][0], acc[mi][ni][1]);
            *(float2*)&C[(size_t)(r + 8) * CC + col] =
                make_float2(acc[mi][ni][2], acc[mi][ni][3]);
        }
    }
}

// ---------------- 3) chunk-boundary states (sequential recurrence) ---------
__global__ void __launch_bounds__(256)
state_kernel(const float* __restrict__ tdecay) {
    __shared__ float kw[TCH * KD];
    __shared__ float vsh[TCH * 16];
    __shared__ float dp[TCH + 1];
    int bh = blockIdx.x;
    int vs = blockIdx.y;
    int b = bh >> 4, h = bh & 15;
    int tid = threadIdx.x;
    float decay = expf(-expf(tdecay[h]));
    if (tid <= TCH) dp[tid] = powf(decay, (float)tid);
    __syncthreads();
    float ws = dp[TCH];
    int tr = tid >> 2;
    int tc = (tid & 3) * 4;
    float s0 = 0.f, s1 = 0.f, s2 = 0.f, s3 = 0.f;
    const float* kb = g_k + ((size_t)b * TTT) * CC + h * KD;
    const float* vb = g_v + ((size_t)b * TTT) * CC + h * KD + vs * 16;
    float* stb = g_states + ((size_t)bh * NCH) * KD * KD;
    for (int n = 0; n < NCH; n++) {
        float* sd = stb + (size_t)n * KD * KD + tr * KD + vs * 16 + tc;
        sd[0] = s0; sd[1] = s1; sd[2] = s2; sd[3] = s3;
        __syncthreads();
        for (int e = tid; e < TCH * KD; e += 256) {
            int j = e >> 6, kk2 = e & 63;
            kw[e] = kb[(size_t)(n * TCH + j) * CC + kk2] * dp[127 - j];
        }
        for (int e = tid; e < TCH * 16; e += 256) {
            int j = e >> 4, cc2 = e & 15;
            vsh[e] = vb[(size_t)(n * TCH + j) * CC + cc2];
        }
        __syncthreads();
        float a0 = 0.f, a1 = 0.f, a2 = 0.f, a3 = 0.f;
#pragma unroll 4
        for (int j = 0; j < TCH; j++) {
            float kv = kw[j * KD + tr];
            float4 v4 = *(const float4*)&vsh[j * 16 + tc];
            a0 = fmaf(kv, v4.x, a0); a1 = fmaf(kv, v4.y, a1);
            a2 = fmaf(kv, v4.z, a2); a3 = fmaf(kv, v4.w, a3);
        }
        s0 = ws * s0 + a0; s1 = ws * s1 + a1;
        s2 = ws * s2 + a2; s3 = ws * s3 + a3;
    }
}

// ---------------- 4) per-chunk attention output (parallel) -----------------
#define OUT_SMEM_FLOATS (TCH*65 + TCH*65 + TCH*KD + KD*KD + TCH*129)
__global__ void __launch_bounds__(256)
out_kernel(const float* __restrict__ tdecay, const float* __restrict__ tfa) {
    extern __shared__ float sm[];
    float* rs  = sm;
    float* ksm = rs  + TCH * 65;
    float* vsm = ksm + TCH * 65;
    float* ssm = vsm + TCH * KD;
    float* att = ssm + KD * KD;
    __shared__ float dp[TCH];
    int bhn = blockIdx.x;
    int n  = bhn & (NCH - 1);
    int bh = bhn >> 5;
    int h = bh & 15, b = bh >> 4;
    int tid = threadIdx.x;
    float decay = expf(-expf(tdecay[h]));
    if (tid < TCH) dp[tid] = powf(decay, (float)tid);
    float u = tfa[h];
    size_t base = ((size_t)(b * TTT + n * TCH)) * CC + h * KD;
    for (int e = tid; e < TCH * KD; e += 256) {
        int i = e >> 6, k2 = e & 63;
        size_t gi = base + (size_t)i * CC + k2;
        rs [i * 65 + k2] = g_r[gi];
        ksm[i * 65 + k2] = g_k[gi];
        vsm[e]           = g_v[gi];
    }
    const float* stp = g_states + ((size_t)bh * NCH + n) * KD * KD;
    for (int e = tid; e < KD * KD; e += 256) ssm[e] = stp[e];
    __syncthreads();
    {
        int i0 = (tid >> 4) * 8, j0 = (tid & 15) * 8;
        float acc[8][8];
#pragma unroll
        for (int i = 0; i < 8; i++)
#pragma unroll
            for (int j = 0; j < 8; j++) acc[i][j] = 0.f;
        for (int k2 = 0; k2 < KD; k2++) {
            float ra[8], rb[8];
#pragma unroll
            for (int ii = 0; ii < 8; ii++) ra[ii] = rs[(i0 + ii) * 65 + k2];
#pragma unroll
            for (int jj = 0; jj < 8; jj++) rb[jj] = ksm[(j0 + jj) * 65 + k2];
#pragma unroll
            for (int ii = 0; ii < 8; ii++)
#pragma unroll
                for (int jj = 0; jj < 8; jj++)
                    acc[ii][jj] = fmaf(ra[ii], rb[jj], acc[ii][jj]);
        }
#pragma unroll
        for (int ii = 0; ii < 8; ii++)
#pragma unroll
            for (int jj = 0; jj < 8; jj++) {
                int i = i0 + ii, j = j0 + jj, d = i - j;
                float w = (d > 0) ? dp[d - 1] : ((d == 0) ? u : 0.f);
                att[i * 129 + j] = acc[ii][jj] * w;
            }
    }
    __syncthreads();
    {
        int i0 = (tid >> 3) * 4, v0 = (tid & 7) * 8;
        float aA[4][8], aB[4][8];
#pragma unroll
        for (int i = 0; i < 4; i++)
#pragma unroll
            for (int j = 0; j < 8; j++) { aA[i][j] = 0.f; aB[i][j] = 0.f; }
        for (int j = 0; j < TCH; j++) {
            float a4[4];
#pragma unroll
            for (int ii = 0; ii < 4; ii++) a4[ii] = att[(i0 + ii) * 129 + j];
            float4 va = *(const float4*)&vsm[j * KD + v0];
            float4 vb2 = *(const float4*)&vsm[j * KD + v0 + 4];
            float vv[8] = {va.x, va.y, va.z, va.w, vb2.x, vb2.y, vb2.z, vb2.w};
#pragma unroll
            for (int ii = 0; ii < 4; ii++)
#pragma unroll
                for (int jj = 0; jj < 8; jj++)
                    aA[ii][jj] = fmaf(a4[ii], vv[jj], aA[ii][jj]);
        }
        for (int k2 = 0; k2 < KD; k2++) {
            float r4[4];
#pragma unroll
            for (int ii = 0; ii < 4; ii++) r4[ii] = rs[(i0 + ii) * 65 + k2];
            float4 sa = *(const float4*)&ssm[k2 * KD + v0];
            float4 sb = *(const float4*)&ssm[k2 * KD + v0 + 4];
            float sv[8] = {sa.x, sa.y, sa.z, sa.w, sb.x, sb.y, sb.z, sb.w};
#pragma unroll
            for (int ii = 0; ii < 4; ii++)
#pragma unroll
                for (int jj = 0; jj < 8; jj++)
                    aB[ii][jj] = fmaf(r4[ii], sv[jj], aB[ii][jj]);
        }
#pragma unroll
        for (int ii = 0; ii < 4; ii++) {
            float wbv = dp[i0 + ii];
#pragma unroll
            for (int jj = 0; jj < 8; jj++)
                g_xo[base + (size_t)(i0 + ii) * CC + v0 + jj] =
                    aA[ii][jj] + wbv * aB[ii][jj];
        }
    }
}

// ---------------- 5) GroupNorm(/8) + silu gate -> bf16 hi/lo ---------------
__global__ void gn_gate_kernel(const float* __restrict__ lnw,
                               const float* __restrict__ lnb) {
    int gidx = blockIdx.x * blockDim.x + threadIdx.x;
    int warp = gidx >> 5, lane = gidx & 31;
    size_t basep = (size_t)warp * 64;
    float a  = g_xo[basep + lane]      * 0.125f;
    float c2 = g_xo[basep + 32 + lane] * 0.125f;
    float s = a + c2, sq = a * a + c2 * c2;
#pragma unroll
    for (int o = 16; o; o >>= 1) {
        s  += __shfl_xor_sync(0xffffffffu, s,  o);
        sq += __shfl_xor_sync(0xffffffffu, sq, o);
    }
    float mu  = s * (1.f / 64.f);
    float var = sq * (1.f / 64.f) - mu * mu;
    float inv = rsqrtf(var + 1e-5f);
    int h = warp & 15;
    int cb = h * 64;
    float g0r = g_g[basep + lane];
    float g1r = g_g[basep + 32 + lane];
    float y0 = ((a  - mu) * inv) * lnw[cb + lane]      + lnb[cb + lane];
    float y1 = ((c2 - mu) * inv) * lnw[cb + 32 + lane] + lnb[cb + 32 + lane];
    split_store(g_z_h, g_z_l, basep + lane,      y0 * (g0r / (1.f + expf(-g0r))));
    split_store(g_z_h, g_z_l, basep + 32 + lane, y1 * (g1r / (1.f + expf(-g1r))));
}

// ---------------- launch ---------------------------------------------------
extern "C" void kernel_launch(void* const* d_in, const int* in_sizes, int n_in,
                              void* d_out, int out_size) {
    const float* xq     = (const float*)d_in[0];
    const float* tmk    = (const float*)d_in[1];
    const float* tmv    = (const float*)d_in[2];
    const float* tmr    = (const float*)d_in[3];
    const float* tmg    = (const float*)d_in[4];
    const float* tdecay = (const float*)d_in[5];
    const float* tfa    = (const float*)d_in[6];
    const float* Wr     = (const float*)d_in[7];
    const float* Wk     = (const float*)d_in[8];
    const float* Wv     = (const float*)d_in[9];
    const float* Wg     = (const float*)d_in[10];
    const float* Wo     = (const float*)d_in[11];
    const float* lnw    = (const float*)d_in[12];
    const float* lnb    = (const float*)d_in[13];
    float* out = (float*)d_out;

    __nv_bfloat16 *pxr_h, *pxr_l, *pxk_h, *pxk_l, *pxv_h, *pxv_l, *pxg_h, *pxg_l;
    __nv_bfloat16 *pz_h, *pz_l;
    __nv_bfloat16 *pwr_h, *pwr_l, *pwk_h, *pwk_l, *pwv_h, *pwv_l, *pwg_h, *pwg_l,
                  *pwo_h, *pwo_l;
    float *pr, *pk, *pv, *pg;
    cudaGetSymbolAddress((void**)&pxr_h, g_xr_h); cudaGetSymbolAddress((void**)&pxr_l, g_xr_l);
    cudaGetSymbolAddress((void**)&pxk_h, g_xk_h); cudaGetSymbolAddress((void**)&pxk_l, g_xk_l);
    cudaGetSymbolAddress((void**)&pxv_h, g_xv_h); cudaGetSymbolAddress((void**)&pxv_l, g_xv_l);
    cudaGetSymbolAddress((void**)&pxg_h, g_xg_h); cudaGetSymbolAddress((void**)&pxg_l, g_xg_l);
    cudaGetSymbolAddress((void**)&pz_h,  g_z_h);  cudaGetSymbolAddress((void**)&pz_l,  g_z_l);
    cudaGetSymbolAddress((void**)&pwr_h, g_wr_h); cudaGetSymbolAddress((void**)&pwr_l, g_wr_l);
    cudaGetSymbolAddress((void**)&pwk_h, g_wk_h); cudaGetSymbolAddress((void**)&pwk_l, g_wk_l);
    cudaGetSymbolAddress((void**)&pwv_h, g_wv_h); cudaGetSymbolAddress((void**)&pwv_l, g_wv_l);
    cudaGetSymbolAddress((void**)&pwg_h, g_wg_h); cudaGetSymbolAddress((void**)&pwg_l, g_wg_l);
    cudaGetSymbolAddress((void**)&pwo_h, g_wo_h); cudaGetSymbolAddress((void**)&pwo_l, g_wo_l);
    cudaGetSymbolAddress((void**)&pr, g_r); cudaGetSymbolAddress((void**)&pk, g_k);
    cudaGetSymbolAddress((void**)&pv, g_v); cudaGetSymbolAddress((void**)&pg, g_g);

    wsplit5_kernel<<<dim3(CC * CC / 256, 5), 256>>>(
        Wr, Wk, Wv, Wg, Wo,
        pwr_h, pwr_l, pwk_h, pwk_l, pwv_h, pwv_l, pwg_h, pwg_l, pwo_h, pwo_l);

    mix_kernel<<<MM * CC / 256, 256>>>(xq, tmk, tmv, tmr, tmg);

    cudaFuncSetAttribute(gemm_mma, cudaFuncAttributeMaxDynamicSharedMemorySize,
                         GSM_TOTAL);
    // fused r/k/v/g projections: gridDim.z = 4
    gemm_mma<<<dim3(CC / 128, MM / 128, 4), 256, GSM_TOTAL>>>(
        pxr_h, pxr_l, pwr_h, pwr_l, pr,
        pxk_h, pxk_l, pwk_h, pwk_l, pk,
        pxv_h, pxv_l, pwv_h, pwv_l, pv,
        pxg_h, pxg_l, pwg_h, pwg_l, pg);

    state_kernel<<<dim3(BB * HH, 4), 256>>>(tdecay);

    size_t out_smem = OUT_SMEM_FLOATS * sizeof(float);
    cudaFuncSetAttribute(out_kernel, cudaFuncAttributeMaxDynamicSharedMemorySize,
                         (int)out_smem);
    out_kernel<<<BB * HH * NCH, 256, out_smem>>>(tdecay, tfa);

    gn_gate_kernel<<<(MM * HH * 32) / 256, 256>>>(lnw, lnb);

    // output projection (single GEMM via slot 0)
    gemm_mma<<<dim3(CC / 128, MM / 128, 1), 256, GSM_TOTAL>>>(
        pz_h, pz_l, pwo_h, pwo_l, out,
        pz_h, pz_l, pwo_h, pwo_l, out,
        pz_h, pz_l, pwo_h, pwo_l, out,
        pz_h, pz_l, pwo_h, pwo_l, out);
}

// round 8
// speedup vs baseline: 1.7335x; 1.0421x over previous
#include <cuda_runtime.h>
#include <cuda_bf16.h>
#include <stdint.h>
#include <math.h>

// Problem constants
#define BB   4
#define TTT  4096
#define CC   1024
#define HH   16
#define KD   64          // head dim
#define TCH  128         // chunk length
#define NCH  32          // chunks
#define MM   (BB*TTT)    // 16384 rows

// ---------------- scratch (device globals; no allocation allowed) ----------
__device__ __nv_bfloat16 g_xr_h[MM*CC], g_xr_l[MM*CC];
__device__ __nv_bfloat16 g_xk_h[MM*CC], g_xk_l[MM*CC];
__device__ __nv_bfloat16 g_xv_h[MM*CC], g_xv_l[MM*CC];
__device__ __nv_bfloat16 g_xg_h[MM*CC], g_xg_l[MM*CC];
__device__ __nv_bfloat16 g_z_h [MM*CC], g_z_l [MM*CC];
__device__ __nv_bfloat16 g_wr_h[CC*CC], g_wr_l[CC*CC];
__device__ __nv_bfloat16 g_wk_h[CC*CC], g_wk_l[CC*CC];
__device__ __nv_bfloat16 g_wv_h[CC*CC], g_wv_l[CC*CC];
__device__ __nv_bfloat16 g_wg_h[CC*CC], g_wg_l[CC*CC];
__device__ __nv_bfloat16 g_wo_h[CC*CC], g_wo_l[CC*CC];
__device__ float g_r [MM*CC];
__device__ float g_k [MM*CC];
__device__ float g_v [MM*CC];
__device__ float g_g [MM*CC];
__device__ float g_xo[MM*CC];
__device__ float g_states[BB*HH*NCH*KD*KD];

// ---------------- helpers ---------------------------------------------------
__device__ __forceinline__ void split_store(__nv_bfloat16* ah, __nv_bfloat16* al,
                                            size_t i, float v) {
    __nv_bfloat16 h = __float2bfloat16(v);
    ah[i] = h;
    al[i] = __float2bfloat16(v - __bfloat162float(h));
}

__device__ __forceinline__ void mma_bf16(float* c, const uint32_t* a,
                                         uint32_t b0, uint32_t b1) {
    asm volatile(
        "mma.sync.aligned.m16n8k16.row.col.f32.bf16.bf16.f32 "
        "{%0,%1,%2,%3}, {%4,%5,%6,%7}, {%8,%9}, {%0,%1,%2,%3};"
        : "+f"(c[0]), "+f"(c[1]), "+f"(c[2]), "+f"(c[3])
        : "r"(a[0]), "r"(a[1]), "r"(a[2]), "r"(a[3]), "r"(b0), "r"(b1));
}

__device__ __forceinline__ uint32_t smem_u32(const void* p) {
    uint32_t a;
    asm("{ .reg .u64 t; cvta.to.shared.u64 t, %1; cvt.u32.u64 %0, t; }"
        : "=r"(a) : "l"(p));
    return a;
}
__device__ __forceinline__ void cp16(uint32_t saddr, const void* g) {
    asm volatile("cp.async.cg.shared.global [%0], [%1], 16;" :: "r"(saddr), "l"(g));
}
__device__ __forceinline__ void cp_commit() {
    asm volatile("cp.async.commit_group;");
}
__device__ __forceinline__ void cp_wait1() {
    asm volatile("cp.async.wait_group 1;");
}
__device__ __forceinline__ void ldsm4(uint32_t* r, uint32_t addr) {
    asm volatile("ldmatrix.sync.aligned.m8n8.x4.shared.b16 {%0,%1,%2,%3}, [%4];"
                 : "=r"(r[0]), "=r"(r[1]), "=r"(r[2]), "=r"(r[3]) : "r"(addr));
}

// ---- packed fp32x2 (Blackwell double-pumped fp32) ----
typedef unsigned long long u64t;
__device__ __forceinline__ u64t fma2(u64t a, u64t b, u64t c) {
    u64t d;
    asm("fma.rn.f32x2 %0, %1, %2, %3;" : "=l"(d) : "l"(a), "l"(b), "l"(c));
    return d;
}
__device__ __forceinline__ u64t pack2(float x, float y) {
    u64t d;
    asm("mov.b64 %0, {%1, %2};" : "=l"(d) : "f"(x), "f"(y));
    return d;
}
__device__ __forceinline__ void unpack2(u64t v, float& x, float& y) {
    asm("mov.b64 {%0, %1}, %2;" : "=f"(x), "=f"(y) : "l"(v));
}

// swizzled byte offset within a 128-row x 64B tile: row r, 16B-unit u (0..3)
__device__ __forceinline__ uint32_t swz(int r, int u) {
    return (uint32_t)(r * 64 + ((u ^ ((r >> 1) & 3)) << 4));
}

// ---------------- 0) weight split fp32 -> bf16 hi/lo (all 5 fused) ---------
__global__ void wsplit5_kernel(const float* __restrict__ W0, const float* __restrict__ W1,
                               const float* __restrict__ W2, const float* __restrict__ W3,
                               const float* __restrict__ W4,
                               __nv_bfloat16* __restrict__ H0, __nv_bfloat16* __restrict__ L0,
                               __nv_bfloat16* __restrict__ H1, __nv_bfloat16* __restrict__ L1,
                               __nv_bfloat16* __restrict__ H2, __nv_bfloat16* __restrict__ L2,
                               __nv_bfloat16* __restrict__ H3, __nv_bfloat16* __restrict__ L3,
                               __nv_bfloat16* __restrict__ H4, __nv_bfloat16* __restrict__ L4) {
    int i = blockIdx.x * blockDim.x + threadIdx.x;
    const float* W; __nv_bfloat16 *Hh, *Ll;
    switch (blockIdx.y) {
        case 0: W = W0; Hh = H0; Ll = L0; break;
        case 1: W = W1; Hh = H1; Ll = L1; break;
        case 2: W = W2; Hh = H2; Ll = L2; break;
        case 3: W = W3; Hh = H3; Ll = L3; break;
        default: W = W4; Hh = H4; Ll = L4; break;
    }
    split_store(Hh, Ll, i, W[i]);
}

// ---------------- 1) time-shift mixing -> bf16 hi/lo ----------------------
__global__ void mix_kernel(const float* __restrict__ x,
                           const float* __restrict__ tmk,
                           const float* __restrict__ tmv,
                           const float* __restrict__ tmr,
                           const float* __restrict__ tmg) {
    int idx = blockIdx.x * blockDim.x + threadIdx.x;   // MM*CC total
    int c = idx & (CC - 1);
    int t = (idx >> 10) & (TTT - 1);
    float xc = x[idx];
    float xp = t ? x[idx - CC] : 0.f;
    float mr = tmr[c]; split_store(g_xr_h, g_xr_l, idx, xc * mr + xp * (1.f - mr));
    float mk = tmk[c]; split_store(g_xk_h, g_xk_l, idx, xc * mk + xp * (1.f - mk));
    float mv = tmv[c]; split_store(g_xv_h, g_xv_l, idx, xc * mv + xp * (1.f - mv));
    float mg = tmg[c]; split_store(g_xg_h, g_xg_l, idx, xc * mg + xp * (1.f - mg));
}

// ---------------- 2) mma.sync GEMM: C = A @ W^T (bf16 hi/lo, 3 passes) -----
#define KCH     32
#define TILE_B  8192                     // 128 rows x 64B
#define BUF_B   (4*TILE_B)               // Ah, Al, Bh, Bl
#define GSM_TOTAL (3*BUF_B)              // 98304 B
#define NKC     (CC/KCH)                 // 32 chunks

__global__ void __launch_bounds__(256, 2)
gemm_mma(const __nv_bfloat16* __restrict__ A0h, const __nv_bfloat16* __restrict__ A0l,
         const __nv_bfloat16* __restrict__ B0h, const __nv_bfloat16* __restrict__ B0l,
         float* __restrict__ C0,
         const __nv_bfloat16* __restrict__ A1h, const __nv_bfloat16* __restrict__ A1l,
         const __nv_bfloat16* __restrict__ B1h, const __nv_bfloat16* __restrict__ B1l,
         float* __restrict__ C1,
         const __nv_bfloat16* __restrict__ A2h, const __nv_bfloat16* __restrict__ A2l,
         const __nv_bfloat16* __restrict__ B2h, const __nv_bfloat16* __restrict__ B2l,
         float* __restrict__ C2,
         const __nv_bfloat16* __restrict__ A3h, const __nv_bfloat16* __restrict__ A3l,
         const __nv_bfloat16* __restrict__ B3h, const __nv_bfloat16* __restrict__ B3l,
         float* __restrict__ C3) {
    extern __shared__ char dsm[];
    uint32_t sbase = smem_u32(dsm);
    int tid = threadIdx.x;
    int w   = tid >> 5;
    int lane = tid & 31;
    int g = lane >> 2;
    int t = lane & 3;
    int n0 = blockIdx.x * 128;
    int m0 = blockIdx.y * 128;
    int m0w = (w >> 1) * 32;
    int n0w = (w & 1) * 64;

    const __nv_bfloat16 *Ah, *Al, *Bh, *Bl; float* C;
    switch (blockIdx.z) {
        case 0: Ah = A0h; Al = A0l; Bh = B0h; Bl = B0l; C = C0; break;
        case 1: Ah = A1h; Al = A1l; Bh = B1h; Bl = B1l; C = C1; break;
        case 2: Ah = A2h; Al = A2l; Bh = B2h; Bl = B2l; C = C2; break;
        default: Ah = A3h; Al = A3l; Bh = B3h; Bl = B3l; C = C3; break;
    }
    const __nv_bfloat16* sAh = Ah + (size_t)m0 * CC;
    const __nv_bfloat16* sAl = Al + (size_t)m0 * CC;
    const __nv_bfloat16* sBh = Bh + (size_t)n0 * CC;
    const __nv_bfloat16* sBl = Bl + (size_t)n0 * CC;

    int r0 = tid >> 2, u = tid & 3;
    size_t go0 = (size_t)r0 * CC + u * 8;
    size_t go1 = go0 + (size_t)64 * CC;
    uint32_t so0 = swz(r0, u);
    uint32_t so1 = so0 + 64 * 64;

    int arow = lane & 15;
    int akof = (lane >> 4) << 3;
    int brow = ((lane >> 4) << 3) + (lane & 7);
    int bkof = ((lane >> 3) & 1) << 3;
    int rowA0 = m0w + arow, rowA1 = m0w + 16 + arow;

    float acc[2][8][4];
#pragma unroll
    for (int mi = 0; mi < 2; mi++)
#pragma unroll
        for (int ni = 0; ni < 8; ni++)
#pragma unroll
            for (int q = 0; q < 4; q++) acc[mi][ni][q] = 0.f;

    auto issue = [&](int chunk) {
        int k0 = chunk * KCH;
        uint32_t b = sbase + (uint32_t)((chunk % 3) * BUF_B);
        cp16(b + 0*TILE_B + so0, sAh + go0 + k0); cp16(b + 0*TILE_B + so1, sAh + go1 + k0);
        cp16(b + 1*TILE_B + so0, sAl + go0 + k0); cp16(b + 1*TILE_B + so1, sAl + go1 + k0);
        cp16(b + 2*TILE_B + so0, sBh + go0 + k0); cp16(b + 2*TILE_B + so1, sBh + go1 + k0);
        cp16(b + 3*TILE_B + so0, sBl + go0 + k0); cp16(b + 3*TILE_B + so1, sBl + go1 + k0);
        cp_commit();
    };

    issue(0);
    issue(1);

    for (int c = 0; c < NKC; ++c) {
        cp_wait1();
        __syncthreads();
        if (c + 2 < NKC) issue(c + 2);

        uint32_t sb = sbase + (uint32_t)((c % 3) * BUF_B);
        uint32_t tAh = sb;
        uint32_t tAl = sb + TILE_B;
        uint32_t tBh = sb + 2 * TILE_B;
        uint32_t tBl = sb + 3 * TILE_B;
#pragma unroll
        for (int ks = 0; ks < 2; ++ks) {
            int kk = ks * 16;
            int uA = (kk + akof) >> 3;
            uint32_t ah[2][4], al[2][4];
            {
                uint32_t o0 = swz(rowA0, uA), o1 = swz(rowA1, uA);
                ldsm4(ah[0], tAh + o0);
                ldsm4(ah[1], tAh + o1);
                ldsm4(al[0], tAl + o0);
                ldsm4(al[1], tAl + o1);
            }
            int uB = (kk + bkof) >> 3;
#pragma unroll
            for (int np = 0; np < 4; np++) {
                uint32_t bo = swz(n0w + np * 16 + brow, uB);
                uint32_t bh4[4], bl4[4];
                ldsm4(bh4, tBh + bo);
                ldsm4(bl4, tBl + bo);
#pragma unroll
                for (int sub = 0; sub < 2; sub++) {
                    int ni = np * 2 + sub;
                    uint32_t b0h = bh4[sub * 2], b1h = bh4[sub * 2 + 1];
                    uint32_t b0l = bl4[sub * 2], b1l = bl4[sub * 2 + 1];
#pragma unroll
                    for (int mi = 0; mi < 2; mi++) {
                        mma_bf16(acc[mi][ni], ah[mi], b0h, b1h);
                        mma_bf16(acc[mi][ni], ah[mi], b0l, b1l);
                        mma_bf16(acc[mi][ni], al[mi], b0h, b1h);
                    }
                }
            }
        }
    }

#pragma unroll
    for (int mi = 0; mi < 2; mi++) {
        int r = m0 + m0w + mi * 16 + g;
#pragma unroll
        for (int ni = 0; ni < 8; ni++) {
            int col = n0 + n0w + ni * 8 + 2 * t;
            *(float2*)&C[(size_t)r * CC + col] =
                make_float2(acc[mi][ni][0], acc[mi][ni][1]);
            *(float2*)&C[(size_t)(r + 8) * CC + col] =
                make_float2(acc[mi][ni][2], acc[mi][ni][3]);
        }
    }
}

// ---------------- 3a) per-chunk state contributions A_n (fully parallel) ---
// grid = B*H*N = 2048 blocks (blockIdx.x = bh*NCH + n), 256 threads.
// A_n[kk][vv] = sum_j k[j][kk]*decay^(127-j) * v[j][vv]  -> g_states[bhn]
#define SA_SMEM ((2*TCH*KD + TCH) * 4)
__global__ void __launch_bounds__(256)
stateA_kernel(const float* __restrict__ tdecay) {
    extern __shared__ float sa[];
    float* kw  = sa;                 // [128][64]
    float* vsh = sa + TCH * KD;      // [128][64]
    float* dp  = sa + 2 * TCH * KD;  // [128]
    int bhn = blockIdx.x;
    int n  = bhn & (NCH - 1);
    int bh = bhn >> 5;
    int b = bh >> 4, h = bh & 15;
    int tid = threadIdx.x;
    float decay = expf(-expf(tdecay[h]));
    if (tid < TCH) dp[tid] = powf(decay, (float)(TCH - 1 - tid));
    __syncthreads();
    const float* kb = g_k + ((size_t)(b * TTT + n * TCH)) * CC + h * KD;
    const float* vb = g_v + ((size_t)(b * TTT + n * TCH)) * CC + h * KD;
    for (int e = tid * 4; e < TCH * KD; e += 1024) {
        int j = e >> 6, c = e & 63;
        float4 k4 = *(const float4*)(kb + (size_t)j * CC + c);
        float wj = dp[j];
        k4.x *= wj; k4.y *= wj; k4.z *= wj; k4.w *= wj;
        *(float4*)&kw[e]  = k4;
        *(float4*)&vsh[e] = *(const float4*)(vb + (size_t)j * CC + c);
    }
    __syncthreads();
    int kk = tid >> 2;
    int c0 = (tid & 3) * 16;
    u64t acc2[8];
#pragma unroll
    for (int q = 0; q < 8; q++) acc2[q] = 0ull;
    for (int j = 0; j < TCH; j++) {
        float kv = kw[j * KD + kk];
        u64t kv2 = pack2(kv, kv);
        const u64t* vp = (const u64t*)&vsh[j * KD + c0];
#pragma unroll
        for (int q = 0; q < 8; q++) acc2[q] = fma2(kv2, vp[q], acc2[q]);
    }
    u64t* dst = (u64t*)(g_states + (size_t)bhn * (KD * KD) + kk * KD + c0);
#pragma unroll
    for (int q = 0; q < 8; q++) dst[q] = acc2[q];
}

// ---------------- 3b) linear scan over chunks: s_n = ws*s_{n-1} + A_{n-1} --
// In-place: g_states[bh][n] becomes the state at the START of chunk n.
__global__ void __launch_bounds__(256)
stateScan_kernel(const float* __restrict__ tdecay) {
    int bh = blockIdx.x;
    int h = bh & 15;
    int tid = threadIdx.x;
    float decay = expf(-expf(tdecay[h]));
    float ws = powf(decay, (float)TCH);
    float* base = g_states + (size_t)bh * NCH * (KD * KD) + tid * 16;
    float4 s0 = {0,0,0,0}, s1 = {0,0,0,0}, s2 = {0,0,0,0}, s3 = {0,0,0,0};
    for (int n = 0; n < NCH; n++) {
        float4* p = (float4*)(base + (size_t)n * (KD * KD));
        float4 a0 = p[0], a1 = p[1], a2 = p[2], a3 = p[3];
        p[0] = s0; p[1] = s1; p[2] = s2; p[3] = s3;
        s0.x = ws*s0.x + a0.x; s0.y = ws*s0.y + a0.y; s0.z = ws*s0.z + a0.z; s0.w = ws*s0.w + a0.w;
        s1.x = ws*s1.x + a1.x; s1.y = ws*s1.y + a1.y; s1.z = ws*s1.z + a1.z; s1.w = ws*s1.w + a1.w;
        s2.x = ws*s2.x + a2.x; s2.y = ws*s2.y + a2.y; s2.z = ws*s2.z + a2.z; s2.w = ws*s2.w + a2.w;
        s3.x = ws*s3.x + a3.x; s3.y = ws*s3.y + a3.y; s3.z = ws*s3.z + a3.z; s3.w = ws*s3.w + a3.w;
    }
}

// ---------------- 4) per-chunk attention output (parallel, fp32x2) --------
#define OUT_SMEM_FLOATS (TCH*65 + TCH*65 + TCH*KD + KD*KD + TCH*129)
__global__ void __launch_bounds__(256)
out_kernel(const float* __restrict__ tdecay, const float* __restrict__ tfa) {
    extern __shared__ float sm[];
    float* rs  = sm;
    float* ksm = rs  + TCH * 65;
    float* vsm = ksm + TCH * 65;
    float* ssm = vsm + TCH * KD;
    float* att = ssm + KD * KD;
    __shared__ float dp[TCH];
    int bhn = blockIdx.x;
    int n  = bhn & (NCH - 1);
    int bh = bhn >> 5;
    int h = bh & 15, b = bh >> 4;
    int tid = threadIdx.x;
    float decay = expf(-expf(tdecay[h]));
    if (tid < TCH) dp[tid] = powf(decay, (float)tid);
    float u = tfa[h];
    size_t base = ((size_t)(b * TTT + n * TCH)) * CC + h * KD;
    for (int e = tid; e < TCH * KD; e += 256) {
        int i = e >> 6, k2 = e & 63;
        size_t gi = base + (size_t)i * CC + k2;
        rs [i * 65 + k2] = g_r[gi];
        ksm[i * 65 + k2] = g_k[gi];
        vsm[e]           = g_v[gi];
    }
    const float* stp = g_states + ((size_t)bh * NCH + n) * KD * KD;
    for (int e = tid; e < KD * KD; e += 256) ssm[e] = stp[e];
    __syncthreads();

    // Phase A: att[i,j] = (r_i . k_j) * w_mat[i,j]; packed along j-pairs
    {
        int i0 = (tid >> 4) * 8, j0 = (tid & 15) * 8;
        u64t acc2[8][4];
#pragma unroll
        for (int i = 0; i < 8; i++)
#pragma unroll
            for (int j = 0; j < 4; j++) acc2[i][j] = 0ull;
        for (int k2 = 0; k2 < KD; k2++) {
            u64t a2[8], b2[4];
#pragma unroll
            for (int ii = 0; ii < 8; ii++) {
                float ra = rs[(i0 + ii) * 65 + k2];
                a2[ii] = pack2(ra, ra);
            }
#pragma unroll
            for (int jp = 0; jp < 4; jp++)
                b2[jp] = pack2(ksm[(j0 + 2 * jp)     * 65 + k2],
                               ksm[(j0 + 2 * jp + 1) * 65 + k2]);
#pragma unroll
            for (int ii = 0; ii < 8; ii++)
#pragma unroll
                for (int jp = 0; jp < 4; jp++)
                    acc2[ii][jp] = fma2(a2[ii], b2[jp], acc2[ii][jp]);
        }
#pragma unroll
        for (int ii = 0; ii < 8; ii++)
#pragma unroll
            for (int jp = 0; jp < 4; jp++) {
                float lo, hi;
                unpack2(acc2[ii][jp], lo, hi);
                int i = i0 + ii;
                int j = j0 + 2 * jp;
                int d0 = i - j, d1 = i - (j + 1);
                float w0 = (d0 > 0) ? dp[d0 - 1] : ((d0 == 0) ? u : 0.f);
                float w1 = (d1 > 0) ? dp[d1 - 1] : ((d1 == 0) ? u : 0.f);
                att[i * 129 + j]     = lo * w0;
                att[i * 129 + j + 1] = hi * w1;
            }
    }
    __syncthreads();

    // Phase B: out = att @ v + (r @ s) * decay^i ; packed along c-pairs
    {
        int i0 = (tid >> 3) * 4, v0 = (tid & 7) * 8;
        u64t aA[4][4], aB[4][4];
#pragma unroll
        for (int i = 0; i < 4; i++)
#pragma unroll
            for (int j = 0; j < 4; j++) { aA[i][j] = 0ull; aB[i][j] = 0ull; }
        for (int j = 0; j < TCH; j++) {
            u64t a2[4];
#pragma unroll
            for (int ii = 0; ii < 4; ii++) {
                float av = att[(i0 + ii) * 129 + j];
                a2[ii] = pack2(av, av);
            }
            const u64t* vp = (const u64t*)&vsm[j * KD + v0];
#pragma unroll
            for (int ii = 0; ii < 4; ii++)
#pragma unroll
                for (int q = 0; q < 4; q++)
                    aA[ii][q] = fma2(a2[ii], vp[q], aA[ii][q]);
        }
        for (int k2 = 0; k2 < KD; k2++) {
            u64t r2[4];
#pragma unroll
            for (int ii = 0; ii < 4; ii++) {
                float rv = rs[(i0 + ii) * 65 + k2];
                r2[ii] = pack2(rv, rv);
            }
            const u64t* sp = (const u64t*)&ssm[k2 * KD + v0];
#pragma unroll
            for (int ii = 0; ii < 4; ii++)
#pragma unroll
                for (int q = 0; q < 4; q++)
                    aB[ii][q] = fma2(r2[ii], sp[q], aB[ii][q]);
        }
#pragma unroll
        for (int ii = 0; ii < 4; ii++) {
            float wbv = dp[i0 + ii];
            u64t w2 = pack2(wbv, wbv);
            float* dst = &g_xo[base + (size_t)(i0 + ii) * CC + v0];
#pragma unroll
            for (int q = 0; q < 4; q++) {
                u64t res = fma2(w2, aB[ii][q], aA[ii][q]);
                float lo, hi;
                unpack2(res, lo, hi);
                *(float2*)(dst + 2 * q) = make_float2(lo, hi);
            }
        }
    }
}

// ---------------- 5) GroupNorm(/8) + silu gate -> bf16 hi/lo ---------------
__global__ void gn_gate_kernel(const float* __restrict__ lnw,
                               const float* __restrict__ lnb) {
    int gidx = blockIdx.x * blockDim.x + threadIdx.x;
    int warp = gidx >> 5, lane = gidx & 31;
    size_t basep = (size_t)warp * 64;
    float a  = g_xo[basep + lane]      * 0.125f;
    float c2 = g_xo[basep + 32 + lane] * 0.125f;
    float s = a + c2, sq = a * a + c2 * c2;
#pragma unroll
    for (int o = 16; o; o >>= 1) {
        s  += __shfl_xor_sync(0xffffffffu, s,  o);
        sq += __shfl_xor_sync(0xffffffffu, sq, o);
    }
    float mu  = s * (1.f / 64.f);
    float var = sq * (1.f / 64.f) - mu * mu;
    float inv = rsqrtf(var + 1e-5f);
    int h = warp & 15;
    int cb = h * 64;
    float g0r = g_g[basep + lane];
    float g1r = g_g[basep + 32 + lane];
    float y0 = ((a  - mu) * inv) * lnw[cb + lane]      + lnb[cb + lane];
    float y1 = ((c2 - mu) * inv) * lnw[cb + 32 + lane] + lnb[cb + 32 + lane];
    split_store(g_z_h, g_z_l, basep + lane,      y0 * (g0r / (1.f + expf(-g0r))));
    split_store(g_z_h, g_z_l, basep + 32 + lane, y1 * (g1r / (1.f + expf(-g1r))));
}

// ---------------- launch ---------------------------------------------------
extern "C" void kernel_launch(void* const* d_in, const int* in_sizes, int n_in,
                              void* d_out, int out_size) {
    const float* xq     = (const float*)d_in[0];
    const float* tmk    = (const float*)d_in[1];
    const float* tmv    = (const float*)d_in[2];
    const float* tmr    = (const float*)d_in[3];
    const float* tmg    = (const float*)d_in[4];
    const float* tdecay = (const float*)d_in[5];
    const float* tfa    = (const float*)d_in[6];
    const float* Wr     = (const float*)d_in[7];
    const float* Wk     = (const float*)d_in[8];
    const float* Wv     = (const float*)d_in[9];
    const float* Wg     = (const float*)d_in[10];
    const float* Wo     = (const float*)d_in[11];
    const float* lnw    = (const float*)d_in[12];
    const float* lnb    = (const float*)d_in[13];
    float* out = (float*)d_out;

    __nv_bfloat16 *pxr_h, *pxr_l, *pxk_h, *pxk_l, *pxv_h, *pxv_l, *pxg_h, *pxg_l;
    __nv_bfloat16 *pz_h, *pz_l;
    __nv_bfloat16 *pwr_h, *pwr_l, *pwk_h, *pwk_l, *pwv_h, *pwv_l, *pwg_h, *pwg_l,
                  *pwo_h, *pwo_l;
    float *pr, *pk, *pv, *pg;
    cudaGetSymbolAddress((void**)&pxr_h, g_xr_h); cudaGetSymbolAddress((void**)&pxr_l, g_xr_l);
    cudaGetSymbolAddress((void**)&pxk_h, g_xk_h); cudaGetSymbolAddress((void**)&pxk_l, g_xk_l);
    cudaGetSymbolAddress((void**)&pxv_h, g_xv_h); cudaGetSymbolAddress((void**)&pxv_l, g_xv_l);
    cudaGetSymbolAddress((void**)&pxg_h, g_xg_h); cudaGetSymbolAddress((void**)&pxg_l, g_xg_l);
    cudaGetSymbolAddress((void**)&pz_h,  g_z_h);  cudaGetSymbolAddress((void**)&pz_l,  g_z_l);
    cudaGetSymbolAddress((void**)&pwr_h, g_wr_h); cudaGetSymbolAddress((void**)&pwr_l, g_wr_l);
    cudaGetSymbolAddress((void**)&pwk_h, g_wk_h); cudaGetSymbolAddress((void**)&pwk_l, g_wk_l);
    cudaGetSymbolAddress((void**)&pwv_h, g_wv_h); cudaGetSymbolAddress((void**)&pwv_l, g_wv_l);
    cudaGetSymbolAddress((void**)&pwg_h, g_wg_h); cudaGetSymbolAddress((void**)&pwg_l, g_wg_l);
    cudaGetSymbolAddress((void**)&pwo_h, g_wo_h); cudaGetSymbolAddress((void**)&pwo_l, g_wo_l);
    cudaGetSymbolAddress((void**)&pr, g_r); cudaGetSymbolAddress((void**)&pk, g_k);
    cudaGetSymbolAddress((void**)&pv, g_v); cudaGetSymbolAddress((void**)&pg, g_g);

    wsplit5_kernel<<<dim3(CC * CC / 256, 5), 256>>>(
        Wr, Wk, Wv, Wg, Wo,
        pwr_h, pwr_l, pwk_h, pwk_l, pwv_h, pwv_l, pwg_h, pwg_l, pwo_h, pwo_l);

    mix_kernel<<<MM * CC / 256, 256>>>(xq, tmk, tmv, tmr, tmg);

    cudaFuncSetAttribute(gemm_mma, cudaFuncAttributeMaxDynamicSharedMemorySize,
                         GSM_TOTAL);
    gemm_mma<<<dim3(CC / 128, MM / 128, 4), 256, GSM_TOTAL>>>(
        pxr_h, pxr_l, pwr_h, pwr_l, pr,
        pxk_h, pxk_l, pwk_h, pwk_l, pk,
        pxv_h, pxv_l, pwv_h, pwv_l, pv,
        pxg_h, pxg_l, pwg_h, pwg_l, pg);

    cudaFuncSetAttribute(stateA_kernel, cudaFuncAttributeMaxDynamicSharedMemorySize,
                         SA_SMEM);
    stateA_kernel<<<BB * HH * NCH, 256, SA_SMEM>>>(tdecay);
    stateScan_kernel<<<BB * HH, 256>>>(tdecay);

    size_t out_smem = OUT_SMEM_FLOATS * sizeof(float);
    cudaFuncSetAttribute(out_kernel, cudaFuncAttributeMaxDynamicSharedMemorySize,
                         (int)out_smem);
    out_kernel<<<BB * HH * NCH, 256, out_smem>>>(tdecay, tfa);

    gn_gate_kernel<<<(MM * HH * 32) / 256, 256>>>(lnw, lnb);

    gemm_mma<<<dim3(CC / 128, MM / 128, 1), 256, GSM_TOTAL>>>(
        pz_h, pz_l, pwo_h, pwo_l, out,
        pz_h, pz_l, pwo_h, pwo_l, out,
        pz_h, pz_l, pwo_h, pwo_l, out,
        pz_h, pz_l, pwo_h, pwo_l, out);
}

// round 9
// speedup vs baseline: 1.8895x; 1.0900x over previous
#include <cuda_runtime.h>
#include <cuda_bf16.h>
#include <stdint.h>
#include <math.h>

// Problem constants
#define BB   4
#define TTT  4096
#define CC   1024
#define HH   16
#define KD   64          // head dim
#define TCH  128         // chunk length
#define NCH  32          // chunks
#define MM   (BB*TTT)    // 16384 rows

// ---------------- scratch (device globals; no allocation allowed) ----------
__device__ __nv_bfloat16 g_xr_h[MM*CC], g_xr_l[MM*CC];
__device__ __nv_bfloat16 g_xk_h[MM*CC], g_xk_l[MM*CC];
__device__ __nv_bfloat16 g_xv_h[MM*CC], g_xv_l[MM*CC];
__device__ __nv_bfloat16 g_xg_h[MM*CC], g_xg_l[MM*CC];
__device__ __nv_bfloat16 g_z_h [MM*CC], g_z_l [MM*CC];
__device__ __nv_bfloat16 g_wr_h[CC*CC], g_wr_l[CC*CC];
__device__ __nv_bfloat16 g_wk_h[CC*CC], g_wk_l[CC*CC];
__device__ __nv_bfloat16 g_wv_h[CC*CC], g_wv_l[CC*CC];
__device__ __nv_bfloat16 g_wg_h[CC*CC], g_wg_l[CC*CC];
__device__ __nv_bfloat16 g_wo_h[CC*CC], g_wo_l[CC*CC];
__device__ float g_r [MM*CC];
__device__ float g_k [MM*CC];
__device__ float g_v [MM*CC];
__device__ float g_g [MM*CC];
__device__ float g_xo[MM*CC];
__device__ float g_states[BB*HH*NCH*KD*KD];

// ---------------- helpers ---------------------------------------------------
__device__ __forceinline__ void split_store(__nv_bfloat16* ah, __nv_bfloat16* al,
                                            size_t i, float v) {
    __nv_bfloat16 h = __float2bfloat16(v);
    ah[i] = h;
    al[i] = __float2bfloat16(v - __bfloat162float(h));
}

__device__ __forceinline__ void mma_bf16(float* c, const uint32_t* a,
                                         uint32_t b0, uint32_t b1) {
    asm volatile(
        "mma.sync.aligned.m16n8k16.row.col.f32.bf16.bf16.f32 "
        "{%0,%1,%2,%3}, {%4,%5,%6,%7}, {%8,%9}, {%0,%1,%2,%3};"
        : "+f"(c[0]), "+f"(c[1]), "+f"(c[2]), "+f"(c[3])
        : "r"(a[0]), "r"(a[1]), "r"(a[2]), "r"(a[3]), "r"(b0), "r"(b1));
}

__device__ __forceinline__ uint32_t smem_u32(const void* p) {
    uint32_t a;
    asm("{ .reg .u64 t; cvta.to.shared.u64 t, %1; cvt.u32.u64 %0, t; }"
        : "=r"(a) : "l"(p));
    return a;
}
__device__ __forceinline__ void cp16(uint32_t saddr, const void* g) {
    asm volatile("cp.async.cg.shared.global [%0], [%1], 16;" :: "r"(saddr), "l"(g));
}
__device__ __forceinline__ void cp_commit() {
    asm volatile("cp.async.commit_group;");
}
__device__ __forceinline__ void cp_wait1() {
    asm volatile("cp.async.wait_group 1;");
}
__device__ __forceinline__ void ldsm4(uint32_t* r, uint32_t addr) {
    asm volatile("ldmatrix.sync.aligned.m8n8.x4.shared.b16 {%0,%1,%2,%3}, [%4];"
                 : "=r"(r[0]), "=r"(r[1]), "=r"(r[2]), "=r"(r[3]) : "r"(addr));
}

// ---- packed fp32x2 (Blackwell double-pumped fp32) ----
typedef unsigned long long u64t;
__device__ __forceinline__ u64t fma2(u64t a, u64t b, u64t c) {
    u64t d;
    asm("fma.rn.f32x2 %0, %1, %2, %3;" : "=l"(d) : "l"(a), "l"(b), "l"(c));
    return d;
}
__device__ __forceinline__ u64t pack2(float x, float y) {
    u64t d;
    asm("mov.b64 %0, {%1, %2};" : "=l"(d) : "f"(x), "f"(y));
    return d;
}
__device__ __forceinline__ void unpack2(u64t v, float& x, float& y) {
    asm("mov.b64 {%0, %1}, %2;" : "=f"(x), "=f"(y) : "l"(v));
}

// swizzled byte offset within a 128-row x 64B tile: row r, 16B-unit u (0..3)
__device__ __forceinline__ uint32_t swz(int r, int u) {
    return (uint32_t)(r * 64 + ((u ^ ((r >> 1) & 3)) << 4));
}

// ---------------- 0) weight split fp32 -> bf16 hi/lo (all 5 fused) ---------
__global__ void wsplit5_kernel(const float* __restrict__ W0, const float* __restrict__ W1,
                               const float* __restrict__ W2, const float* __restrict__ W3,
                               const float* __restrict__ W4,
                               __nv_bfloat16* __restrict__ H0, __nv_bfloat16* __restrict__ L0,
                               __nv_bfloat16* __restrict__ H1, __nv_bfloat16* __restrict__ L1,
                               __nv_bfloat16* __restrict__ H2, __nv_bfloat16* __restrict__ L2,
                               __nv_bfloat16* __restrict__ H3, __nv_bfloat16* __restrict__ L3,
                               __nv_bfloat16* __restrict__ H4, __nv_bfloat16* __restrict__ L4) {
    int i = blockIdx.x * blockDim.x + threadIdx.x;
    const float* W; __nv_bfloat16 *Hh, *Ll;
    switch (blockIdx.y) {
        case 0: W = W0; Hh = H0; Ll = L0; break;
        case 1: W = W1; Hh = H1; Ll = L1; break;
        case 2: W = W2; Hh = H2; Ll = L2; break;
        case 3: W = W3; Hh = H3; Ll = L3; break;
        default: W = W4; Hh = H4; Ll = L4; break;
    }
    split_store(Hh, Ll, i, W[i]);
}

// ---------------- 1) time-shift mixing -> bf16 hi/lo (float4 vectorized) ---
__device__ __forceinline__ void mix4_store(const float* __restrict__ tm, int c,
                                           float4 xc, float4 xp,
                                           __nv_bfloat16* __restrict__ H,
                                           __nv_bfloat16* __restrict__ L, int idx) {
    float4 m = *(const float4*)(tm + c);
    float y0 = xc.x * m.x + xp.x * (1.f - m.x);
    float y1 = xc.y * m.y + xp.y * (1.f - m.y);
    float y2 = xc.z * m.z + xp.z * (1.f - m.z);
    float y3 = xc.w * m.w + xp.w * (1.f - m.w);
    __nv_bfloat16 h0 = __float2bfloat16(y0), h1 = __float2bfloat16(y1);
    __nv_bfloat16 h2 = __float2bfloat16(y2), h3 = __float2bfloat16(y3);
    __nv_bfloat162 hh0(h0, h1), hh1(h2, h3);
    *(__nv_bfloat162*)(H + idx)     = hh0;
    *(__nv_bfloat162*)(H + idx + 2) = hh1;
    __nv_bfloat162 ll0(__float2bfloat16(y0 - __bfloat162float(h0)),
                       __float2bfloat16(y1 - __bfloat162float(h1)));
    __nv_bfloat162 ll1(__float2bfloat16(y2 - __bfloat162float(h2)),
                       __float2bfloat16(y3 - __bfloat162float(h3)));
    *(__nv_bfloat162*)(L + idx)     = ll0;
    *(__nv_bfloat162*)(L + idx + 2) = ll1;
}

__global__ void mix_kernel(const float* __restrict__ x,
                           const float* __restrict__ tmk,
                           const float* __restrict__ tmv,
                           const float* __restrict__ tmr,
                           const float* __restrict__ tmg) {
    int idx = (blockIdx.x * blockDim.x + threadIdx.x) * 4;
    int c = idx & (CC - 1);
    int t = (idx >> 10) & (TTT - 1);
    float4 xc = *(const float4*)(x + idx);
    float4 xp = t ? *(const float4*)(x + idx - CC) : make_float4(0.f, 0.f, 0.f, 0.f);
    mix4_store(tmr, c, xc, xp, g_xr_h, g_xr_l, idx);
    mix4_store(tmk, c, xc, xp, g_xk_h, g_xk_l, idx);
    mix4_store(tmv, c, xc, xp, g_xv_h, g_xv_l, idx);
    mix4_store(tmg, c, xc, xp, g_xg_h, g_xg_l, idx);
}

// ---------------- 2) mma.sync GEMM: C = A @ W^T (bf16 hi/lo, 3 passes) -----
#define KCH     32
#define TILE_B  8192                     // 128 rows x 64B
#define BUF_B   (4*TILE_B)               // Ah, Al, Bh, Bl
#define GSM_TOTAL (3*BUF_B)              // 98304 B
#define NKC     (CC/KCH)                 // 32 chunks

__global__ void __launch_bounds__(256, 2)
gemm_mma(const __nv_bfloat16* __restrict__ A0h, const __nv_bfloat16* __restrict__ A0l,
         const __nv_bfloat16* __restrict__ B0h, const __nv_bfloat16* __restrict__ B0l,
         float* __restrict__ C0,
         const __nv_bfloat16* __restrict__ A1h, const __nv_bfloat16* __restrict__ A1l,
         const __nv_bfloat16* __restrict__ B1h, const __nv_bfloat16* __restrict__ B1l,
         float* __restrict__ C1,
         const __nv_bfloat16* __restrict__ A2h, const __nv_bfloat16* __restrict__ A2l,
         const __nv_bfloat16* __restrict__ B2h, const __nv_bfloat16* __restrict__ B2l,
         float* __restrict__ C2,
         const __nv_bfloat16* __restrict__ A3h, const __nv_bfloat16* __restrict__ A3l,
         const __nv_bfloat16* __restrict__ B3h, const __nv_bfloat16* __restrict__ B3l,
         float* __restrict__ C3) {
    extern __shared__ char dsm[];
    uint32_t sbase = smem_u32(dsm);
    int tid = threadIdx.x;
    int w   = tid >> 5;
    int lane = tid & 31;
    int g = lane >> 2;
    int t = lane & 3;
    int n0 = blockIdx.x * 128;
    int m0 = blockIdx.y * 128;
    int m0w = (w >> 1) * 32;
    int n0w = (w & 1) * 64;

    const __nv_bfloat16 *Ah, *Al, *Bh, *Bl; float* C;
    switch (blockIdx.z) {
        case 0: Ah = A0h; Al = A0l; Bh = B0h; Bl = B0l; C = C0; break;
        case 1: Ah = A1h; Al = A1l; Bh = B1h; Bl = B1l; C = C1; break;
        case 2: Ah = A2h; Al = A2l; Bh = B2h; Bl = B2l; C = C2; break;
        default: Ah = A3h; Al = A3l; Bh = B3h; Bl = B3l; C = C3; break;
    }
    const __nv_bfloat16* sAh = Ah + (size_t)m0 * CC;
    const __nv_bfloat16* sAl = Al + (size_t)m0 * CC;
    const __nv_bfloat16* sBh = Bh + (size_t)n0 * CC;
    const __nv_bfloat16* sBl = Bl + (size_t)n0 * CC;

    int r0 = tid >> 2, u = tid & 3;
    size_t go0 = (size_t)r0 * CC + u * 8;
    size_t go1 = go0 + (size_t)64 * CC;
    uint32_t so0 = swz(r0, u);
    uint32_t so1 = so0 + 64 * 64;

    int arow = lane & 15;
    int akof = (lane >> 4) << 3;
    int brow = ((lane >> 4) << 3) + (lane & 7);
    int bkof = ((lane >> 3) & 1) << 3;
    int rowA0 = m0w + arow, rowA1 = m0w + 16 + arow;

    float acc[2][8][4];
#pragma unroll
    for (int mi = 0; mi < 2; mi++)
#pragma unroll
        for (int ni = 0; ni < 8; ni++)
#pragma unroll
            for (int q = 0; q < 4; q++) acc[mi][ni][q] = 0.f;

    auto issue = [&](int chunk) {
        int k0 = chunk * KCH;
        uint32_t b = sbase + (uint32_t)((chunk % 3) * BUF_B);
        cp16(b + 0*TILE_B + so0, sAh + go0 + k0); cp16(b + 0*TILE_B + so1, sAh + go1 + k0);
        cp16(b + 1*TILE_B + so0, sAl + go0 + k0); cp16(b + 1*TILE_B + so1, sAl + go1 + k0);
        cp16(b + 2*TILE_B + so0, sBh + go0 + k0); cp16(b + 2*TILE_B + so1, sBh + go1 + k0);
        cp16(b + 3*TILE_B + so0, sBl + go0 + k0); cp16(b + 3*TILE_B + so1, sBl + go1 + k0);
        cp_commit();
    };

    issue(0);
    issue(1);

    for (int c = 0; c < NKC; ++c) {
        cp_wait1();
        __syncthreads();
        if (c + 2 < NKC) issue(c + 2);

        uint32_t sb = sbase + (uint32_t)((c % 3) * BUF_B);
        uint32_t tAh = sb;
        uint32_t tAl = sb + TILE_B;
        uint32_t tBh = sb + 2 * TILE_B;
        uint32_t tBl = sb + 3 * TILE_B;
#pragma unroll
        for (int ks = 0; ks < 2; ++ks) {
            int kk = ks * 16;
            int uA = (kk + akof) >> 3;
            uint32_t ah[2][4], al[2][4];
            {
                uint32_t o0 = swz(rowA0, uA), o1 = swz(rowA1, uA);
                ldsm4(ah[0], tAh + o0);
                ldsm4(ah[1], tAh + o1);
                ldsm4(al[0], tAl + o0);
                ldsm4(al[1], tAl + o1);
            }
            int uB = (kk + bkof) >> 3;
#pragma unroll
            for (int np = 0; np < 4; np++) {
                uint32_t bo = swz(n0w + np * 16 + brow, uB);
                uint32_t bh4[4], bl4[4];
                ldsm4(bh4, tBh + bo);
                ldsm4(bl4, tBl + bo);
#pragma unroll
                for (int sub = 0; sub < 2; sub++) {
                    int ni = np * 2 + sub;
                    uint32_t b0h = bh4[sub * 2], b1h = bh4[sub * 2 + 1];
                    uint32_t b0l = bl4[sub * 2], b1l = bl4[sub * 2 + 1];
#pragma unroll
                    for (int mi = 0; mi < 2; mi++) {
                        mma_bf16(acc[mi][ni], ah[mi], b0h, b1h);
                        mma_bf16(acc[mi][ni], ah[mi], b0l, b1l);
                        mma_bf16(acc[mi][ni], al[mi], b0h, b1h);
                    }
                }
            }
        }
    }

#pragma unroll
    for (int mi = 0; mi < 2; mi++) {
        int r = m0 + m0w + mi * 16 + g;
#pragma unroll
        for (int ni = 0; ni < 8; ni++) {
            int col = n0 + n0w + ni * 8 + 2 * t;
            *(float2*)&C[(size_t)r * CC + col] =
                make_float2(acc[mi][ni][0], acc[mi][ni][1]);
            *(float2*)&C[(size_t)(r + 8) * CC + col] =
                make_float2(acc[mi][ni][2], acc[mi][ni][3]);
        }
    }
}

// ---------------- 3a) per-chunk state contributions A_n (fully parallel) ---
// grid = B*H*N = 2048 blocks, 256 threads. Thread tile: 4(kk) x 4(vv).
// Per j: one LDS.128 for k (broadcast in half-warp), one LDS.128 for v.
#define SA_SMEM ((2*TCH*KD + TCH) * 4)
__global__ void __launch_bounds__(256)
stateA_kernel(const float* __restrict__ tdecay) {
    extern __shared__ float sa[];
    float* kw  = sa;                 // [128][64]
    float* vsh = sa + TCH * KD;      // [128][64]
    float* dp  = sa + 2 * TCH * KD;  // [128]
    int bhn = blockIdx.x;
    int n  = bhn & (NCH - 1);
    int bh = bhn >> 5;
    int b = bh >> 4, h = bh & 15;
    int tid = threadIdx.x;
    float decay = expf(-expf(tdecay[h]));
    if (tid < TCH) dp[tid] = powf(decay, (float)(TCH - 1 - tid));
    __syncthreads();
    const float* kb = g_k + ((size_t)(b * TTT + n * TCH)) * CC + h * KD;
    const float* vb = g_v + ((size_t)(b * TTT + n * TCH)) * CC + h * KD;
    for (int e = tid * 4; e < TCH * KD; e += 1024) {
        int j = e >> 6, c = e & 63;
        float4 k4 = *(const float4*)(kb + (size_t)j * CC + c);
        float wj = dp[j];
        k4.x *= wj; k4.y *= wj; k4.z *= wj; k4.w *= wj;
        *(float4*)&kw[e]  = k4;
        *(float4*)&vsh[e] = *(const float4*)(vb + (size_t)j * CC + c);
    }
    __syncthreads();
    int kk0 = (tid >> 4) * 4;        // 16 groups of 4 consecutive kk
    int c0  = (tid & 15) * 4;        // 16 groups of 4 consecutive vv
    u64t acc[4][2];
#pragma unroll
    for (int i = 0; i < 4; i++) { acc[i][0] = 0ull; acc[i][1] = 0ull; }
#pragma unroll 2
    for (int j = 0; j < TCH; j++) {
        float4 k4 = *(const float4*)&kw[j * KD + kk0];
        float4 v4 = *(const float4*)&vsh[j * KD + c0];
        u64t v0 = pack2(v4.x, v4.y), v1 = pack2(v4.z, v4.w);
        u64t a0 = pack2(k4.x, k4.x), a1 = pack2(k4.y, k4.y);
        u64t a2 = pack2(k4.z, k4.z), a3 = pack2(k4.w, k4.w);
        acc[0][0] = fma2(a0, v0, acc[0][0]); acc[0][1] = fma2(a0, v1, acc[0][1]);
        acc[1][0] = fma2(a1, v0, acc[1][0]); acc[1][1] = fma2(a1, v1, acc[1][1]);
        acc[2][0] = fma2(a2, v0, acc[2][0]); acc[2][1] = fma2(a2, v1, acc[2][1]);
        acc[3][0] = fma2(a3, v0, acc[3][0]); acc[3][1] = fma2(a3, v1, acc[3][1]);
    }
    float* outb = g_states + (size_t)bhn * (KD * KD);
#pragma unroll
    for (int i = 0; i < 4; i++) {
        u64t* dst = (u64t*)(outb + (kk0 + i) * KD + c0);
        dst[0] = acc[i][0]; dst[1] = acc[i][1];
    }
}

// ---------------- 3b) linear scan over chunks: s_n = ws*s_{n-1} + A_{n-1} --
__global__ void __launch_bounds__(256)
stateScan_kernel(const float* __restrict__ tdecay) {
    int bh = blockIdx.x;
    int h = bh & 15;
    int tid = threadIdx.x;
    float decay = expf(-expf(tdecay[h]));
    float ws = powf(decay, (float)TCH);
    float* base = g_states + (size_t)bh * NCH * (KD * KD) + tid * 16;
    float4 s0 = {0,0,0,0}, s1 = {0,0,0,0}, s2 = {0,0,0,0}, s3 = {0,0,0,0};
    for (int n = 0; n < NCH; n++) {
        float4* p = (float4*)(base + (size_t)n * (KD * KD));
        float4 a0 = p[0], a1 = p[1], a2 = p[2], a3 = p[3];
        p[0] = s0; p[1] = s1; p[2] = s2; p[3] = s3;
        s0.x = ws*s0.x + a0.x; s0.y = ws*s0.y + a0.y; s0.z = ws*s0.z + a0.z; s0.w = ws*s0.w + a0.w;
        s1.x = ws*s1.x + a1.x; s1.y = ws*s1.y + a1.y; s1.z = ws*s1.z + a1.z; s1.w = ws*s1.w + a1.w;
        s2.x = ws*s2.x + a2.x; s2.y = ws*s2.y + a2.y; s2.z = ws*s2.z + a2.z; s2.w = ws*s2.w + a2.w;
        s3.x = ws*s3.x + a3.x; s3.y = ws*s3.y + a3.y; s3.z = ws*s3.z + a3.z; s3.w = ws*s3.w + a3.w;
    }
}

// ---------------- 4) per-chunk attention output (parallel, fp32x2) --------
#define OUT_SMEM_FLOATS (TCH*65 + TCH*65 + TCH*KD + KD*KD + TCH*129)
__global__ void __launch_bounds__(256)
out_kernel(const float* __restrict__ tdecay, const float* __restrict__ tfa) {
    extern __shared__ float sm[];
    float* rs  = sm;
    float* ksm = rs  + TCH * 65;
    float* vsm = ksm + TCH * 65;
    float* ssm = vsm + TCH * KD;
    float* att = ssm + KD * KD;
    __shared__ float dp[TCH];
    int bhn = blockIdx.x;
    int n  = bhn & (NCH - 1);
    int bh = bhn >> 5;
    int h = bh & 15, b = bh >> 4;
    int tid = threadIdx.x;
    float decay = expf(-expf(tdecay[h]));
    if (tid < TCH) dp[tid] = powf(decay, (float)tid);
    float u = tfa[h];
    size_t base = ((size_t)(b * TTT + n * TCH)) * CC + h * KD;
    for (int e = tid; e < TCH * KD; e += 256) {
        int i = e >> 6, k2 = e & 63;
        size_t gi = base + (size_t)i * CC + k2;
        rs [i * 65 + k2] = g_r[gi];
        ksm[i * 65 + k2] = g_k[gi];
        vsm[e]           = g_v[gi];
    }
    const float* stp = g_states + ((size_t)bh * NCH + n) * KD * KD;
    for (int e = tid; e < KD * KD; e += 256) ssm[e] = stp[e];
    __syncthreads();

    // Phase A: att[i,j] = (r_i . k_j) * w_mat[i,j]; packed along j-pairs
    {
        int i0 = (tid >> 4) * 8, j0 = (tid & 15) * 8;
        u64t acc2[8][4];
#pragma unroll
        for (int i = 0; i < 8; i++)
#pragma unroll
            for (int j = 0; j < 4; j++) acc2[i][j] = 0ull;
        for (int k2 = 0; k2 < KD; k2++) {
            u64t a2[8], b2[4];
#pragma unroll
            for (int ii = 0; ii < 8; ii++) {
                float ra = rs[(i0 + ii) * 65 + k2];
                a2[ii] = pack2(ra, ra);
            }
#pragma unroll
            for (int jp = 0; jp < 4; jp++)
                b2[jp] = pack2(ksm[(j0 + 2 * jp)     * 65 + k2],
                               ksm[(j0 + 2 * jp + 1) * 65 + k2]);
#pragma unroll
            for (int ii = 0; ii < 8; ii++)
#pragma unroll
                for (int jp = 0; jp < 4; jp++)
                    acc2[ii][jp] = fma2(a2[ii], b2[jp], acc2[ii][jp]);
        }
#pragma unroll
        for (int ii = 0; ii < 8; ii++)
#pragma unroll
            for (int jp = 0; jp < 4; jp++) {
                float lo, hi;
                unpack2(acc2[ii][jp], lo, hi);
                int i = i0 + ii;
                int j = j0 + 2 * jp;
                int d0 = i - j, d1 = i - (j + 1);
                float w0 = (d0 > 0) ? dp[d0 - 1] : ((d0 == 0) ? u : 0.f);
                float w1 = (d1 > 0) ? dp[d1 - 1] : ((d1 == 0) ? u : 0.f);
                att[i * 129 + j]     = lo * w0;
                att[i * 129 + j + 1] = hi * w1;
            }
    }
    __syncthreads();

    // Phase B: out = att @ v + (r @ s) * decay^i ; packed along c-pairs
    {
        int i0 = (tid >> 3) * 4, v0 = (tid & 7) * 8;
        u64t aA[4][4], aB[4][4];
#pragma unroll
        for (int i = 0; i < 4; i++)
#pragma unroll
            for (int j = 0; j < 4; j++) { aA[i][j] = 0ull; aB[i][j] = 0ull; }
        for (int j = 0; j < TCH; j++) {
            u64t a2[4];
#pragma unroll
            for (int ii = 0; ii < 4; ii++) {
                float av = att[(i0 + ii) * 129 + j];
                a2[ii] = pack2(av, av);
            }
            const u64t* vp = (const u64t*)&vsm[j * KD + v0];
#pragma unroll
            for (int ii = 0; ii < 4; ii++)
#pragma unroll
                for (int q = 0; q < 4; q++)
                    aA[ii][q] = fma2(a2[ii], vp[q], aA[ii][q]);
        }
        for (int k2 = 0; k2 < KD; k2++) {
            u64t r2[4];
#pragma unroll
            for (int ii = 0; ii < 4; ii++) {
                float rv = rs[(i0 + ii) * 65 + k2];
                r2[ii] = pack2(rv, rv);
            }
            const u64t* sp = (const u64t*)&ssm[k2 * KD + v0];
#pragma unroll
            for (int ii = 0; ii < 4; ii++)
#pragma unroll
                for (int q = 0; q < 4; q++)
                    aB[ii][q] = fma2(r2[ii], sp[q], aB[ii][q]);
        }
#pragma unroll
        for (int ii = 0; ii < 4; ii++) {
            float wbv = dp[i0 + ii];
            u64t w2 = pack2(wbv, wbv);
            float* dst = &g_xo[base + (size_t)(i0 + ii) * CC + v0];
#pragma unroll
            for (int q = 0; q < 4; q++) {
                u64t res = fma2(w2, aB[ii][q], aA[ii][q]);
                float lo, hi;
                unpack2(res, lo, hi);
                *(float2*)(dst + 2 * q) = make_float2(lo, hi);
            }
        }
    }
}

// ---------------- 5) GroupNorm(/8) + silu gate -> bf16 hi/lo ---------------
__global__ void gn_gate_kernel(const float* __restrict__ lnw,
                               const float* __restrict__ lnb) {
    int gidx = blockIdx.x * blockDim.x + threadIdx.x;
    int warp = gidx >> 5, lane = gidx & 31;
    size_t basep = (size_t)warp * 64;
    float a  = g_xo[basep + lane]      * 0.125f;
    float c2 = g_xo[basep + 32 + lane] * 0.125f;
    float s = a + c2, sq = a * a + c2 * c2;
#pragma unroll
    for (int o = 16; o; o >>= 1) {
        s  += __shfl_xor_sync(0xffffffffu, s,  o);
        sq += __shfl_xor_sync(0xffffffffu, sq, o);
    }
    float mu  = s * (1.f / 64.f);
    float var = sq * (1.f / 64.f) - mu * mu;
    float inv = rsqrtf(var + 1e-5f);
    int h = warp & 15;
    int cb = h * 64;
    float g0r = g_g[basep + lane];
    float g1r = g_g[basep + 32 + lane];
    float y0 = ((a  - mu) * inv) * lnw[cb + lane]      + lnb[cb + lane];
    float y1 = ((c2 - mu) * inv) * lnw[cb + 32 + lane] + lnb[cb + 32 + lane];
    split_store(g_z_h, g_z_l, basep + lane,      y0 * (g0r / (1.f + expf(-g0r))));
    split_store(g_z_h, g_z_l, basep + 32 + lane, y1 * (g1r / (1.f + expf(-g1r))));
}

// ---------------- launch ---------------------------------------------------
extern "C" void kernel_launch(void* const* d_in, const int* in_sizes, int n_in,
                              void* d_out, int out_size) {
    const float* xq     = (const float*)d_in[0];
    const float* tmk    = (const float*)d_in[1];
    const float* tmv    = (const float*)d_in[2];
    const float* tmr    = (const float*)d_in[3];
    const float* tmg    = (const float*)d_in[4];
    const float* tdecay = (const float*)d_in[5];
    const float* tfa    = (const float*)d_in[6];
    const float* Wr     = (const float*)d_in[7];
    const float* Wk     = (const float*)d_in[8];
    const float* Wv     = (const float*)d_in[9];
    const float* Wg     = (const float*)d_in[10];
    const float* Wo     = (const float*)d_in[11];
    const float* lnw    = (const float*)d_in[12];
    const float* lnb    = (const float*)d_in[13];
    float* out = (float*)d_out;

    __nv_bfloat16 *pxr_h, *pxr_l, *pxk_h, *pxk_l, *pxv_h, *pxv_l, *pxg_h, *pxg_l;
    __nv_bfloat16 *pz_h, *pz_l;
    __nv_bfloat16 *pwr_h, *pwr_l, *pwk_h, *pwk_l, *pwv_h, *pwv_l, *pwg_h, *pwg_l,
                  *pwo_h, *pwo_l;
    float *pr, *pk, *pv, *pg;
    cudaGetSymbolAddress((void**)&pxr_h, g_xr_h); cudaGetSymbolAddress((void**)&pxr_l, g_xr_l);
    cudaGetSymbolAddress((void**)&pxk_h, g_xk_h); cudaGetSymbolAddress((void**)&pxk_l, g_xk_l);
    cudaGetSymbolAddress((void**)&pxv_h, g_xv_h); cudaGetSymbolAddress((void**)&pxv_l, g_xv_l);
    cudaGetSymbolAddress((void**)&pxg_h, g_xg_h); cudaGetSymbolAddress((void**)&pxg_l, g_xg_l);
    cudaGetSymbolAddress((void**)&pz_h,  g_z_h);  cudaGetSymbolAddress((void**)&pz_l,  g_z_l);
    cudaGetSymbolAddress((void**)&pwr_h, g_wr_h); cudaGetSymbolAddress((void**)&pwr_l, g_wr_l);
    cudaGetSymbolAddress((void**)&pwk_h, g_wk_h); cudaGetSymbolAddress((void**)&pwk_l, g_wk_l);
    cudaGetSymbolAddress((void**)&pwv_h, g_wv_h); cudaGetSymbolAddress((void**)&pwv_l, g_wv_l);
    cudaGetSymbolAddress((void**)&pwg_h, g_wg_h); cudaGetSymbolAddress((void**)&pwg_l, g_wg_l);
    cudaGetSymbolAddress((void**)&pwo_h, g_wo_h); cudaGetSymbolAddress((void**)&pwo_l, g_wo_l);
    cudaGetSymbolAddress((void**)&pr, g_r); cudaGetSymbolAddress((void**)&pk, g_k);
    cudaGetSymbolAddress((void**)&pv, g_v); cudaGetSymbolAddress((void**)&pg, g_g);

    wsplit5_kernel<<<dim3(CC * CC / 256, 5), 256>>>(
        Wr, Wk, Wv, Wg, Wo,
        pwr_h, pwr_l, pwk_h, pwk_l, pwv_h, pwv_l, pwg_h, pwg_l, pwo_h, pwo_l);

    mix_kernel<<<MM * CC / 1024, 256>>>(xq, tmk, tmv, tmr, tmg);

    cudaFuncSetAttribute(gemm_mma, cudaFuncAttributeMaxDynamicSharedMemorySize,
                         GSM_TOTAL);
    gemm_mma<<<dim3(CC / 128, MM / 128, 4), 256, GSM_TOTAL>>>(
        pxr_h, pxr_l, pwr_h, pwr_l, pr,
        pxk_h, pxk_l, pwk_h, pwk_l, pk,
        pxv_h, pxv_l, pwv_h, pwv_l, pv,
        pxg_h, pxg_l, pwg_h, pwg_l, pg);

    cudaFuncSetAttribute(stateA_kernel, cudaFuncAttributeMaxDynamicSharedMemorySize,
                         SA_SMEM);
    stateA_kernel<<<BB * HH * NCH, 256, SA_SMEM>>>(tdecay);
    stateScan_kernel<<<BB * HH, 256>>>(tdecay);

    size_t out_smem = OUT_SMEM_FLOATS * sizeof(float);
    cudaFuncSetAttribute(out_kernel, cudaFuncAttributeMaxDynamicSharedMemorySize,
                         (int)out_smem);
    out_kernel<<<BB * HH * NCH, 256, out_smem>>>(tdecay, tfa);

    gn_gate_kernel<<<(MM * HH * 32) / 256, 256>>>(lnw, lnb);

    gemm_mma<<<dim3(CC / 128, MM / 128, 1), 256, GSM_TOTAL>>>(
        pz_h, pz_l, pwo_h, pwo_l, out,
        pz_h, pz_l, pwo_h, pwo_l, out,
        pz_h, pz_l, pwo_h, pwo_l, out,
        pz_h, pz_l, pwo_h, pwo_l, out);
}

// round 10
// speedup vs baseline: 2.3349x; 1.2357x over previous
#include <cuda_runtime.h>
#include <cuda_fp16.h>
#include <stdint.h>
#include <math.h>

// Problem constants
#define BB   4
#define TTT  4096
#define CC   1024
#define HH   16
#define KD   64          // head dim
#define TCH  128         // chunk length
#define NCH  32          // chunks
#define MM   (BB*TTT)    // 16384 rows

// ---------------- scratch (device globals; no allocation allowed) ----------
__device__ __half g_xr_h[MM*CC], g_xr_l[MM*CC];
__device__ __half g_xk_h[MM*CC], g_xk_l[MM*CC];
__device__ __half g_xv_h[MM*CC], g_xv_l[MM*CC];
__device__ __half g_xg_h[MM*CC], g_xg_l[MM*CC];
__device__ __half g_z_h [MM*CC], g_z_l [MM*CC];
__device__ __half g_wr[CC*CC];
__device__ __half g_wk[CC*CC];
__device__ __half g_wv[CC*CC];
__device__ __half g_wg[CC*CC];
__device__ __half g_wo[CC*CC];
__device__ float g_r [MM*CC];
__device__ float g_k [MM*CC];
__device__ float g_v [MM*CC];
__device__ float g_g [MM*CC];
__device__ float g_xo[MM*CC];
__device__ float g_states[BB*HH*NCH*KD*KD];

// ---------------- helpers ---------------------------------------------------
__device__ __forceinline__ void split_store_h(__half* ah, __half* al,
                                              size_t i, float v) {
    __half h = __float2half_rn(v);
    ah[i] = h;
    al[i] = __float2half_rn(v - __half2float(h));
}

__device__ __forceinline__ void mma_f16(float* c, const uint32_t* a,
                                        uint32_t b0, uint32_t b1) {
    asm volatile(
        "mma.sync.aligned.m16n8k16.row.col.f32.f16.f16.f32 "
        "{%0,%1,%2,%3}, {%4,%5,%6,%7}, {%8,%9}, {%0,%1,%2,%3};"
        : "+f"(c[0]), "+f"(c[1]), "+f"(c[2]), "+f"(c[3])
        : "r"(a[0]), "r"(a[1]), "r"(a[2]), "r"(a[3]), "r"(b0), "r"(b1));
}

__device__ __forceinline__ uint32_t smem_u32(const void* p) {
    uint32_t a;
    asm("{ .reg .u64 t; cvta.to.shared.u64 t, %1; cvt.u32.u64 %0, t; }"
        : "=r"(a) : "l"(p));
    return a;
}
__device__ __forceinline__ void cp16(uint32_t saddr, const void* g) {
    asm volatile("cp.async.cg.shared.global [%0], [%1], 16;" :: "r"(saddr), "l"(g));
}
__device__ __forceinline__ void cp_commit() {
    asm volatile("cp.async.commit_group;");
}
__device__ __forceinline__ void cp_wait1() {
    asm volatile("cp.async.wait_group 1;");
}
__device__ __forceinline__ void ldsm4(uint32_t* r, uint32_t addr) {
    asm volatile("ldmatrix.sync.aligned.m8n8.x4.shared.b16 {%0,%1,%2,%3}, [%4];"
                 : "=r"(r[0]), "=r"(r[1]), "=r"(r[2]), "=r"(r[3]) : "r"(addr));
}

// ---- packed fp32x2 (Blackwell double-pumped fp32) ----
typedef unsigned long long u64t;
__device__ __forceinline__ u64t fma2(u64t a, u64t b, u64t c) {
    u64t d;
    asm("fma.rn.f32x2 %0, %1, %2, %3;" : "=l"(d) : "l"(a), "l"(b), "l"(c));
    return d;
}
__device__ __forceinline__ u64t pack2(float x, float y) {
    u64t d;
    asm("mov.b64 %0, {%1, %2};" : "=l"(d) : "f"(x), "f"(y));
    return d;
}
__device__ __forceinline__ void unpack2(u64t v, float& x, float& y) {
    asm("mov.b64 {%0, %1}, %2;" : "=f"(x), "=f"(y) : "l"(v));
}

// swizzled byte offset within a 128-row x 64B tile: row r, 16B-unit u (0..3)
__device__ __forceinline__ uint32_t swz(int r, int u) {
    return (uint32_t)(r * 64 + ((u ^ ((r >> 1) & 3)) << 4));
}

// ---------------- 0) weight convert fp32 -> fp16 (all 5 fused) -------------
__global__ void wsplit5_kernel(const float* __restrict__ W0, const float* __restrict__ W1,
                               const float* __restrict__ W2, const float* __restrict__ W3,
                               const float* __restrict__ W4,
                               __half* __restrict__ H0, __half* __restrict__ H1,
                               __half* __restrict__ H2, __half* __restrict__ H3,
                               __half* __restrict__ H4) {
    int i = blockIdx.x * blockDim.x + threadIdx.x;
    const float* W; __half* Hh;
    switch (blockIdx.y) {
        case 0: W = W0; Hh = H0; break;
        case 1: W = W1; Hh = H1; break;
        case 2: W = W2; Hh = H2; break;
        case 3: W = W3; Hh = H3; break;
        default: W = W4; Hh = H4; break;
    }
    Hh[i] = __float2half_rn(W[i]);
}

// ---------------- 1) time-shift mixing -> fp16 hi/lo (float4 vectorized) ---
__device__ __forceinline__ void mix4_store(const float* __restrict__ tm, int c,
                                           float4 xc, float4 xp,
                                           __half* __restrict__ H,
                                           __half* __restrict__ L, int idx) {
    float4 m = *(const float4*)(tm + c);
    float y0 = xc.x * m.x + xp.x * (1.f - m.x);
    float y1 = xc.y * m.y + xp.y * (1.f - m.y);
    float y2 = xc.z * m.z + xp.z * (1.f - m.z);
    float y3 = xc.w * m.w + xp.w * (1.f - m.w);
    __half h0 = __float2half_rn(y0), h1 = __float2half_rn(y1);
    __half h2 = __float2half_rn(y2), h3 = __float2half_rn(y3);
    __half2 hh0(h0, h1), hh1(h2, h3);
    *(__half2*)(H + idx)     = hh0;
    *(__half2*)(H + idx + 2) = hh1;
    __half2 ll0(__float2half_rn(y0 - __half2float(h0)),
                __float2half_rn(y1 - __half2float(h1)));
    __half2 ll1(__float2half_rn(y2 - __half2float(h2)),
                __float2half_rn(y3 - __half2float(h3)));
    *(__half2*)(L + idx)     = ll0;
    *(__half2*)(L + idx + 2) = ll1;
}

__global__ void mix_kernel(const float* __restrict__ x,
                           const float* __restrict__ tmk,
                           const float* __restrict__ tmv,
                           const float* __restrict__ tmr,
                           const float* __restrict__ tmg) {
    int idx = (blockIdx.x * blockDim.x + threadIdx.x) * 4;
    int c = idx & (CC - 1);
    int t = (idx >> 10) & (TTT - 1);
    float4 xc = *(const float4*)(x + idx);
    float4 xp = t ? *(const float4*)(x + idx - CC) : make_float4(0.f, 0.f, 0.f, 0.f);
    mix4_store(tmr, c, xc, xp, g_xr_h, g_xr_l, idx);
    mix4_store(tmk, c, xc, xp, g_xk_h, g_xk_l, idx);
    mix4_store(tmv, c, xc, xp, g_xv_h, g_xv_l, idx);
    mix4_store(tmg, c, xc, xp, g_xg_h, g_xg_l, idx);
}

// ---------------- 2) mma.sync GEMM: C = A @ W^T (fp16 A hi/lo, 2 passes) ---
// CTA tile 128x128, 8 warps (warp tile 32x64), K-chunk 32.
// Tiles: Ah, Al, W (fp16 single). 3-stage cp.async, 72KB smem, 2 CTAs/SM.
#define KCH     32
#define TILE_B  8192                     // 128 rows x 64B
#define BUF_B   (3*TILE_B)               // Ah, Al, B
#define GSM_TOTAL (3*BUF_B)              // 73728 B
#define NKC     (CC/KCH)                 // 32 chunks

__global__ void __launch_bounds__(256, 2)
gemm_mma(const __half* __restrict__ A0h, const __half* __restrict__ A0l,
         const __half* __restrict__ B0, float* __restrict__ C0,
         const __half* __restrict__ A1h, const __half* __restrict__ A1l,
         const __half* __restrict__ B1, float* __restrict__ C1,
         const __half* __restrict__ A2h, const __half* __restrict__ A2l,
         const __half* __restrict__ B2, float* __restrict__ C2,
         const __half* __restrict__ A3h, const __half* __restrict__ A3l,
         const __half* __restrict__ B3, float* __restrict__ C3) {
    extern __shared__ char dsm[];
    uint32_t sbase = smem_u32(dsm);
    int tid = threadIdx.x;
    int w   = tid >> 5;
    int lane = tid & 31;
    int g = lane >> 2;
    int t = lane & 3;
    int n0 = blockIdx.x * 128;
    int m0 = blockIdx.y * 128;
    int m0w = (w >> 1) * 32;
    int n0w = (w & 1) * 64;

    const __half *Ah, *Al, *Bw; float* C;
    switch (blockIdx.z) {
        case 0: Ah = A0h; Al = A0l; Bw = B0; C = C0; break;
        case 1: Ah = A1h; Al = A1l; Bw = B1; C = C1; break;
        case 2: Ah = A2h; Al = A2l; Bw = B2; C = C2; break;
        default: Ah = A3h; Al = A3l; Bw = B3; C = C3; break;
    }
    const __half* sAh = Ah + (size_t)m0 * CC;
    const __half* sAl = Al + (size_t)m0 * CC;
    const __half* sB  = Bw + (size_t)n0 * CC;

    int r0 = tid >> 2, u = tid & 3;
    size_t go0 = (size_t)r0 * CC + u * 8;
    size_t go1 = go0 + (size_t)64 * CC;
    uint32_t so0 = swz(r0, u);
    uint32_t so1 = so0 + 64 * 64;

    int arow = lane & 15;
    int akof = (lane >> 4) << 3;
    int brow = ((lane >> 4) << 3) + (lane & 7);
    int bkof = ((lane >> 3) & 1) << 3;
    int rowA0 = m0w + arow, rowA1 = m0w + 16 + arow;

    float acc[2][8][4];
#pragma unroll
    for (int mi = 0; mi < 2; mi++)
#pragma unroll
        for (int ni = 0; ni < 8; ni++)
#pragma unroll
            for (int q = 0; q < 4; q++) acc[mi][ni][q] = 0.f;

    auto issue = [&](int chunk) {
        int k0 = chunk * KCH;
        uint32_t b = sbase + (uint32_t)((chunk % 3) * BUF_B);
        cp16(b + 0*TILE_B + so0, sAh + go0 + k0); cp16(b + 0*TILE_B + so1, sAh + go1 + k0);
        cp16(b + 1*TILE_B + so0, sAl + go0 + k0); cp16(b + 1*TILE_B + so1, sAl + go1 + k0);
        cp16(b + 2*TILE_B + so0, sB  + go0 + k0); cp16(b + 2*TILE_B + so1, sB  + go1 + k0);
        cp_commit();
    };

    issue(0);
    issue(1);

    for (int c = 0; c < NKC; ++c) {
        cp_wait1();
        __syncthreads();
        if (c + 2 < NKC) issue(c + 2);

        uint32_t sb = sbase + (uint32_t)((c % 3) * BUF_B);
        uint32_t tAh = sb;
        uint32_t tAl = sb + TILE_B;
        uint32_t tB  = sb + 2 * TILE_B;
#pragma unroll
        for (int ks = 0; ks < 2; ++ks) {
            int kk = ks * 16;
            int uA = (kk + akof) >> 3;
            uint32_t ah[2][4], al[2][4];
            {
                uint32_t o0 = swz(rowA0, uA), o1 = swz(rowA1, uA);
                ldsm4(ah[0], tAh + o0);
                ldsm4(ah[1], tAh + o1);
                ldsm4(al[0], tAl + o0);
                ldsm4(al[1], tAl + o1);
            }
            int uB = (kk + bkof) >> 3;
#pragma unroll
            for (int np = 0; np < 4; np++) {
                uint32_t bo = swz(n0w + np * 16 + brow, uB);
                uint32_t b4[4];
                ldsm4(b4, tB + bo);
#pragma unroll
                for (int sub = 0; sub < 2; sub++) {
                    int ni = np * 2 + sub;
                    uint32_t b0 = b4[sub * 2], b1 = b4[sub * 2 + 1];
#pragma unroll
                    for (int mi = 0; mi < 2; mi++) {
                        mma_f16(acc[mi][ni], ah[mi], b0, b1);
                        mma_f16(acc[mi][ni], al[mi], b0, b1);
                    }
                }
            }
        }
    }

#pragma unroll
    for (int mi = 0; mi < 2; mi++) {
        int r = m0 + m0w + mi * 16 + g;
#pragma unroll
        for (int ni = 0; ni < 8; ni++) {
            int col = n0 + n0w + ni * 8 + 2 * t;
            *(float2*)&C[(size_t)r * CC + col] =
                make_float2(acc[mi][ni][0], acc[mi][ni][1]);
            *(float2*)&C[(size_t)(r + 8) * CC + col] =
                make_float2(acc[mi][ni][2], acc[mi][ni][3]);
        }
    }
}

// ---------------- 3a) per-chunk state contributions A_n (fully parallel) ---
#define SA_SMEM ((2*TCH*KD + TCH) * 4)
__global__ void __launch_bounds__(256)
stateA_kernel(const float* __restrict__ tdecay) {
    extern __shared__ float sa[];
    float* kw  = sa;                 // [128][64]
    float* vsh = sa + TCH * KD;      // [128][64]
    float* dp  = sa + 2 * TCH * KD;  // [128]
    int bhn = blockIdx.x;
    int n  = bhn & (NCH - 1);
    int bh = bhn >> 5;
    int b = bh >> 4, h = bh & 15;
    int tid = threadIdx.x;
    float decay = expf(-expf(tdecay[h]));
    if (tid < TCH) dp[tid] = powf(decay, (float)(TCH - 1 - tid));
    __syncthreads();
    const float* kb = g_k + ((size_t)(b * TTT + n * TCH)) * CC + h * KD;
    const float* vb = g_v + ((size_t)(b * TTT + n * TCH)) * CC + h * KD;
    for (int e = tid * 4; e < TCH * KD; e += 1024) {
        int j = e >> 6, c = e & 63;
        float4 k4 = *(const float4*)(kb + (size_t)j * CC + c);
        float wj = dp[j];
        k4.x *= wj; k4.y *= wj; k4.z *= wj; k4.w *= wj;
        *(float4*)&kw[e]  = k4;
        *(float4*)&vsh[e] = *(const float4*)(vb + (size_t)j * CC + c);
    }
    __syncthreads();
    int kk0 = (tid >> 4) * 4;
    int c0  = (tid & 15) * 4;
    u64t acc[4][2];
#pragma unroll
    for (int i = 0; i < 4; i++) { acc[i][0] = 0ull; acc[i][1] = 0ull; }
#pragma unroll 2
    for (int j = 0; j < TCH; j++) {
        float4 k4 = *(const float4*)&kw[j * KD + kk0];
        float4 v4 = *(const float4*)&vsh[j * KD + c0];
        u64t v0 = pack2(v4.x, v4.y), v1 = pack2(v4.z, v4.w);
        u64t a0 = pack2(k4.x, k4.x), a1 = pack2(k4.y, k4.y);
        u64t a2 = pack2(k4.z, k4.z), a3 = pack2(k4.w, k4.w);
        acc[0][0] = fma2(a0, v0, acc[0][0]); acc[0][1] = fma2(a0, v1, acc[0][1]);
        acc[1][0] = fma2(a1, v0, acc[1][0]); acc[1][1] = fma2(a1, v1, acc[1][1]);
        acc[2][0] = fma2(a2, v0, acc[2][0]); acc[2][1] = fma2(a2, v1, acc[2][1]);
        acc[3][0] = fma2(a3, v0, acc[3][0]); acc[3][1] = fma2(a3, v1, acc[3][1]);
    }
    float* outb = g_states + (size_t)bhn * (KD * KD);
#pragma unroll
    for (int i = 0; i < 4; i++) {
        u64t* dst = (u64t*)(outb + (kk0 + i) * KD + c0);
        dst[0] = acc[i][0]; dst[1] = acc[i][1];
    }
}

// ---------------- 3b) linear scan over chunks: s_n = ws*s_{n-1} + A_{n-1} --
__global__ void __launch_bounds__(256)
stateScan_kernel(const float* __restrict__ tdecay) {
    int bh = blockIdx.x;
    int h = bh & 15;
    int tid = threadIdx.x;
    float decay = expf(-expf(tdecay[h]));
    float ws = powf(decay, (float)TCH);
    float* base = g_states + (size_t)bh * NCH * (KD * KD) + tid * 16;
    float4 s0 = {0,0,0,0}, s1 = {0,0,0,0}, s2 = {0,0,0,0}, s3 = {0,0,0,0};
    for (int n = 0; n < NCH; n++) {
        float4* p = (float4*)(base + (size_t)n * (KD * KD));
        float4 a0 = p[0], a1 = p[1], a2 = p[2], a3 = p[3];
        p[0] = s0; p[1] = s1; p[2] = s2; p[3] = s3;
        s0.x = ws*s0.x + a0.x; s0.y = ws*s0.y + a0.y; s0.z = ws*s0.z + a0.z; s0.w = ws*s0.w + a0.w;
        s1.x = ws*s1.x + a1.x; s1.y = ws*s1.y + a1.y; s1.z = ws*s1.z + a1.z; s1.w = ws*s1.w + a1.w;
        s2.x = ws*s2.x + a2.x; s2.y = ws*s2.y + a2.y; s2.z = ws*s2.z + a2.z; s2.w = ws*s2.w + a2.w;
        s3.x = ws*s3.x + a3.x; s3.y = ws*s3.y + a3.y; s3.z = ws*s3.z + a3.z; s3.w = ws*s3.w + a3.w;
    }
}

// ---------------- 4) per-chunk attention output (parallel, fp32x2) --------
#define OUT_SMEM_FLOATS (TCH*65 + TCH*65 + TCH*KD + KD*KD + TCH*129)
__global__ void __launch_bounds__(256)
out_kernel(const float* __restrict__ tdecay, const float* __restrict__ tfa) {
    extern __shared__ float sm[];
    float* rs  = sm;
    float* ksm = rs  + TCH * 65;
    float* vsm = ksm + TCH * 65;
    float* ssm = vsm + TCH * KD;
    float* att = ssm + KD * KD;
    __shared__ float dp[TCH];
    int bhn = blockIdx.x;
    int n  = bhn & (NCH - 1);
    int bh = bhn >> 5;
    int h = bh & 15, b = bh >> 4;
    int tid = threadIdx.x;
    float decay = expf(-expf(tdecay[h]));
    if (tid < TCH) dp[tid] = powf(decay, (float)tid);
    float u = tfa[h];
    size_t base = ((size_t)(b * TTT + n * TCH)) * CC + h * KD;
    for (int e = tid; e < TCH * KD; e += 256) {
        int i = e >> 6, k2 = e & 63;
        size_t gi = base + (size_t)i * CC + k2;
        rs [i * 65 + k2] = g_r[gi];
        ksm[i * 65 + k2] = g_k[gi];
        vsm[e]           = g_v[gi];
    }
    const float* stp = g_states + ((size_t)bh * NCH + n) * KD * KD;
    for (int e = tid; e < KD * KD; e += 256) ssm[e] = stp[e];
    __syncthreads();

    // Phase A: att[i,j] = (r_i . k_j) * w_mat[i,j]; packed along j-pairs
    {
        int i0 = (tid >> 4) * 8, j0 = (tid & 15) * 8;
        u64t acc2[8][4];
#pragma unroll
        for (int i = 0; i < 8; i++)
#pragma unroll
            for (int j = 0; j < 4; j++) acc2[i][j] = 0ull;
        for (int k2 = 0; k2 < KD; k2++) {
            u64t a2[8], b2[4];
#pragma unroll
            for (int ii = 0; ii < 8; ii++) {
                float ra = rs[(i0 + ii) * 65 + k2];
                a2[ii] = pack2(ra, ra);
            }
#pragma unroll
            for (int jp = 0; jp < 4; jp++)
                b2[jp] = pack2(ksm[(j0 + 2 * jp)     * 65 + k2],
                               ksm[(j0 + 2 * jp + 1) * 65 + k2]);
#pragma unroll
            for (int ii = 0; ii < 8; ii++)
#pragma unroll
                for (int jp = 0; jp < 4; jp++)
                    acc2[ii][jp] = fma2(a2[ii], b2[jp], acc2[ii][jp]);
        }
#pragma unroll
        for (int ii = 0; ii < 8; ii++)
#pragma unroll
            for (int jp = 0; jp < 4; jp++) {
                float lo, hi;
                unpack2(acc2[ii][jp], lo, hi);
                int i = i0 + ii;
                int j = j0 + 2 * jp;
                int d0 = i - j, d1 = i - (j + 1);
                float w0 = (d0 > 0) ? dp[d0 - 1] : ((d0 == 0) ? u : 0.f);
                float w1 = (d1 > 0) ? dp[d1 - 1] : ((d1 == 0) ? u : 0.f);
                att[i * 129 + j]     = lo * w0;
                att[i * 129 + j + 1] = hi * w1;
            }
    }
    __syncthreads();

    // Phase B: out = att @ v + (r @ s) * decay^i ; packed along c-pairs
    {
        int i0 = (tid >> 3) * 4, v0 = (tid & 7) * 8;
        u64t aA[4][4], aB[4][4];
#pragma unroll
        for (int i = 0; i < 4; i++)
#pragma unroll
            for (int j = 0; j < 4; j++) { aA[i][j] = 0ull; aB[i][j] = 0ull; }
        for (int j = 0; j < TCH; j++) {
            u64t a2[4];
#pragma unroll
            for (int ii = 0; ii < 4; ii++) {
                float av = att[(i0 + ii) * 129 + j];
                a2[ii] = pack2(av, av);
            }
            const u64t* vp = (const u64t*)&vsm[j * KD + v0];
#pragma unroll
            for (int ii = 0; ii < 4; ii++)
#pragma unroll
                for (int q = 0; q < 4; q++)
                    aA[ii][q] = fma2(a2[ii], vp[q], aA[ii][q]);
        }
        for (int k2 = 0; k2 < KD; k2++) {
            u64t r2[4];
#pragma unroll
            for (int ii = 0; ii < 4; ii++) {
                float rv = rs[(i0 + ii) * 65 + k2];
                r2[ii] = pack2(rv, rv);
            }
            const u64t* sp = (const u64t*)&ssm[k2 * KD + v0];
#pragma unroll
            for (int ii = 0; ii < 4; ii++)
#pragma unroll
                for (int q = 0; q < 4; q++)
                    aB[ii][q] = fma2(r2[ii], sp[q], aB[ii][q]);
        }
#pragma unroll
        for (int ii = 0; ii < 4; ii++) {
            float wbv = dp[i0 + ii];
            u64t w2 = pack2(wbv, wbv);
            float* dst = &g_xo[base + (size_t)(i0 + ii) * CC + v0];
#pragma unroll
            for (int q = 0; q < 4; q++) {
                u64t res = fma2(w2, aB[ii][q], aA[ii][q]);
                float lo, hi;
                unpack2(res, lo, hi);
                *(float2*)(dst + 2 * q) = make_float2(lo, hi);
            }
        }
    }
}

// ---------------- 5) GroupNorm(/8) + silu gate -> fp16 hi/lo ---------------
__global__ void gn_gate_kernel(const float* __restrict__ lnw,
                               const float* __restrict__ lnb) {
    int gidx = blockIdx.x * blockDim.x + threadIdx.x;
    int warp = gidx >> 5, lane = gidx & 31;
    size_t basep = (size_t)warp * 64;
    float a  = g_xo[basep + lane]      * 0.125f;
    float c2 = g_xo[basep + 32 + lane] * 0.125f;
    float s = a + c2, sq = a * a + c2 * c2;
#pragma unroll
    for (int o = 16; o; o >>= 1) {
        s  += __shfl_xor_sync(0xffffffffu, s,  o);
        sq += __shfl_xor_sync(0xffffffffu, sq, o);
    }
    float mu  = s * (1.f / 64.f);
    float var = sq * (1.f / 64.f) - mu * mu;
    float inv = rsqrtf(var + 1e-5f);
    int h = warp & 15;
    int cb = h * 64;
    float g0r = g_g[basep + lane];
    float g1r = g_g[basep + 32 + lane];
    float y0 = ((a  - mu) * inv) * lnw[cb + lane]      + lnb[cb + lane];
    float y1 = ((c2 - mu) * inv) * lnw[cb + 32 + lane] + lnb[cb + 32 + lane];
    split_store_h(g_z_h, g_z_l, basep + lane,      y0 * (g0r / (1.f + expf(-g0r))));
    split_store_h(g_z_h, g_z_l, basep + 32 + lane, y1 * (g1r / (1.f + expf(-g1r))));
}

// ---------------- launch ---------------------------------------------------
extern "C" void kernel_launch(void* const* d_in, const int* in_sizes, int n_in,
                              void* d_out, int out_size) {
    const float* xq     = (const float*)d_in[0];
    const float* tmk    = (const float*)d_in[1];
    const float* tmv    = (const float*)d_in[2];
    const float* tmr    = (const float*)d_in[3];
    const float* tmg    = (const float*)d_in[4];
    const float* tdecay = (const float*)d_in[5];
    const float* tfa    = (const float*)d_in[6];
    const float* Wr     = (const float*)d_in[7];
    const float* Wk     = (const float*)d_in[8];
    const float* Wv     = (const float*)d_in[9];
    const float* Wg     = (const float*)d_in[10];
    const float* Wo     = (const float*)d_in[11];
    const float* lnw    = (const float*)d_in[12];
    const float* lnb    = (const float*)d_in[13];
    float* out = (float*)d_out;

    __half *pxr_h, *pxr_l, *pxk_h, *pxk_l, *pxv_h, *pxv_l, *pxg_h, *pxg_l;
    __half *pz_h, *pz_l;
    __half *pwr, *pwk, *pwv, *pwg, *pwo;
    float *pr, *pk, *pv, *pg;
    cudaGetSymbolAddress((void**)&pxr_h, g_xr_h); cudaGetSymbolAddress((void**)&pxr_l, g_xr_l);
    cudaGetSymbolAddress((void**)&pxk_h, g_xk_h); cudaGetSymbolAddress((void**)&pxk_l, g_xk_l);
    cudaGetSymbolAddress((void**)&pxv_h, g_xv_h); cudaGetSymbolAddress((void**)&pxv_l, g_xv_l);
    cudaGetSymbolAddress((void**)&pxg_h, g_xg_h); cudaGetSymbolAddress((void**)&pxg_l, g_xg_l);
    cudaGetSymbolAddress((void**)&pz_h,  g_z_h);  cudaGetSymbolAddress((void**)&pz_l,  g_z_l);
    cudaGetSymbolAddress((void**)&pwr, g_wr); cudaGetSymbolAddress((void**)&pwk, g_wk);
    cudaGetSymbolAddress((void**)&pwv, g_wv); cudaGetSymbolAddress((void**)&pwg, g_wg);
    cudaGetSymbolAddress((void**)&pwo, g_wo);
    cudaGetSymbolAddress((void**)&pr, g_r); cudaGetSymbolAddress((void**)&pk, g_k);
    cudaGetSymbolAddress((void**)&pv, g_v); cudaGetSymbolAddress((void**)&pg, g_g);

    wsplit5_kernel<<<dim3(CC * CC / 256, 5), 256>>>(
        Wr, Wk, Wv, Wg, Wo, pwr, pwk, pwv, pwg, pwo);

    mix_kernel<<<MM * CC / 1024, 256>>>(xq, tmk, tmv, tmr, tmg);

    cudaFuncSetAttribute(gemm_mma, cudaFuncAttributeMaxDynamicSharedMemorySize,
                         GSM_TOTAL);
    gemm_mma<<<dim3(CC / 128, MM / 128, 4), 256, GSM_TOTAL>>>(
        pxr_h, pxr_l, pwr, pr,
        pxk_h, pxk_l, pwk, pk,
        pxv_h, pxv_l, pwv, pv,
        pxg_h, pxg_l, pwg, pg);

    cudaFuncSetAttribute(stateA_kernel, cudaFuncAttributeMaxDynamicSharedMemorySize,
                         SA_SMEM);
    stateA_kernel<<<BB * HH * NCH, 256, SA_SMEM>>>(tdecay);
    stateScan_kernel<<<BB * HH, 256>>>(tdecay);

    size_t out_smem = OUT_SMEM_FLOATS * sizeof(float);
    cudaFuncSetAttribute(out_kernel, cudaFuncAttributeMaxDynamicSharedMemorySize,
                         (int)out_smem);
    out_kernel<<<BB * HH * NCH, 256, out_smem>>>(tdecay, tfa);

    gn_gate_kernel<<<(MM * HH * 32) / 256, 256>>>(lnw, lnb);

    gemm_mma<<<dim3(CC / 128, MM / 128, 1), 256, GSM_TOTAL>>>(
        pz_h, pz_l, pwo, out,
        pz_h, pz_l, pwo, out,
        pz_h, pz_l, pwo, out,
        pz_h, pz_l, pwo, out);
}

// round 11
// speedup vs baseline: 3.0658x; 1.3130x over previous
#include <cuda_runtime.h>
#include <cuda_fp16.h>
#include <stdint.h>
#include <math.h>

// Problem constants
#define BB   4
#define TTT  4096
#define CC   1024
#define HH   16
#define KD   64          // head dim
#define TCH  128         // chunk length
#define NCH  32          // chunks
#define MM   (BB*TTT)    // 16384 rows

// ---------------- scratch (device globals; no allocation allowed) ----------
__device__ __half g_xr_h[MM*CC], g_xr_l[MM*CC];
__device__ __half g_xk_h[MM*CC], g_xk_l[MM*CC];
__device__ __half g_xv_h[MM*CC], g_xv_l[MM*CC];
__device__ __half g_xg_h[MM*CC], g_xg_l[MM*CC];
__device__ __half g_z_h [MM*CC], g_z_l [MM*CC];
__device__ __half g_wr[CC*CC];
__device__ __half g_wk[CC*CC];
__device__ __half g_wv[CC*CC];
__device__ __half g_wg[CC*CC];
__device__ __half g_wo[CC*CC];
__device__ float g_r [MM*CC];
__device__ float g_k [MM*CC];
__device__ float g_v [MM*CC];
__device__ float g_g [MM*CC];
__device__ float g_states[BB*HH*NCH*KD*KD];

// ---------------- helpers ---------------------------------------------------
__device__ __forceinline__ void split_store_h(__half* ah, __half* al,
                                              size_t i, float v) {
    __half h = __float2half_rn(v);
    ah[i] = h;
    al[i] = __float2half_rn(v - __half2float(h));
}

__device__ __forceinline__ void mma_f16(float* c, const uint32_t* a,
                                        uint32_t b0, uint32_t b1) {
    asm volatile(
        "mma.sync.aligned.m16n8k16.row.col.f32.f16.f16.f32 "
        "{%0,%1,%2,%3}, {%4,%5,%6,%7}, {%8,%9}, {%0,%1,%2,%3};"
        : "+f"(c[0]), "+f"(c[1]), "+f"(c[2]), "+f"(c[3])
        : "r"(a[0]), "r"(a[1]), "r"(a[2]), "r"(a[3]), "r"(b0), "r"(b1));
}

__device__ __forceinline__ uint32_t smem_u32(const void* p) {
    uint32_t a;
    asm("{ .reg .u64 t; cvta.to.shared.u64 t, %1; cvt.u32.u64 %0, t; }"
        : "=r"(a) : "l"(p));
    return a;
}
__device__ __forceinline__ void cp16(uint32_t saddr, const void* g) {
    asm volatile("cp.async.cg.shared.global [%0], [%1], 16;" :: "r"(saddr), "l"(g));
}
__device__ __forceinline__ void cp_commit() {
    asm volatile("cp.async.commit_group;");
}
__device__ __forceinline__ void cp_wait1() {
    asm volatile("cp.async.wait_group 1;");
}
__device__ __forceinline__ void ldsm4(uint32_t* r, uint32_t addr) {
    asm volatile("ldmatrix.sync.aligned.m8n8.x4.shared.b16 {%0,%1,%2,%3}, [%4];"
                 : "=r"(r[0]), "=r"(r[1]), "=r"(r[2]), "=r"(r[3]) : "r"(addr));
}
__device__ __forceinline__ void ldsm4t(uint32_t* r, uint32_t addr) {
    asm volatile("ldmatrix.sync.aligned.m8n8.x4.trans.shared.b16 {%0,%1,%2,%3}, [%4];"
                 : "=r"(r[0]), "=r"(r[1]), "=r"(r[2]), "=r"(r[3]) : "r"(addr));
}

// ---- packed fp32x2 (Blackwell double-pumped fp32) ----
typedef unsigned long long u64t;
__device__ __forceinline__ u64t fma2(u64t a, u64t b, u64t c) {
    u64t d;
    asm("fma.rn.f32x2 %0, %1, %2, %3;" : "=l"(d) : "l"(a), "l"(b), "l"(c));
    return d;
}
__device__ __forceinline__ u64t pack2(float x, float y) {
    u64t d;
    asm("mov.b64 %0, {%1, %2};" : "=l"(d) : "f"(x), "f"(y));
    return d;
}

__device__ __forceinline__ uint32_t h2pack(float a, float b) {
    __half2 h(__float2half_rn(a), __float2half_rn(b));
    return *(uint32_t*)&h;
}

// swizzled byte offset within a 128-row x 64B tile (32 fp16 rows): unit u 0..3
__device__ __forceinline__ uint32_t swz(int r, int u) {
    return (uint32_t)(r * 64 + ((u ^ ((r >> 1) & 3)) << 4));
}
// 128B rows (64 fp16): unit u 0..7
__device__ __forceinline__ uint32_t swz64(int r, int u) {
    return (uint32_t)(r * 128 + ((u ^ (r & 7)) << 4));
}
// 256B rows (128 fp16): unit u 0..15
__device__ __forceinline__ uint32_t swzA(int r, int u) {
    int phys = (u & 8) | ((u ^ (r & 7)) & 7);
    return (uint32_t)(r * 256 + phys * 16);
}

// ---------------- 0) weight convert fp32 -> fp16 (all 5 fused) -------------
__global__ void wsplit5_kernel(const float* __restrict__ W0, const float* __restrict__ W1,
                               const float* __restrict__ W2, const float* __restrict__ W3,
                               const float* __restrict__ W4,
                               __half* __restrict__ H0, __half* __restrict__ H1,
                               __half* __restrict__ H2, __half* __restrict__ H3,
                               __half* __restrict__ H4) {
    int i = blockIdx.x * blockDim.x + threadIdx.x;
    const float* W; __half* Hh;
    switch (blockIdx.y) {
        case 0: W = W0; Hh = H0; break;
        case 1: W = W1; Hh = H1; break;
        case 2: W = W2; Hh = H2; break;
        case 3: W = W3; Hh = H3; break;
        default: W = W4; Hh = H4; break;
    }
    Hh[i] = __float2half_rn(W[i]);
}

// ---------------- 1) time-shift mixing -> fp16 hi/lo (float4 vectorized) ---
__device__ __forceinline__ void mix4_store(const float* __restrict__ tm, int c,
                                           float4 xc, float4 xp,
                                           __half* __restrict__ H,
                                           __half* __restrict__ L, int idx) {
    float4 m = *(const float4*)(tm + c);
    float y0 = xc.x * m.x + xp.x * (1.f - m.x);
    float y1 = xc.y * m.y + xp.y * (1.f - m.y);
    float y2 = xc.z * m.z + xp.z * (1.f - m.z);
    float y3 = xc.w * m.w + xp.w * (1.f - m.w);
    __half h0 = __float2half_rn(y0), h1 = __float2half_rn(y1);
    __half h2 = __float2half_rn(y2), h3 = __float2half_rn(y3);
    __half2 hh0(h0, h1), hh1(h2, h3);
    *(__half2*)(H + idx)     = hh0;
    *(__half2*)(H + idx + 2) = hh1;
    __half2 ll0(__float2half_rn(y0 - __half2float(h0)),
                __float2half_rn(y1 - __half2float(h1)));
    __half2 ll1(__float2half_rn(y2 - __half2float(h2)),
                __float2half_rn(y3 - __half2float(h3)));
    *(__half2*)(L + idx)     = ll0;
    *(__half2*)(L + idx + 2) = ll1;
}

__global__ void mix_kernel(const float* __restrict__ x,
                           const float* __restrict__ tmk,
                           const float* __restrict__ tmv,
                           const float* __restrict__ tmr,
                           const float* __restrict__ tmg) {
    int idx = (blockIdx.x * blockDim.x + threadIdx.x) * 4;
    int c = idx & (CC - 1);
    int t = (idx >> 10) & (TTT - 1);
    float4 xc = *(const float4*)(x + idx);
    float4 xp = t ? *(const float4*)(x + idx - CC) : make_float4(0.f, 0.f, 0.f, 0.f);
    mix4_store(tmr, c, xc, xp, g_xr_h, g_xr_l, idx);
    mix4_store(tmk, c, xc, xp, g_xk_h, g_xk_l, idx);
    mix4_store(tmv, c, xc, xp, g_xv_h, g_xv_l, idx);
    mix4_store(tmg, c, xc, xp, g_xg_h, g_xg_l, idx);
}

// ---------------- 2) mma.sync GEMM: C = A @ W^T (fp16 A hi/lo, 2 passes) ---
#define KCH     32
#define TILE_B  8192                     // 128 rows x 64B
#define BUF_B   (3*TILE_B)               // Ah, Al, B
#define GSM_TOTAL (3*BUF_B)              // 73728 B
#define NKC     (CC/KCH)                 // 32 chunks

__global__ void __launch_bounds__(256, 2)
gemm_mma(const __half* __restrict__ A0h, const __half* __restrict__ A0l,
         const __half* __restrict__ B0, float* __restrict__ C0,
         const __half* __restrict__ A1h, const __half* __restrict__ A1l,
         const __half* __restrict__ B1, float* __restrict__ C1,
         const __half* __restrict__ A2h, const __half* __restrict__ A2l,
         const __half* __restrict__ B2, float* __restrict__ C2,
         const __half* __restrict__ A3h, const __half* __restrict__ A3l,
         const __half* __restrict__ B3, float* __restrict__ C3) {
    extern __shared__ char dsm[];
    uint32_t sbase = smem_u32(dsm);
    int tid = threadIdx.x;
    int w   = tid >> 5;
    int lane = tid & 31;
    int g = lane >> 2;
    int t = lane & 3;
    int n0 = blockIdx.x * 128;
    int m0 = blockIdx.y * 128;
    int m0w = (w >> 1) * 32;
    int n0w = (w & 1) * 64;

    const __half *Ah, *Al, *Bw; float* C;
    switch (blockIdx.z) {
        case 0: Ah = A0h; Al = A0l; Bw = B0; C = C0; break;
        case 1: Ah = A1h; Al = A1l; Bw = B1; C = C1; break;
        case 2: Ah = A2h; Al = A2l; Bw = B2; C = C2; break;
        default: Ah = A3h; Al = A3l; Bw = B3; C = C3; break;
    }
    const __half* sAh = Ah + (size_t)m0 * CC;
    const __half* sAl = Al + (size_t)m0 * CC;
    const __half* sB  = Bw + (size_t)n0 * CC;

    int r0 = tid >> 2, u = tid & 3;
    size_t go0 = (size_t)r0 * CC + u * 8;
    size_t go1 = go0 + (size_t)64 * CC;
    uint32_t so0 = swz(r0, u);
    uint32_t so1 = so0 + 64 * 64;

    int arow = lane & 15;
    int akof = (lane >> 4) << 3;
    int brow = ((lane >> 4) << 3) + (lane & 7);
    int bkof = ((lane >> 3) & 1) << 3;
    int rowA0 = m0w + arow, rowA1 = m0w + 16 + arow;

    float acc[2][8][4];
#pragma unroll
    for (int mi = 0; mi < 2; mi++)
#pragma unroll
        for (int ni = 0; ni < 8; ni++)
#pragma unroll
            for (int q = 0; q < 4; q++) acc[mi][ni][q] = 0.f;

    auto issue = [&](int chunk) {
        int k0 = chunk * KCH;
        uint32_t b = sbase + (uint32_t)((chunk % 3) * BUF_B);
        cp16(b + 0*TILE_B + so0, sAh + go0 + k0); cp16(b + 0*TILE_B + so1, sAh + go1 + k0);
        cp16(b + 1*TILE_B + so0, sAl + go0 + k0); cp16(b + 1*TILE_B + so1, sAl + go1 + k0);
        cp16(b + 2*TILE_B + so0, sB  + go0 + k0); cp16(b + 2*TILE_B + so1, sB  + go1 + k0);
        cp_commit();
    };

    issue(0);
    issue(1);

    for (int c = 0; c < NKC; ++c) {
        cp_wait1();
        __syncthreads();
        if (c + 2 < NKC) issue(c + 2);

        uint32_t sb = sbase + (uint32_t)((c % 3) * BUF_B);
        uint32_t tAh = sb;
        uint32_t tAl = sb + TILE_B;
        uint32_t tB  = sb + 2 * TILE_B;
#pragma unroll
        for (int ks = 0; ks < 2; ++ks) {
            int kk = ks * 16;
            int uA = (kk + akof) >> 3;
            uint32_t ah[2][4], al[2][4];
            {
                uint32_t o0 = swz(rowA0, uA), o1 = swz(rowA1, uA);
                ldsm4(ah[0], tAh + o0);
                ldsm4(ah[1], tAh + o1);
                ldsm4(al[0], tAl + o0);
                ldsm4(al[1], tAl + o1);
            }
            int uB = (kk + bkof) >> 3;
#pragma unroll
            for (int np = 0; np < 4; np++) {
                uint32_t bo = swz(n0w + np * 16 + brow, uB);
                uint32_t b4[4];
                ldsm4(b4, tB + bo);
#pragma unroll
                for (int sub = 0; sub < 2; sub++) {
                    int ni = np * 2 + sub;
                    uint32_t b0 = b4[sub * 2], b1 = b4[sub * 2 + 1];
#pragma unroll
                    for (int mi = 0; mi < 2; mi++) {
                        mma_f16(acc[mi][ni], ah[mi], b0, b1);
                        mma_f16(acc[mi][ni], al[mi], b0, b1);
                    }
                }
            }
        }
    }

#pragma unroll
    for (int mi = 0; mi < 2; mi++) {
        int r = m0 + m0w + mi * 16 + g;
#pragma unroll
        for (int ni = 0; ni < 8; ni++) {
            int col = n0 + n0w + ni * 8 + 2 * t;
            *(float2*)&C[(size_t)r * CC + col] =
                make_float2(acc[mi][ni][0], acc[mi][ni][1]);
            *(float2*)&C[(size_t)(r + 8) * CC + col] =
                make_float2(acc[mi][ni][2], acc[mi][ni][3]);
        }
    }
}

// ---------------- 3a) per-chunk state contributions A_n (fully parallel) ---
#define SA_SMEM ((2*TCH*KD + TCH) * 4)
__global__ void __launch_bounds__(256)
stateA_kernel(const float* __restrict__ tdecay) {
    extern __shared__ float sa[];
    float* kw  = sa;
    float* vsh = sa + TCH * KD;
    float* dp  = sa + 2 * TCH * KD;
    int bhn = blockIdx.x;
    int n  = bhn & (NCH - 1);
    int bh = bhn >> 5;
    int b = bh >> 4, h = bh & 15;
    int tid = threadIdx.x;
    float decay = expf(-expf(tdecay[h]));
    if (tid < TCH) dp[tid] = powf(decay, (float)(TCH - 1 - tid));
    __syncthreads();
    const float* kb = g_k + ((size_t)(b * TTT + n * TCH)) * CC + h * KD;
    const float* vb = g_v + ((size_t)(b * TTT + n * TCH)) * CC + h * KD;
    for (int e = tid * 4; e < TCH * KD; e += 1024) {
        int j = e >> 6, c = e & 63;
        float4 k4 = *(const float4*)(kb + (size_t)j * CC + c);
        float wj = dp[j];
        k4.x *= wj; k4.y *= wj; k4.z *= wj; k4.w *= wj;
        *(float4*)&kw[e]  = k4;
        *(float4*)&vsh[e] = *(const float4*)(vb + (size_t)j * CC + c);
    }
    __syncthreads();
    int kk0 = (tid >> 4) * 4;
    int c0  = (tid & 15) * 4;
    u64t acc[4][2];
#pragma unroll
    for (int i = 0; i < 4; i++) { acc[i][0] = 0ull; acc[i][1] = 0ull; }
#pragma unroll 2
    for (int j = 0; j < TCH; j++) {
        float4 k4 = *(const float4*)&kw[j * KD + kk0];
        float4 v4 = *(const float4*)&vsh[j * KD + c0];
        u64t v0 = pack2(v4.x, v4.y), v1 = pack2(v4.z, v4.w);
        u64t a0 = pack2(k4.x, k4.x), a1 = pack2(k4.y, k4.y);
        u64t a2 = pack2(k4.z, k4.z), a3 = pack2(k4.w, k4.w);
        acc[0][0] = fma2(a0, v0, acc[0][0]); acc[0][1] = fma2(a0, v1, acc[0][1]);
        acc[1][0] = fma2(a1, v0, acc[1][0]); acc[1][1] = fma2(a1, v1, acc[1][1]);
        acc[2][0] = fma2(a2, v0, acc[2][0]); acc[2][1] = fma2(a2, v1, acc[2][1]);
        acc[3][0] = fma2(a3, v0, acc[3][0]); acc[3][1] = fma2(a3, v1, acc[3][1]);
    }
    float* outb = g_states + (size_t)bhn * (KD * KD);
#pragma unroll
    for (int i = 0; i < 4; i++) {
        u64t* dst = (u64t*)(outb + (kk0 + i) * KD + c0);
        dst[0] = acc[i][0]; dst[1] = acc[i][1];
    }
}

// ---------------- 3b) linear scan over chunks ------------------------------
__global__ void __launch_bounds__(256)
stateScan_kernel(const float* __restrict__ tdecay) {
    int bh = blockIdx.x;
    int h = bh & 15;
    int tid = threadIdx.x;
    float decay = expf(-expf(tdecay[h]));
    float ws = powf(decay, (float)TCH);
    float* base = g_states + (size_t)bh * NCH * (KD * KD) + tid * 16;
    float4 s0 = {0,0,0,0}, s1 = {0,0,0,0}, s2 = {0,0,0,0}, s3 = {0,0,0,0};
    for (int n = 0; n < NCH; n++) {
        float4* p = (float4*)(base + (size_t)n * (KD * KD));
        float4 a0 = p[0], a1 = p[1], a2 = p[2], a3 = p[3];
        p[0] = s0; p[1] = s1; p[2] = s2; p[3] = s3;
        s0.x = ws*s0.x + a0.x; s0.y = ws*s0.y + a0.y; s0.z = ws*s0.z + a0.z; s0.w = ws*s0.w + a0.w;
        s1.x = ws*s1.x + a1.x; s1.y = ws*s1.y + a1.y; s1.z = ws*s1.z + a1.z; s1.w = ws*s1.w + a1.w;
        s2.x = ws*s2.x + a2.x; s2.y = ws*s2.y + a2.y; s2.z = ws*s2.z + a2.z; s2.w = ws*s2.w + a2.w;
        s3.x = ws*s3.x + a3.x; s3.y = ws*s3.y + a3.y; s3.z = ws*s3.z + a3.z; s3.w = ws*s3.w + a3.w;
    }
}

// ---------------- 4) attention output via mma.sync + fused GN/gate ---------
// SMEM layout (bytes):
#define O_R_H   0
#define O_R_L   16384
#define O_K_H   32768        // overlaid by att_h after P1
#define O_K_L   49152
#define O_ATT_H 32768
#define O_ATT_L 65536
#define O_V_H   98304
#define O_V_L   114688
#define O_S_H   131072
#define O_S_L   139264
#define O_DP    147456       // 128 floats
#define O_LW    147968       // 64 floats
#define O_LB    148224       // 64 floats
#define O_RED   148480       // 128*2 float2 = 2048
#define O_TOTAL 150528

__device__ __forceinline__ void cvt8_store(const float* src, char* smbase,
                                           uint32_t offH, uint32_t offL,
                                           int row, int uu) {
    float4 f0 = *(const float4*)(src);
    float4 f1 = *(const float4*)(src + 4);
    uint4 hi = make_uint4(h2pack(f0.x, f0.y), h2pack(f0.z, f0.w),
                          h2pack(f1.x, f1.y), h2pack(f1.z, f1.w));
    uint32_t sw = swz64(row, uu);
    *(uint4*)(smbase + offH + sw) = hi;
    __half2* hp = (__half2*)&hi;
    uint4 lo = make_uint4(
        h2pack(f0.x - __half2float(hp[0].x), f0.y - __half2float(hp[0].y)),
        h2pack(f0.z - __half2float(hp[1].x), f0.w - __half2float(hp[1].y)),
        h2pack(f1.x - __half2float(hp[2].x), f1.y - __half2float(hp[2].y)),
        h2pack(f1.z - __half2float(hp[3].x), f1.w - __half2float(hp[3].y)));
    *(uint4*)(smbase + offL + sw) = lo;
}

__global__ void __launch_bounds__(256, 1)
out_mma_kernel(const float* __restrict__ tdecay, const float* __restrict__ tfa,
               const float* __restrict__ lnw, const float* __restrict__ lnb) {
    extern __shared__ char sm[];
    uint32_t sb = smem_u32(sm);
    int tid = threadIdx.x;
    int w = tid >> 5, lane = tid & 31;
    int g = lane >> 2, t = lane & 3;
    int wm = w >> 1, wn = w & 1;
    int bhn = blockIdx.x;
    int nck = bhn & (NCH - 1);
    int bh = bhn >> 5;
    int h = bh & 15, b = bh >> 4;
    float decay = expf(-expf(tdecay[h]));
    float* dp = (float*)(sm + O_DP);
    float* lws = (float*)(sm + O_LW);
    float* lbs = (float*)(sm + O_LB);
    if (tid < TCH) dp[tid] = powf(decay, (float)tid);
    if (tid < 64) { lws[tid] = lnw[h * 64 + tid]; lbs[tid] = lnb[h * 64 + tid]; }
    float uf = tfa[h];
    size_t base = ((size_t)(b * TTT + nck * TCH)) * CC + h * KD;

    // load + convert r, k, v (128x64 fp32 -> fp16 hi/lo swizzled)
    {
        const float* gr = g_r + base;
        const float* gk = g_k + base;
        const float* gv = g_v + base;
#pragma unroll
        for (int it = 0; it < 4; it++) {
            int slot = tid + it * 256;          // 1024 slots: row(0..127) x u(0..7)
            int row = slot >> 3, uu = slot & 7;
            size_t go = (size_t)row * CC + uu * 8;
            cvt8_store(gr + go, sm, O_R_H, O_R_L, row, uu);
            cvt8_store(gk + go, sm, O_K_H, O_K_L, row, uu);
            cvt8_store(gv + go, sm, O_V_H, O_V_L, row, uu);
        }
        const float* sp = g_states + ((size_t)bh * NCH + nck) * (KD * KD);
#pragma unroll
        for (int it = 0; it < 2; it++) {
            int slot = tid + it * 256;          // 512 slots: row(0..63) x u(0..7)
            int row = slot >> 3, uu = slot & 7;
            cvt8_store(sp + (size_t)row * KD + uu * 8, sm, O_S_H, O_S_L, row, uu);
        }
    }
    __syncthreads();

    int arow = lane & 15;
    int akof = (lane >> 4) << 3;
    int brow = ((lane >> 4) << 3) + (lane & 7);
    int bkof = ((lane >> 3) & 1) << 3;

    // ---- P1: att = (r . k^T) * w_mat ----
    float acc1[2][8][4];
#pragma unroll
    for (int mi = 0; mi < 2; mi++)
#pragma unroll
        for (int ni = 0; ni < 8; ni++)
#pragma unroll
            for (int q = 0; q < 4; q++) acc1[mi][ni][q] = 0.f;
#pragma unroll
    for (int ks = 0; ks < 4; ks++) {
        int kk = ks * 16;
        int uA = (kk + akof) >> 3;
        uint32_t ah[2][4], al[2][4];
#pragma unroll
        for (int mi = 0; mi < 2; mi++) {
            uint32_t ad = sb + O_R_H + swz64(wm * 32 + mi * 16 + arow, uA);
            ldsm4(ah[mi], ad);
            ldsm4(al[mi], ad + (O_R_L - O_R_H));
        }
        int uB = (kk + bkof) >> 3;
#pragma unroll
        for (int np = 0; np < 4; np++) {
            uint32_t bd = sb + O_K_H + swz64(wn * 64 + np * 16 + brow, uB);
            uint32_t bh4[4], bl4[4];
            ldsm4(bh4, bd);
            ldsm4(bl4, bd + (O_K_L - O_K_H));
#pragma unroll
            for (int sub = 0; sub < 2; sub++) {
                int ni = np * 2 + sub;
                uint32_t b0h = bh4[sub * 2], b1h = bh4[sub * 2 + 1];
                uint32_t b0l = bl4[sub * 2], b1l = bl4[sub * 2 + 1];
#pragma unroll
                for (int mi = 0; mi < 2; mi++) {
                    mma_f16(acc1[mi][ni], ah[mi], b0h, b1h);
                    mma_f16(acc1[mi][ni], ah[mi], b0l, b1l);
                    mma_f16(acc1[mi][ni], al[mi], b0h, b1h);
                }
            }
        }
    }
    __syncthreads();     // all k reads done; safe to overwrite with att

    // apply w_mat, store att hi/lo (256B rows, swzA)
#pragma unroll
    for (int mi = 0; mi < 2; mi++) {
        int r0 = wm * 32 + mi * 16 + g;
        int r1 = r0 + 8;
#pragma unroll
        for (int ni = 0; ni < 8; ni++) {
            int cc = wn * 64 + ni * 8 + 2 * t;
            int d;
            d = r0 - cc;     float w00 = (d > 0) ? dp[d - 1] : ((d == 0) ? uf : 0.f);
            d = r0 - cc - 1; float w01 = (d > 0) ? dp[d - 1] : ((d == 0) ? uf : 0.f);
            d = r1 - cc;     float w10 = (d > 0) ? dp[d - 1] : ((d == 0) ? uf : 0.f);
            d = r1 - cc - 1; float w11 = (d > 0) ? dp[d - 1] : ((d == 0) ? uf : 0.f);
            float a0 = acc1[mi][ni][0] * w00, a1 = acc1[mi][ni][1] * w01;
            float a2 = acc1[mi][ni][2] * w10, a3 = acc1[mi][ni][3] * w11;
            uint32_t o0 = swzA(r0, cc >> 3) + (cc & 7) * 2;
            uint32_t o1 = swzA(r1, cc >> 3) + (cc & 7) * 2;
            uint32_t hA = h2pack(a0, a1), hB = h2pack(a2, a3);
            *(uint32_t*)(sm + O_ATT_H + o0) = hA;
            *(uint32_t*)(sm + O_ATT_H + o1) = hB;
            __half2 hAv = *(__half2*)&hA;
            __half2 hBv = *(__half2*)&hB;
            *(uint32_t*)(sm + O_ATT_L + o0) =
                h2pack(a0 - __half2float(hAv.x), a1 - __half2float(hAv.y));
            *(uint32_t*)(sm + O_ATT_L + o1) =
                h2pack(a2 - __half2float(hBv.x), a3 - __half2float(hBv.y));
        }
    }
    __syncthreads();

    // ---- P2: out = att @ v + (r @ s) * dp[row] ----
    float acc2[2][4][4], acc3[2][4][4];
#pragma unroll
    for (int mi = 0; mi < 2; mi++)
#pragma unroll
        for (int ni = 0; ni < 4; ni++)
#pragma unroll
            for (int q = 0; q < 4; q++) { acc2[mi][ni][q] = 0.f; acc3[mi][ni][q] = 0.f; }

    int trow_lo = ((lane >> 3) & 1) * 8 + (lane & 7);   // trans ldsm row within 16
    int tui = lane >> 4;                                // trans ldsm chan +8 selector
#pragma unroll
    for (int ks = 0; ks < 8; ks++) {                    // att @ v, K = 128
        int kk = ks * 16;
        int uA = (kk + akof) >> 3;
        uint32_t ah[2][4], al[2][4];
#pragma unroll
        for (int mi = 0; mi < 2; mi++) {
            uint32_t ad = sb + O_ATT_H + swzA(wm * 32 + mi * 16 + arow, uA);
            ldsm4(ah[mi], ad);
            ldsm4(al[mi], ad + (O_ATT_L - O_ATT_H));
        }
#pragma unroll
        for (int np = 0; np < 2; np++) {
            int nb = wn * 32 + np * 16;
            uint32_t bd = sb + O_V_H + swz64(kk + trow_lo, (nb >> 3) + tui);
            uint32_t bh4[4], bl4[4];
            ldsm4t(bh4, bd);
            ldsm4t(bl4, bd + (O_V_L - O_V_H));
#pragma unroll
            for (int sub = 0; sub < 2; sub++) {
                int ni = np * 2 + sub;
                uint32_t b0h = bh4[sub * 2], b1h = bh4[sub * 2 + 1];
                uint32_t b0l = bl4[sub * 2], b1l = bl4[sub * 2 + 1];
#pragma unroll
                for (int mi = 0; mi < 2; mi++) {
                    mma_f16(acc2[mi][ni], ah[mi], b0h, b1h);
                    mma_f16(acc2[mi][ni], ah[mi], b0l, b1l);
                    mma_f16(acc2[mi][ni], al[mi], b0h, b1h);
                }
            }
        }
    }
#pragma unroll
    for (int ks = 0; ks < 4; ks++) {                    // r @ s, K = 64
        int kk = ks * 16;
        int uA = (kk + akof) >> 3;
        uint32_t ah[2][4], al[2][4];
#pragma unroll
        for (int mi = 0; mi < 2; mi++) {
            uint32_t ad = sb + O_R_H + swz64(wm * 32 + mi * 16 + arow, uA);
            ldsm4(ah[mi], ad);
            ldsm4(al[mi], ad + (O_R_L - O_R_H));
        }
#pragma unroll
        for (int np = 0; np < 2; np++) {
            int nb = wn * 32 + np * 16;
            uint32_t bd = sb + O_S_H + swz64(kk + trow_lo, (nb >> 3) + tui);
            uint32_t bh4[4], bl4[4];
            ldsm4t(bh4, bd);
            ldsm4t(bl4, bd + (O_S_L - O_S_H));
#pragma unroll
            for (int sub = 0; sub < 2; sub++) {
                int ni = np * 2 + sub;
                uint32_t b0h = bh4[sub * 2], b1h = bh4[sub * 2 + 1];
                uint32_t b0l = bl4[sub * 2], b1l = bl4[sub * 2 + 1];
#pragma unroll
                for (int mi = 0; mi < 2; mi++) {
                    mma_f16(acc3[mi][ni], ah[mi], b0h, b1h);
                    mma_f16(acc3[mi][ni], ah[mi], b0l, b1l);
                    mma_f16(acc3[mi][ni], al[mi], b0h, b1h);
                }
            }
        }
    }

    // ---- epilogue: y = out/8, GroupNorm over 64 ch, *lnw+lnb, *silu(g) ----
    float2* red = (float2*)(sm + O_RED);
#pragma unroll
    for (int mi = 0; mi < 2; mi++) {
        int r0 = wm * 32 + mi * 16 + g, r1 = r0 + 8;
        float d0 = dp[r0], d1 = dp[r1];
        float sA = 0.f, qA = 0.f, sB = 0.f, qB = 0.f;
#pragma unroll
        for (int ni = 0; ni < 4; ni++) {
            float y0 = (acc2[mi][ni][0] + d0 * acc3[mi][ni][0]) * 0.125f;
            float y1 = (acc2[mi][ni][1] + d0 * acc3[mi][ni][1]) * 0.125f;
            float y2 = (acc2[mi][ni][2] + d1 * acc3[mi][ni][2]) * 0.125f;
            float y3 = (acc2[mi][ni][3] + d1 * acc3[mi][ni][3]) * 0.125f;
            acc2[mi][ni][0] = y0; acc2[mi][ni][1] = y1;
            acc2[mi][ni][2] = y2; acc2[mi][ni][3] = y3;
            sA += y0 + y1; qA += y0 * y0 + y1 * y1;
            sB += y2 + y3; qB += y2 * y2 + y3 * y3;
        }
#pragma unroll
        for (int o = 1; o < 4; o <<= 1) {
            sA += __shfl_xor_sync(0xffffffffu, sA, o);
            qA += __shfl_xor_sync(0xffffffffu, qA, o);
            sB += __shfl_xor_sync(0xffffffffu, sB, o);
            qB += __shfl_xor_sync(0xffffffffu, qB, o);
        }
        if (t == 0) {
            red[r0 * 2 + wn] = make_float2(sA, qA);
            red[r1 * 2 + wn] = make_float2(sB, qB);
        }
    }
    __syncthreads();
#pragma unroll
    for (int mi = 0; mi < 2; mi++) {
        int r0 = wm * 32 + mi * 16 + g, r1 = r0 + 8;
        float2 pa = red[r0 * 2], pb = red[r0 * 2 + 1];
        float mu0 = (pa.x + pb.x) * (1.f / 64.f);
        float var0 = (pa.y + pb.y) * (1.f / 64.f) - mu0 * mu0;
        float inv0 = rsqrtf(var0 + 1e-5f);
        pa = red[r1 * 2]; pb = red[r1 * 2 + 1];
        float mu1 = (pa.x + pb.x) * (1.f / 64.f);
        float var1 = (pa.y + pb.y) * (1.f / 64.f) - mu1 * mu1;
        float inv1 = rsqrtf(var1 + 1e-5f);
#pragma unroll
        for (int ni = 0; ni < 4; ni++) {
            int cc = wn * 32 + ni * 8 + 2 * t;
            float lw0 = lws[cc], lw1 = lws[cc + 1];
            float lb0 = lbs[cc], lb1 = lbs[cc + 1];
            float2 gA = *(const float2*)(g_g + base + (size_t)r0 * CC + cc);
            float2 gB = *(const float2*)(g_g + base + (size_t)r1 * CC + cc);
            float s0g = gA.x / (1.f + expf(-gA.x));
            float s1g = gA.y / (1.f + expf(-gA.y));
            float s2g = gB.x / (1.f + expf(-gB.x));
            float s3g = gB.y / (1.f + expf(-gB.y));
            float z0 = ((acc2[mi][ni][0] - mu0) * inv0 * lw0 + lb0) * s0g;
            float z1 = ((acc2[mi][ni][1] - mu0) * inv0 * lw1 + lb1) * s1g;
            float z2 = ((acc2[mi][ni][2] - mu1) * inv1 * lw0 + lb0) * s2g;
            float z3 = ((acc2[mi][ni][3] - mu1) * inv1 * lw1 + lb1) * s3g;
            size_t i0 = base + (size_t)r0 * CC + cc;
            size_t i1 = base + (size_t)r1 * CC + cc;
            uint32_t h0 = h2pack(z0, z1), h1 = h2pack(z2, z3);
            *(uint32_t*)(g_z_h + i0) = h0;
            *(uint32_t*)(g_z_h + i1) = h1;
            __half2 hv0 = *(__half2*)&h0, hv1 = *(__half2*)&h1;
            *(uint32_t*)(g_z_l + i0) =
                h2pack(z0 - __half2float(hv0.x), z1 - __half2float(hv0.y));
            *(uint32_t*)(g_z_l + i1) =
                h2pack(z2 - __half2float(hv1.x), z3 - __half2float(hv1.y));
        }
    }
}

// ---------------- launch ---------------------------------------------------
extern "C" void kernel_launch(void* const* d_in, const int* in_sizes, int n_in,
                              void* d_out, int out_size) {
    const float* xq     = (const float*)d_in[0];
    const float* tmk    = (const float*)d_in[1];
    const float* tmv    = (const float*)d_in[2];
    const float* tmr    = (const float*)d_in[3];
    const float* tmg    = (const float*)d_in[4];
    const float* tdecay = (const float*)d_in[5];
    const float* tfa    = (const float*)d_in[6];
    const float* Wr     = (const float*)d_in[7];
    const float* Wk     = (const float*)d_in[8];
    const float* Wv     = (const float*)d_in[9];
    const float* Wg     = (const float*)d_in[10];
    const float* Wo     = (const float*)d_in[11];
    const float* lnw    = (const float*)d_in[12];
    const float* lnb    = (const float*)d_in[13];
    float* out = (float*)d_out;

    __half *pxr_h, *pxr_l, *pxk_h, *pxk_l, *pxv_h, *pxv_l, *pxg_h, *pxg_l;
    __half *pz_h, *pz_l;
    __half *pwr, *pwk, *pwv, *pwg, *pwo;
    float *pr, *pk, *pv, *pg;
    cudaGetSymbolAddress((void**)&pxr_h, g_xr_h); cudaGetSymbolAddress((void**)&pxr_l, g_xr_l);
    cudaGetSymbolAddress((void**)&pxk_h, g_xk_h); cudaGetSymbolAddress((void**)&pxk_l, g_xk_l);
    cudaGetSymbolAddress((void**)&pxv_h, g_xv_h); cudaGetSymbolAddress((void**)&pxv_l, g_xv_l);
    cudaGetSymbolAddress((void**)&pxg_h, g_xg_h); cudaGetSymbolAddress((void**)&pxg_l, g_xg_l);
    cudaGetSymbolAddress((void**)&pz_h,  g_z_h);  cudaGetSymbolAddress((void**)&pz_l,  g_z_l);
    cudaGetSymbolAddress((void**)&pwr, g_wr); cudaGetSymbolAddress((void**)&pwk, g_wk);
    cudaGetSymbolAddress((void**)&pwv, g_wv); cudaGetSymbolAddress((void**)&pwg, g_wg);
    cudaGetSymbolAddress((void**)&pwo, g_wo);
    cudaGetSymbolAddress((void**)&pr, g_r); cudaGetSymbolAddress((void**)&pk, g_k);
    cudaGetSymbolAddress((void**)&pv, g_v); cudaGetSymbolAddress((void**)&pg, g_g);

    wsplit5_kernel<<<dim3(CC * CC / 256, 5), 256>>>(
        Wr, Wk, Wv, Wg, Wo, pwr, pwk, pwv, pwg, pwo);

    mix_kernel<<<MM * CC / 1024, 256>>>(xq, tmk, tmv, tmr, tmg);

    cudaFuncSetAttribute(gemm_mma, cudaFuncAttributeMaxDynamicSharedMemorySize,
                         GSM_TOTAL);
    gemm_mma<<<dim3(CC / 128, MM / 128, 4), 256, GSM_TOTAL>>>(
        pxr_h, pxr_l, pwr, pr,
        pxk_h, pxk_l, pwk, pk,
        pxv_h, pxv_l, pwv, pv,
        pxg_h, pxg_l, pwg, pg);

    cudaFuncSetAttribute(stateA_kernel, cudaFuncAttributeMaxDynamicSharedMemorySize,
                         SA_SMEM);
    stateA_kernel<<<BB * HH * NCH, 256, SA_SMEM>>>(tdecay);
    stateScan_kernel<<<BB * HH, 256>>>(tdecay);

    cudaFuncSetAttribute(out_mma_kernel, cudaFuncAttributeMaxDynamicSharedMemorySize,
                         O_TOTAL);
    out_mma_kernel<<<BB * HH * NCH, 256, O_TOTAL>>>(tdecay, tfa, lnw, lnb);

    gemm_mma<<<dim3(CC / 128, MM / 128, 1), 256, GSM_TOTAL>>>(
        pz_h, pz_l, pwo, out,
        pz_h, pz_l, pwo, out,
        pz_h, pz_l, pwo, out,
        pz_h, pz_l, pwo, out);
}

// round 12
// speedup vs baseline: 4.9728x; 1.6221x over previous
#include <cuda_runtime.h>
#include <cuda_fp16.h>
#include <stdint.h>
#include <math.h>

// Problem constants
#define BB   4
#define TTT  4096
#define CC   1024
#define HH   16
#define KD   64          // head dim
#define TCH  128         // chunk length
#define NCH  32          // chunks
#define MM   (BB*TTT)    // 16384 rows

// ---------------- scratch (device globals; no allocation allowed) ----------
__device__ __half g_xr[MM*CC];
__device__ __half g_xk[MM*CC];
__device__ __half g_xv[MM*CC];
__device__ __half g_xg[MM*CC];
__device__ __half g_z [MM*CC];
__device__ __half g_wr[CC*CC];
__device__ __half g_wk[CC*CC];
__device__ __half g_wv[CC*CC];
__device__ __half g_wg[CC*CC];
__device__ __half g_wo[CC*CC];
__device__ float g_r [MM*CC];
__device__ float g_k [MM*CC];
__device__ float g_v [MM*CC];
__device__ float g_g [MM*CC];
__device__ float g_states[BB*HH*NCH*KD*KD];

// ---------------- helpers ---------------------------------------------------
__device__ __forceinline__ void mma_f16(float* c, const uint32_t* a,
                                        uint32_t b0, uint32_t b1) {
    asm volatile(
        "mma.sync.aligned.m16n8k16.row.col.f32.f16.f16.f32 "
        "{%0,%1,%2,%3}, {%4,%5,%6,%7}, {%8,%9}, {%0,%1,%2,%3};"
        : "+f"(c[0]), "+f"(c[1]), "+f"(c[2]), "+f"(c[3])
        : "r"(a[0]), "r"(a[1]), "r"(a[2]), "r"(a[3]), "r"(b0), "r"(b1));
}

__device__ __forceinline__ uint32_t smem_u32(const void* p) {
    uint32_t a;
    asm("{ .reg .u64 t; cvta.to.shared.u64 t, %1; cvt.u32.u64 %0, t; }"
        : "=r"(a) : "l"(p));
    return a;
}
__device__ __forceinline__ void cp16(uint32_t saddr, const void* g) {
    asm volatile("cp.async.cg.shared.global [%0], [%1], 16;" :: "r"(saddr), "l"(g));
}
__device__ __forceinline__ void cp_commit() {
    asm volatile("cp.async.commit_group;");
}
__device__ __forceinline__ void cp_wait1() {
    asm volatile("cp.async.wait_group 1;");
}
__device__ __forceinline__ void ldsm4(uint32_t* r, uint32_t addr) {
    asm volatile("ldmatrix.sync.aligned.m8n8.x4.shared.b16 {%0,%1,%2,%3}, [%4];"
                 : "=r"(r[0]), "=r"(r[1]), "=r"(r[2]), "=r"(r[3]) : "r"(addr));
}
__device__ __forceinline__ void ldsm4t(uint32_t* r, uint32_t addr) {
    asm volatile("ldmatrix.sync.aligned.m8n8.x4.trans.shared.b16 {%0,%1,%2,%3}, [%4];"
                 : "=r"(r[0]), "=r"(r[1]), "=r"(r[2]), "=r"(r[3]) : "r"(addr));
}

// ---- packed fp32x2 (Blackwell double-pumped fp32) ----
typedef unsigned long long u64t;
__device__ __forceinline__ u64t fma2(u64t a, u64t b, u64t c) {
    u64t d;
    asm("fma.rn.f32x2 %0, %1, %2, %3;" : "=l"(d) : "l"(a), "l"(b), "l"(c));
    return d;
}
__device__ __forceinline__ u64t pack2(float x, float y) {
    u64t d;
    asm("mov.b64 %0, {%1, %2};" : "=l"(d) : "f"(x), "f"(y));
    return d;
}

__device__ __forceinline__ uint32_t h2pack(float a, float b) {
    __half2 h(__float2half_rn(a), __float2half_rn(b));
    return *(uint32_t*)&h;
}

// swizzled byte offset within a 128-row x 64B tile: row r, 16B-unit u (0..3)
__device__ __forceinline__ uint32_t swz(int r, int u) {
    return (uint32_t)(r * 64 + ((u ^ ((r >> 1) & 3)) << 4));
}
// 128B rows (64 fp16): unit u 0..7
__device__ __forceinline__ uint32_t swz64(int r, int u) {
    return (uint32_t)(r * 128 + ((u ^ (r & 7)) << 4));
}
// 256B rows (128 fp16): unit u 0..15
__device__ __forceinline__ uint32_t swzA(int r, int u) {
    int phys = (u & 8) | ((u ^ (r & 7)) & 7);
    return (uint32_t)(r * 256 + phys * 16);
}

// ---------------- 0) weight convert fp32 -> fp16 (all 5 fused) -------------
__global__ void wsplit5_kernel(const float* __restrict__ W0, const float* __restrict__ W1,
                               const float* __restrict__ W2, const float* __restrict__ W3,
                               const float* __restrict__ W4,
                               __half* __restrict__ H0, __half* __restrict__ H1,
                               __half* __restrict__ H2, __half* __restrict__ H3,
                               __half* __restrict__ H4) {
    int i = blockIdx.x * blockDim.x + threadIdx.x;
    const float* W; __half* Hh;
    switch (blockIdx.y) {
        case 0: W = W0; Hh = H0; break;
        case 1: W = W1; Hh = H1; break;
        case 2: W = W2; Hh = H2; break;
        case 3: W = W3; Hh = H3; break;
        default: W = W4; Hh = H4; break;
    }
    Hh[i] = __float2half_rn(W[i]);
}

// ---------------- 1) time-shift mixing -> fp16 (float4 vectorized) ---------
__device__ __forceinline__ void mix4_store(const float* __restrict__ tm, int c,
                                           float4 xc, float4 xp,
                                           __half* __restrict__ H, int idx) {
    float4 m = *(const float4*)(tm + c);
    float y0 = xc.x * m.x + xp.x * (1.f - m.x);
    float y1 = xc.y * m.y + xp.y * (1.f - m.y);
    float y2 = xc.z * m.z + xp.z * (1.f - m.z);
    float y3 = xc.w * m.w + xp.w * (1.f - m.w);
    uint2 hv = make_uint2(h2pack(y0, y1), h2pack(y2, y3));
    *(uint2*)(H + idx) = hv;
}

__global__ void mix_kernel(const float* __restrict__ x,
                           const float* __restrict__ tmk,
                           const float* __restrict__ tmv,
                           const float* __restrict__ tmr,
                           const float* __restrict__ tmg) {
    int idx = (blockIdx.x * blockDim.x + threadIdx.x) * 4;
    int c = idx & (CC - 1);
    int t = (idx >> 10) & (TTT - 1);
    float4 xc = *(const float4*)(x + idx);
    float4 xp = t ? *(const float4*)(x + idx - CC) : make_float4(0.f, 0.f, 0.f, 0.f);
    mix4_store(tmr, c, xc, xp, g_xr, idx);
    mix4_store(tmk, c, xc, xp, g_xk, idx);
    mix4_store(tmv, c, xc, xp, g_xv, idx);
    mix4_store(tmg, c, xc, xp, g_xg, idx);
}

// ---------------- 2) mma.sync GEMM: C = A @ W^T (fp16 single-pass) ---------
// CTA tile 128x128, 8 warps (warp tile 32x64), K-chunk 32.
// Tiles: A, W (fp16). 3-stage cp.async, 48KB smem, 2 CTAs/SM.
#define KCH     32
#define TILE_B  8192                     // 128 rows x 64B
#define BUF_B   (2*TILE_B)               // A, B
#define GSM_TOTAL (3*BUF_B)              // 49152 B
#define NKC     (CC/KCH)                 // 32 chunks

__global__ void __launch_bounds__(256, 2)
gemm_mma(const __half* __restrict__ A0, const __half* __restrict__ B0,
         float* __restrict__ C0,
         const __half* __restrict__ A1, const __half* __restrict__ B1,
         float* __restrict__ C1,
         const __half* __restrict__ A2, const __half* __restrict__ B2,
         float* __restrict__ C2,
         const __half* __restrict__ A3, const __half* __restrict__ B3,
         float* __restrict__ C3) {
    extern __shared__ char dsm[];
    uint32_t sbase = smem_u32(dsm);
    int tid = threadIdx.x;
    int w   = tid >> 5;
    int lane = tid & 31;
    int g = lane >> 2;
    int t = lane & 3;
    int n0 = blockIdx.x * 128;
    int m0 = blockIdx.y * 128;
    int m0w = (w >> 1) * 32;
    int n0w = (w & 1) * 64;

    const __half *Aa, *Bw; float* C;
    switch (blockIdx.z) {
        case 0: Aa = A0; Bw = B0; C = C0; break;
        case 1: Aa = A1; Bw = B1; C = C1; break;
        case 2: Aa = A2; Bw = B2; C = C2; break;
        default: Aa = A3; Bw = B3; C = C3; break;
    }
    const __half* sA = Aa + (size_t)m0 * CC;
    const __half* sB = Bw + (size_t)n0 * CC;

    int r0 = tid >> 2, u = tid & 3;
    size_t go0 = (size_t)r0 * CC + u * 8;
    size_t go1 = go0 + (size_t)64 * CC;
    uint32_t so0 = swz(r0, u);
    uint32_t so1 = so0 + 64 * 64;

    int arow = lane & 15;
    int akof = (lane >> 4) << 3;
    int brow = ((lane >> 4) << 3) + (lane & 7);
    int bkof = ((lane >> 3) & 1) << 3;
    int rowA0 = m0w + arow, rowA1 = m0w + 16 + arow;

    float acc[2][8][4];
#pragma unroll
    for (int mi = 0; mi < 2; mi++)
#pragma unroll
        for (int ni = 0; ni < 8; ni++)
#pragma unroll
            for (int q = 0; q < 4; q++) acc[mi][ni][q] = 0.f;

    auto issue = [&](int chunk) {
        int k0 = chunk * KCH;
        uint32_t b = sbase + (uint32_t)((chunk % 3) * BUF_B);
        cp16(b + 0*TILE_B + so0, sA + go0 + k0); cp16(b + 0*TILE_B + so1, sA + go1 + k0);
        cp16(b + 1*TILE_B + so0, sB + go0 + k0); cp16(b + 1*TILE_B + so1, sB + go1 + k0);
        cp_commit();
    };

    issue(0);
    issue(1);

    for (int c = 0; c < NKC; ++c) {
        cp_wait1();
        __syncthreads();
        if (c + 2 < NKC) issue(c + 2);

        uint32_t sb = sbase + (uint32_t)((c % 3) * BUF_B);
        uint32_t tA = sb;
        uint32_t tB = sb + TILE_B;
#pragma unroll
        for (int ks = 0; ks < 2; ++ks) {
            int kk = ks * 16;
            int uA = (kk + akof) >> 3;
            uint32_t ah[2][4];
            {
                ldsm4(ah[0], tA + swz(rowA0, uA));
                ldsm4(ah[1], tA + swz(rowA1, uA));
            }
            int uB = (kk + bkof) >> 3;
#pragma unroll
            for (int np = 0; np < 4; np++) {
                uint32_t b4[4];
                ldsm4(b4, tB + swz(n0w + np * 16 + brow, uB));
#pragma unroll
                for (int sub = 0; sub < 2; sub++) {
                    int ni = np * 2 + sub;
                    uint32_t b0 = b4[sub * 2], b1 = b4[sub * 2 + 1];
#pragma unroll
                    for (int mi = 0; mi < 2; mi++)
                        mma_f16(acc[mi][ni], ah[mi], b0, b1);
                }
            }
        }
    }

#pragma unroll
    for (int mi = 0; mi < 2; mi++) {
        int r = m0 + m0w + mi * 16 + g;
#pragma unroll
        for (int ni = 0; ni < 8; ni++) {
            int col = n0 + n0w + ni * 8 + 2 * t;
            *(float2*)&C[(size_t)r * CC + col] =
                make_float2(acc[mi][ni][0], acc[mi][ni][1]);
            *(float2*)&C[(size_t)(r + 8) * CC + col] =
                make_float2(acc[mi][ni][2], acc[mi][ni][3]);
        }
    }
}

// ---------------- 3a) per-chunk state contributions A_n (fully parallel) ---
#define SA_SMEM ((2*TCH*KD + TCH) * 4)
__global__ void __launch_bounds__(256)
stateA_kernel(const float* __restrict__ tdecay) {
    extern __shared__ float sa[];
    float* kw  = sa;
    float* vsh = sa + TCH * KD;
    float* dp  = sa + 2 * TCH * KD;
    int bhn = blockIdx.x;
    int n  = bhn & (NCH - 1);
    int bh = bhn >> 5;
    int b = bh >> 4, h = bh & 15;
    int tid = threadIdx.x;
    float decay = expf(-expf(tdecay[h]));
    if (tid < TCH) dp[tid] = powf(decay, (float)(TCH - 1 - tid));
    __syncthreads();
    const float* kb = g_k + ((size_t)(b * TTT + n * TCH)) * CC + h * KD;
    const float* vb = g_v + ((size_t)(b * TTT + n * TCH)) * CC + h * KD;
    for (int e = tid * 4; e < TCH * KD; e += 1024) {
        int j = e >> 6, c = e & 63;
        float4 k4 = *(const float4*)(kb + (size_t)j * CC + c);
        float wj = dp[j];
        k4.x *= wj; k4.y *= wj; k4.z *= wj; k4.w *= wj;
        *(float4*)&kw[e]  = k4;
        *(float4*)&vsh[e] = *(const float4*)(vb + (size_t)j * CC + c);
    }
    __syncthreads();
    int kk0 = (tid >> 4) * 4;
    int c0  = (tid & 15) * 4;
    u64t acc[4][2];
#pragma unroll
    for (int i = 0; i < 4; i++) { acc[i][0] = 0ull; acc[i][1] = 0ull; }
#pragma unroll 2
    for (int j = 0; j < TCH; j++) {
        float4 k4 = *(const float4*)&kw[j * KD + kk0];
        float4 v4 = *(const float4*)&vsh[j * KD + c0];
        u64t v0 = pack2(v4.x, v4.y), v1 = pack2(v4.z, v4.w);
        u64t a0 = pack2(k4.x, k4.x), a1 = pack2(k4.y, k4.y);
        u64t a2 = pack2(k4.z, k4.z), a3 = pack2(k4.w, k4.w);
        acc[0][0] = fma2(a0, v0, acc[0][0]); acc[0][1] = fma2(a0, v1, acc[0][1]);
        acc[1][0] = fma2(a1, v0, acc[1][0]); acc[1][1] = fma2(a1, v1, acc[1][1]);
        acc[2][0] = fma2(a2, v0, acc[2][0]); acc[2][1] = fma2(a2, v1, acc[2][1]);
        acc[3][0] = fma2(a3, v0, acc[3][0]); acc[3][1] = fma2(a3, v1, acc[3][1]);
    }
    float* outb = g_states + (size_t)bhn * (KD * KD);
#pragma unroll
    for (int i = 0; i < 4; i++) {
        u64t* dst = (u64t*)(outb + (kk0 + i) * KD + c0);
        dst[0] = acc[i][0]; dst[1] = acc[i][1];
    }
}

// ---------------- 3b) linear scan over chunks ------------------------------
__global__ void __launch_bounds__(256)
stateScan_kernel(const float* __restrict__ tdecay) {
    int bh = blockIdx.x;
    int h = bh & 15;
    int tid = threadIdx.x;
    float decay = expf(-expf(tdecay[h]));
    float ws = powf(decay, (float)TCH);
    float* base = g_states + (size_t)bh * NCH * (KD * KD) + tid * 16;
    float4 s0 = {0,0,0,0}, s1 = {0,0,0,0}, s2 = {0,0,0,0}, s3 = {0,0,0,0};
    for (int n = 0; n < NCH; n++) {
        float4* p = (float4*)(base + (size_t)n * (KD * KD));
        float4 a0 = p[0], a1 = p[1], a2 = p[2], a3 = p[3];
        p[0] = s0; p[1] = s1; p[2] = s2; p[3] = s3;
        s0.x = ws*s0.x + a0.x; s0.y = ws*s0.y + a0.y; s0.z = ws*s0.z + a0.z; s0.w = ws*s0.w + a0.w;
        s1.x = ws*s1.x + a1.x; s1.y = ws*s1.y + a1.y; s1.z = ws*s1.z + a1.z; s1.w = ws*s1.w + a1.w;
        s2.x = ws*s2.x + a2.x; s2.y = ws*s2.y + a2.y; s2.z = ws*s2.z + a2.z; s2.w = ws*s2.w + a2.w;
        s3.x = ws*s3.x + a3.x; s3.y = ws*s3.y + a3.y; s3.z = ws*s3.z + a3.z; s3.w = ws*s3.w + a3.w;
    }
}

// ---------------- 4) attention output via mma.sync + fused GN/gate ---------
// SMEM layout (bytes):
#define O_R_H   0
#define O_R_L   16384
#define O_K_H   32768        // overlaid by att_h after P1
#define O_K_L   49152
#define O_ATT_H 32768
#define O_ATT_L 65536
#define O_V_H   98304
#define O_V_L   114688
#define O_S_H   131072
#define O_S_L   139264
#define O_DP    147456       // 128 floats
#define O_LW    147968       // 64 floats
#define O_LB    148224       // 64 floats
#define O_RED   148480       // 128*2 float2 = 2048
#define O_TOTAL 150528

__device__ __forceinline__ void cvt8_store(const float* src, char* smbase,
                                           uint32_t offH, uint32_t offL,
                                           int row, int uu) {
    float4 f0 = *(const float4*)(src);
    float4 f1 = *(const float4*)(src + 4);
    uint4 hi = make_uint4(h2pack(f0.x, f0.y), h2pack(f0.z, f0.w),
                          h2pack(f1.x, f1.y), h2pack(f1.z, f1.w));
    uint32_t sw = swz64(row, uu);
    *(uint4*)(smbase + offH + sw) = hi;
    __half2* hp = (__half2*)&hi;
    uint4 lo = make_uint4(
        h2pack(f0.x - __half2float(hp[0].x), f0.y - __half2float(hp[0].y)),
        h2pack(f0.z - __half2float(hp[1].x), f0.w - __half2float(hp[1].y)),
        h2pack(f1.x - __half2float(hp[2].x), f1.y - __half2float(hp[2].y)),
        h2pack(f1.z - __half2float(hp[3].x), f1.w - __half2float(hp[3].y)));
    *(uint4*)(smbase + offL + sw) = lo;
}

__global__ void __launch_bounds__(256, 1)
out_mma_kernel(const float* __restrict__ tdecay, const float* __restrict__ tfa,
               const float* __restrict__ lnw, const float* __restrict__ lnb) {
    extern __shared__ char sm[];
    uint32_t sb = smem_u32(sm);
    int tid = threadIdx.x;
    int w = tid >> 5, lane = tid & 31;
    int g = lane >> 2, t = lane & 3;
    int wm = w >> 1, wn = w & 1;
    int bhn = blockIdx.x;
    int nck = bhn & (NCH - 1);
    int bh = bhn >> 5;
    int h = bh & 15, b = bh >> 4;
    float decay = expf(-expf(tdecay[h]));
    float* dp = (float*)(sm + O_DP);
    float* lws = (float*)(sm + O_LW);
    float* lbs = (float*)(sm + O_LB);
    if (tid < TCH) dp[tid] = powf(decay, (float)tid);
    if (tid < 64) { lws[tid] = lnw[h * 64 + tid]; lbs[tid] = lnb[h * 64 + tid]; }
    float uf = tfa[h];
    size_t base = ((size_t)(b * TTT + nck * TCH)) * CC + h * KD;

    // load + convert r, k, v (128x64 fp32 -> fp16 hi/lo swizzled)
    {
        const float* gr = g_r + base;
        const float* gk = g_k + base;
        const float* gv = g_v + base;
#pragma unroll
        for (int it = 0; it < 4; it++) {
            int slot = tid + it * 256;
            int row = slot >> 3, uu = slot & 7;
            size_t go = (size_t)row * CC + uu * 8;
            cvt8_store(gr + go, sm, O_R_H, O_R_L, row, uu);
            cvt8_store(gk + go, sm, O_K_H, O_K_L, row, uu);
            cvt8_store(gv + go, sm, O_V_H, O_V_L, row, uu);
        }
        const float* sp = g_states + ((size_t)bh * NCH + nck) * (KD * KD);
#pragma unroll
        for (int it = 0; it < 2; it++) {
            int slot = tid + it * 256;
            int row = slot >> 3, uu = slot & 7;
            cvt8_store(sp + (size_t)row * KD + uu * 8, sm, O_S_H, O_S_L, row, uu);
        }
    }
    __syncthreads();

    int arow = lane & 15;
    int akof = (lane >> 4) << 3;
    int brow = ((lane >> 4) << 3) + (lane & 7);
    int bkof = ((lane >> 3) & 1) << 3;

    // ---- P1: att = (r . k^T) * w_mat ----
    float acc1[2][8][4];
#pragma unroll
    for (int mi = 0; mi < 2; mi++)
#pragma unroll
        for (int ni = 0; ni < 8; ni++)
#pragma unroll
            for (int q = 0; q < 4; q++) acc1[mi][ni][q] = 0.f;
#pragma unroll
    for (int ks = 0; ks < 4; ks++) {
        int kk = ks * 16;
        int uA = (kk + akof) >> 3;
        uint32_t ah[2][4], al[2][4];
#pragma unroll
        for (int mi = 0; mi < 2; mi++) {
            uint32_t ad = sb + O_R_H + swz64(wm * 32 + mi * 16 + arow, uA);
            ldsm4(ah[mi], ad);
            ldsm4(al[mi], ad + (O_R_L - O_R_H));
        }
        int uB = (kk + bkof) >> 3;
#pragma unroll
        for (int np = 0; np < 4; np++) {
            uint32_t bd = sb + O_K_H + swz64(wn * 64 + np * 16 + brow, uB);
            uint32_t bh4[4], bl4[4];
            ldsm4(bh4, bd);
            ldsm4(bl4, bd + (O_K_L - O_K_H));
#pragma unroll
            for (int sub = 0; sub < 2; sub++) {
                int ni = np * 2 + sub;
                uint32_t b0h = bh4[sub * 2], b1h = bh4[sub * 2 + 1];
                uint32_t b0l = bl4[sub * 2], b1l = bl4[sub * 2 + 1];
#pragma unroll
                for (int mi = 0; mi < 2; mi++) {
                    mma_f16(acc1[mi][ni], ah[mi], b0h, b1h);
                    mma_f16(acc1[mi][ni], ah[mi], b0l, b1l);
                    mma_f16(acc1[mi][ni], al[mi], b0h, b1h);
                }
            }
        }
    }
    __syncthreads();

    // apply w_mat, store att hi/lo (256B rows, swzA)
#pragma unroll
    for (int mi = 0; mi < 2; mi++) {
        int r0 = wm * 32 + mi * 16 + g;
        int r1 = r0 + 8;
#pragma unroll
        for (int ni = 0; ni < 8; ni++) {
            int cc = wn * 64 + ni * 8 + 2 * t;
            int d;
            d = r0 - cc;     float w00 = (d > 0) ? dp[d - 1] : ((d == 0) ? uf : 0.f);
            d = r0 - cc - 1; float w01 = (d > 0) ? dp[d - 1] : ((d == 0) ? uf : 0.f);
            d = r1 - cc;     float w10 = (d > 0) ? dp[d - 1] : ((d == 0) ? uf : 0.f);
            d = r1 - cc - 1; float w11 = (d > 0) ? dp[d - 1] : ((d == 0) ? uf : 0.f);
            float a0 = acc1[mi][ni][0] * w00, a1 = acc1[mi][ni][1] * w01;
            float a2 = acc1[mi][ni][2] * w10, a3 = acc1[mi][ni][3] * w11;
            uint32_t o0 = swzA(r0, cc >> 3) + (cc & 7) * 2;
            uint32_t o1 = swzA(r1, cc >> 3) + (cc & 7) * 2;
            uint32_t hA = h2pack(a0, a1), hB = h2pack(a2, a3);
            *(uint32_t*)(sm + O_ATT_H + o0) = hA;
            *(uint32_t*)(sm + O_ATT_H + o1) = hB;
            __half2 hAv = *(__half2*)&hA;
            __half2 hBv = *(__half2*)&hB;
            *(uint32_t*)(sm + O_ATT_L + o0) =
                h2pack(a0 - __half2float(hAv.x), a1 - __half2float(hAv.y));
            *(uint32_t*)(sm + O_ATT_L + o1) =
                h2pack(a2 - __half2float(hBv.x), a3 - __half2float(hBv.y));
        }
    }
    __syncthreads();

    // ---- P2: out = att @ v + (r @ s) * dp[row] ----
    float acc2[2][4][4], acc3[2][4][4];
#pragma unroll
    for (int mi = 0; mi < 2; mi++)
#pragma unroll
        for (int ni = 0; ni < 4; ni++)
#pragma unroll
            for (int q = 0; q < 4; q++) { acc2[mi][ni][q] = 0.f; acc3[mi][ni][q] = 0.f; }

    int trow_lo = ((lane >> 3) & 1) * 8 + (lane & 7);
    int tui = lane >> 4;
#pragma unroll
    for (int ks = 0; ks < 8; ks++) {
        int kk = ks * 16;
        int uA = (kk + akof) >> 3;
        uint32_t ah[2][4], al[2][4];
#pragma unroll
        for (int mi = 0; mi < 2; mi++) {
            uint32_t ad = sb + O_ATT_H + swzA(wm * 32 + mi * 16 + arow, uA);
            ldsm4(ah[mi], ad);
            ldsm4(al[mi], ad + (O_ATT_L - O_ATT_H));
        }
#pragma unroll
        for (int np = 0; np < 2; np++) {
            int nb = wn * 32 + np * 16;
            uint32_t bd = sb + O_V_H + swz64(kk + trow_lo, (nb >> 3) + tui);
            uint32_t bh4[4], bl4[4];
            ldsm4t(bh4, bd);
            ldsm4t(bl4, bd + (O_V_L - O_V_H));
#pragma unroll
            for (int sub = 0; sub < 2; sub++) {
                int ni = np * 2 + sub;
                uint32_t b0h = bh4[sub * 2], b1h = bh4[sub * 2 + 1];
                uint32_t b0l = bl4[sub * 2], b1l = bl4[sub * 2 + 1];
#pragma unroll
                for (int mi = 0; mi < 2; mi++) {
                    mma_f16(acc2[mi][ni], ah[mi], b0h, b1h);
                    mma_f16(acc2[mi][ni], ah[mi], b0l, b1l);
                    mma_f16(acc2[mi][ni], al[mi], b0h, b1h);
                }
            }
        }
    }
#pragma unroll
    for (int ks = 0; ks < 4; ks++) {
        int kk = ks * 16;
        int uA = (kk + akof) >> 3;
        uint32_t ah[2][4], al[2][4];
#pragma unroll
        for (int mi = 0; mi < 2; mi++) {
            uint32_t ad = sb + O_R_H + swz64(wm * 32 + mi * 16 + arow, uA);
            ldsm4(ah[mi], ad);
            ldsm4(al[mi], ad + (O_R_L - O_R_H));
        }
#pragma unroll
        for (int np = 0; np < 2; np++) {
            int nb = wn * 32 + np * 16;
            uint32_t bd = sb + O_S_H + swz64(kk + trow_lo, (nb >> 3) + tui);
            uint32_t bh4[4], bl4[4];
            ldsm4t(bh4, bd);
            ldsm4t(bl4, bd + (O_S_L - O_S_H));
#pragma unroll
            for (int sub = 0; sub < 2; sub++) {
                int ni = np * 2 + sub;
                uint32_t b0h = bh4[sub * 2], b1h = bh4[sub * 2 + 1];
                uint32_t b0l = bl4[sub * 2], b1l = bl4[sub * 2 + 1];
#pragma unroll
                for (int mi = 0; mi < 2; mi++) {
                    mma_f16(acc3[mi][ni], ah[mi], b0h, b1h);
                    mma_f16(acc3[mi][ni], ah[mi], b0l, b1l);
                    mma_f16(acc3[mi][ni], al[mi], b0h, b1h);
                }
            }
        }
    }

    // ---- epilogue: y = out/8, GroupNorm over 64 ch, *lnw+lnb, *silu(g) ----
    float2* red = (float2*)(sm + O_RED);
#pragma unroll
    for (int mi = 0; mi < 2; mi++) {
        int r0 = wm * 32 + mi * 16 + g, r1 = r0 + 8;
        float d0 = dp[r0], d1 = dp[r1];
        float sA = 0.f, qA = 0.f, sB = 0.f, qB = 0.f;
#pragma unroll
        for (int ni = 0; ni < 4; ni++) {
            float y0 = (acc2[mi][ni][0] + d0 * acc3[mi][ni][0]) * 0.125f;
            float y1 = (acc2[mi][ni][1] + d0 * acc3[mi][ni][1]) * 0.125f;
            float y2 = (acc2[mi][ni][2] + d1 * acc3[mi][ni][2]) * 0.125f;
            float y3 = (acc2[mi][ni][3] + d1 * acc3[mi][ni][3]) * 0.125f;
            acc2[mi][ni][0] = y0; acc2[mi][ni][1] = y1;
            acc2[mi][ni][2] = y2; acc2[mi][ni][3] = y3;
            sA += y0 + y1; qA += y0 * y0 + y1 * y1;
            sB += y2 + y3; qB += y2 * y2 + y3 * y3;
        }
#pragma unroll
        for (int o = 1; o < 4; o <<= 1) {
            sA += __shfl_xor_sync(0xffffffffu, sA, o);
            qA += __shfl_xor_sync(0xffffffffu, qA, o);
            sB += __shfl_xor_sync(0xffffffffu, sB, o);
            qB += __shfl_xor_sync(0xffffffffu, qB, o);
        }
        if (t == 0) {
            red[r0 * 2 + wn] = make_float2(sA, qA);
            red[r1 * 2 + wn] = make_float2(sB, qB);
        }
    }
    __syncthreads();
#pragma unroll
    for (int mi = 0; mi < 2; mi++) {
        int r0 = wm * 32 + mi * 16 + g, r1 = r0 + 8;
        float2 pa = red[r0 * 2], pb = red[r0 * 2 + 1];
        float mu0 = (pa.x + pb.x) * (1.f / 64.f);
        float var0 = (pa.y + pb.y) * (1.f / 64.f) - mu0 * mu0;
        float inv0 = rsqrtf(var0 + 1e-5f);
        pa = red[r1 * 2]; pb = red[r1 * 2 + 1];
        float mu1 = (pa.x + pb.x) * (1.f / 64.f);
        float var1 = (pa.y + pb.y) * (1.f / 64.f) - mu1 * mu1;
        float inv1 = rsqrtf(var1 + 1e-5f);
#pragma unroll
        for (int ni = 0; ni < 4; ni++) {
            int cc = wn * 32 + ni * 8 + 2 * t;
            float lw0 = lws[cc], lw1 = lws[cc + 1];
            float lb0 = lbs[cc], lb1 = lbs[cc + 1];
            float2 gA = *(const float2*)(g_g + base + (size_t)r0 * CC + cc);
            float2 gB = *(const float2*)(g_g + base + (size_t)r1 * CC + cc);
            float s0g = gA.x / (1.f + expf(-gA.x));
            float s1g = gA.y / (1.f + expf(-gA.y));
            float s2g = gB.x / (1.f + expf(-gB.x));
            float s3g = gB.y / (1.f + expf(-gB.y));
            float z0 = ((acc2[mi][ni][0] - mu0) * inv0 * lw0 + lb0) * s0g;
            float z1 = ((acc2[mi][ni][1] - mu0) * inv0 * lw1 + lb1) * s1g;
            float z2 = ((acc2[mi][ni][2] - mu1) * inv1 * lw0 + lb0) * s2g;
            float z3 = ((acc2[mi][ni][3] - mu1) * inv1 * lw1 + lb1) * s3g;
            size_t i0 = base + (size_t)r0 * CC + cc;
            size_t i1 = base + (size_t)r1 * CC + cc;
            *(uint32_t*)(g_z + i0) = h2pack(z0, z1);
            *(uint32_t*)(g_z + i1) = h2pack(z2, z3);
        }
    }
}

// ---------------- launch ---------------------------------------------------
extern "C" void kernel_launch(void* const* d_in, const int* in_sizes, int n_in,
                              void* d_out, int out_size) {
    const float* xq     = (const float*)d_in[0];
    const float* tmk    = (const float*)d_in[1];
    const float* tmv    = (const float*)d_in[2];
    const float* tmr    = (const float*)d_in[3];
    const float* tmg    = (const float*)d_in[4];
    const float* tdecay = (const float*)d_in[5];
    const float* tfa    = (const float*)d_in[6];
    const float* Wr     = (const float*)d_in[7];
    const float* Wk     = (const float*)d_in[8];
    const float* Wv     = (const float*)d_in[9];
    const float* Wg     = (const float*)d_in[10];
    const float* Wo     = (const float*)d_in[11];
    const float* lnw    = (const float*)d_in[12];
    const float* lnb    = (const float*)d_in[13];
    float* out = (float*)d_out;

    __half *pxr, *pxk, *pxv, *pxg, *pz;
    __half *pwr, *pwk, *pwv, *pwg, *pwo;
    float *pr, *pk, *pv, *pg;
    cudaGetSymbolAddress((void**)&pxr, g_xr);
    cudaGetSymbolAddress((void**)&pxk, g_xk);
    cudaGetSymbolAddress((void**)&pxv, g_xv);
    cudaGetSymbolAddress((void**)&pxg, g_xg);
    cudaGetSymbolAddress((void**)&pz,  g_z);
    cudaGetSymbolAddress((void**)&pwr, g_wr); cudaGetSymbolAddress((void**)&pwk, g_wk);
    cudaGetSymbolAddress((void**)&pwv, g_wv); cudaGetSymbolAddress((void**)&pwg, g_wg);
    cudaGetSymbolAddress((void**)&pwo, g_wo);
    cudaGetSymbolAddress((void**)&pr, g_r); cudaGetSymbolAddress((void**)&pk, g_k);
    cudaGetSymbolAddress((void**)&pv, g_v); cudaGetSymbolAddress((void**)&pg, g_g);

    wsplit5_kernel<<<dim3(CC * CC / 256, 5), 256>>>(
        Wr, Wk, Wv, Wg, Wo, pwr, pwk, pwv, pwg, pwo);

    mix_kernel<<<MM * CC / 1024, 256>>>(xq, tmk, tmv, tmr, tmg);

    cudaFuncSetAttribute(gemm_mma, cudaFuncAttributeMaxDynamicSharedMemorySize,
                         GSM_TOTAL);
    gemm_mma<<<dim3(CC / 128, MM / 128, 4), 256, GSM_TOTAL>>>(
        pxr, pwr, pr,
        pxk, pwk, pk,
        pxv, pwv, pv,
        pxg, pwg, pg);

    cudaFuncSetAttribute(stateA_kernel, cudaFuncAttributeMaxDynamicSharedMemorySize,
                         SA_SMEM);
    stateA_kernel<<<BB * HH * NCH, 256, SA_SMEM>>>(tdecay);
    stateScan_kernel<<<BB * HH, 256>>>(tdecay);

    cudaFuncSetAttribute(out_mma_kernel, cudaFuncAttributeMaxDynamicSharedMemorySize,
                         O_TOTAL);
    out_mma_kernel<<<BB * HH * NCH, 256, O_TOTAL>>>(tdecay, tfa, lnw, lnb);

    gemm_mma<<<dim3(CC / 128, MM / 128, 1), 256, GSM_TOTAL>>>(
        pz, pwo, out,
        pz, pwo, out,
        pz, pwo, out,
        pz, pwo, out);
}